// round 3
// baseline (speedup 1.0000x reference)
#include <cuda_runtime.h>
#include <cuda_bf16.h>
#include <cstdint>

#define DEVFN static __device__ __forceinline__

constexpr int cB  = 2;
constexpr int cL  = 2048;
constexpr int cDM = 2048;            // D_MODEL
constexpr int cDS = 4096;            // D_SSM
constexpr int cST = 128;             // D_STATE
constexpr int cNH = 64;              // NHEADS
constexpr int cHD = 64;              // HEADDIM
constexpr int cCK = 128;             // CHUNK
constexpr int cNC = cL / cCK;        // 16
constexpr int cDP = 2*cDS + 2*cST + cNH;   // 8512
constexpr int cCD = cDS + 2*cST;           // 4352
constexpr float cEPS = 1e-5f;

// ---------------- scratch (static device globals; no allocation) ----------
__device__ float g_zx [(size_t)cB*cL*cDP];           // in-proj output
__device__ float g_xbc[(size_t)cB*cL*cCD];           // conv+silu output
__device__ float g_dt [(size_t)cB*cNH*cL];           // softplus dt, layout [b][h][l]
__device__ float g_ac [(size_t)cB*cNH*cL];           // per-chunk incl cumsum of dt*A, [b][h][l]
__device__ float g_T  [(size_t)cB*cNH*cNC];          // chunk totals
__device__ float g_cs [(size_t)cB*cNC*cNH*cST*cHD];  // per-chunk states [b][c][h][n][p]
__device__ float g_pv [(size_t)cB*cNC*cNH*cST*cHD];  // carried states   [b][c][h][n][p]
__device__ float g_y  [(size_t)cB*cL*cDS];           // y buffer
__device__ float g_o  [(size_t)cB*cL*cDM];           // out-proj output

// ---------------- helpers -------------------------------------------------
DEVFN float fexp(float x) {          // exp(x), FFMA-only, x <= ~0 in our use
  float t = x * 1.44269504088896340736f;
  t = fminf(fmaxf(t, -126.0f), 126.0f);
  float fi = rintf(t);
  float f  = t - fi;
  float p = 1.5403530393381610e-4f;
  p = fmaf(p, f, 1.3333558146428443e-3f);
  p = fmaf(p, f, 9.6181291076284772e-3f);
  p = fmaf(p, f, 5.5504108664821580e-2f);
  p = fmaf(p, f, 2.4022650695910071e-1f);
  p = fmaf(p, f, 6.9314718055994531e-1f);
  p = fmaf(p, f, 1.0f);
  int i = (int)fi;
  return __int_as_float((i + 127) << 23) * p;
}
DEVFN float fsig(float x) { return 1.0f / (1.0f + fexp(-x)); }

typedef unsigned long long u64;
DEVFN u64 pack1(float x) {           // (x, x) packed
  u64 r; unsigned u = __float_as_uint(x);
  asm("mov.b64 %0, {%1, %2};" : "=l"(r) : "r"(u), "r"(u));
  return r;
}
DEVFN u64 ffma2(u64 a, u64 b, u64 c) {
  u64 d;
  asm("fma.rn.f32x2 %0, %1, %2, %3;" : "=l"(d) : "l"(a), "l"(b), "l"(c));
  return d;
}
DEVFN void unpack2(u64 v, float& lo, float& hi) {
  unsigned a, b;
  asm("mov.b64 {%0, %1}, %2;" : "=r"(a), "=r"(b) : "l"(v));
  lo = __uint_as_float(a); hi = __uint_as_float(b);
}

// ============= K1/K8: C[M,N] = A[M,K] * B[N,K]^T (fp32, f32x2 packed) =====
__global__ void __launch_bounds__(256, 2) sgemm_tn(
    const float* __restrict__ A, const float* __restrict__ B,
    float* __restrict__ Cm, int M, int N, int K)
{
  __shared__ float As[2][8][132];
  __shared__ float Bs[2][8][132];
  const int tid = threadIdx.x;
  const int bm = blockIdx.y * 128, bn = blockIdx.x * 128;
  const int lr = tid >> 1, lk = (tid & 1) * 4;
  const float* Ap = A + (size_t)(bm + lr) * K + lk;
  int brow = bn + lr; if (brow >= N) brow = N - 1;
  const float* Bp = B + (size_t)brow * K + lk;
  const int ty = tid >> 4, tx = tid & 15;
  const int r0 = ty * 8, c0 = tx * 8;
  u64 acc[8][4];
  #pragma unroll
  for (int i = 0; i < 8; ++i)
    #pragma unroll
    for (int j = 0; j < 4; ++j) acc[i][j] = 0ull;

  // prologue: tile 0
  {
    float4 av = *(const float4*)Ap;
    float4 bv = *(const float4*)Bp;
    As[0][lk+0][lr] = av.x; As[0][lk+1][lr] = av.y;
    As[0][lk+2][lr] = av.z; As[0][lk+3][lr] = av.w;
    Bs[0][lk+0][lr] = bv.x; Bs[0][lk+1][lr] = bv.y;
    Bs[0][lk+2][lr] = bv.z; Bs[0][lk+3][lr] = bv.w;
  }
  __syncthreads();

  const int KT = K / 8;
  for (int kt = 0; kt < KT; ++kt) {
    const int cur = kt & 1, nxt = cur ^ 1;
    float4 av, bv;
    const bool more = (kt + 1 < KT);
    if (more) {
      av = *(const float4*)(Ap + (size_t)(kt + 1) * 8);
      bv = *(const float4*)(Bp + (size_t)(kt + 1) * 8);
    }
    #pragma unroll
    for (int k = 0; k < 8; ++k) {
      float4 a0 = *(const float4*)&As[cur][k][r0];
      float4 a1 = *(const float4*)&As[cur][k][r0 + 4];
      const double2 bp0 = *(const double2*)&Bs[cur][k][c0];
      const double2 bp1 = *(const double2*)&Bs[cur][k][c0 + 4];
      u64 b0 = __double_as_longlong(bp0.x);
      u64 b1 = __double_as_longlong(bp0.y);
      u64 b2 = __double_as_longlong(bp1.x);
      u64 b3 = __double_as_longlong(bp1.y);
      float a[8] = {a0.x, a0.y, a0.z, a0.w, a1.x, a1.y, a1.z, a1.w};
      #pragma unroll
      for (int i = 0; i < 8; ++i) {
        u64 a2 = pack1(a[i]);
        acc[i][0] = ffma2(a2, b0, acc[i][0]);
        acc[i][1] = ffma2(a2, b1, acc[i][1]);
        acc[i][2] = ffma2(a2, b2, acc[i][2]);
        acc[i][3] = ffma2(a2, b3, acc[i][3]);
      }
    }
    if (more) {
      As[nxt][lk+0][lr] = av.x; As[nxt][lk+1][lr] = av.y;
      As[nxt][lk+2][lr] = av.z; As[nxt][lk+3][lr] = av.w;
      Bs[nxt][lk+0][lr] = bv.x; Bs[nxt][lk+1][lr] = bv.y;
      Bs[nxt][lk+2][lr] = bv.z; Bs[nxt][lk+3][lr] = bv.w;
    }
    __syncthreads();
  }

  #pragma unroll
  for (int i = 0; i < 8; ++i) {
    float* crow = Cm + (size_t)(bm + r0 + i) * N + bn;
    #pragma unroll
    for (int j = 0; j < 4; ++j) {
      float lo, hi; unpack2(acc[i][j], lo, hi);
      int cc = c0 + 2 * j;
      if (bn + cc     < N) crow[cc]     = lo;
      if (bn + cc + 1 < N) crow[cc + 1] = hi;
    }
  }
}

// ============= K2: conv1d + SiLU + softplus(dt) ===========================
__global__ void __launch_bounds__(256) k_conv(
    const float* __restrict__ conv_w, const float* __restrict__ conv_b,
    const float* __restrict__ dt_bias)
{
  const int row = blockIdx.x;           // b*L + l
  const int b = row / cL, l = row % cL;
  const int tid = threadIdx.x;
  const size_t base0 = (size_t)row * cDP + cDS;   // xBC part of zx row
  const size_t obase = (size_t)row * cCD;
  #pragma unroll 1
  for (int q = 0; q < cCD / 256; ++q) {
    int c = tid + q * 256;
    float w0 = conv_w[c*3 + 0], w1 = conv_w[c*3 + 1], w2 = conv_w[c*3 + 2];
    float s = conv_b[c];
    if (l >= 2) s += g_zx[base0 - 2*(size_t)cDP + c] * w0;
    if (l >= 1) s += g_zx[base0 -   (size_t)cDP + c] * w1;
    s += g_zx[base0 + c] * w2;
    s = s * fsig(s);
    g_xbc[obase + c] = s;
  }
  if (tid < cNH) {
    float v = g_zx[(size_t)row * cDP + (cDP - cNH) + tid] + dt_bias[tid];
    float sp = (v > 15.0f) ? v : log1pf(expf(v));
    g_dt[((size_t)b * cNH + tid) * cL + l] = sp;
  }
}

// ============= K3: per-chunk inclusive cumsum of dt*A =====================
__global__ void __launch_bounds__(128) k_scan(const float* __restrict__ A_log)
{
  const int h = blockIdx.x, c = blockIdx.y, b = blockIdx.z;
  const int l = threadIdx.x;
  const float ah = -expf(A_log[h]);
  const size_t base = ((size_t)b * cNH + h) * cL + c * cCK;
  __shared__ float s[128];
  s[l] = g_dt[base + l] * ah;
  __syncthreads();
  #pragma unroll
  for (int off = 1; off < 128; off <<= 1) {
    float t = (l >= off) ? s[l - off] : 0.0f;
    __syncthreads();
    s[l] += t;
    __syncthreads();
  }
  g_ac[base + l] = s[l];
  if (l == 127) g_T[((size_t)b * cNH + h) * cNC + c] = s[127];
}

// ============= K4: chunk states  states[n][p] = sum_l B[l,n] dec[l] X[l,p] =
__global__ void __launch_bounds__(256) k_states()
{
  const int h = blockIdx.x, c = blockIdx.y, b = blockIdx.z;
  const int tid = threadIdx.x;
  __shared__ float Bt[32][132];   // [l-sub][n]
  __shared__ float Xt[32][68];    // [l-sub][p]
  __shared__ float acs[128];
  __shared__ float Tsh;
  const size_t acb = ((size_t)b * cNH + h) * cL + c * cCK;
  if (tid < 128) acs[tid] = g_ac[acb + tid];
  if (tid == 0)  Tsh = g_T[((size_t)b * cNH + h) * cNC + c];
  __syncthreads();
  const float T = Tsh;
  const int px = tid & 15, ny = tid >> 4;
  const int p0 = px * 4, n0 = ny * 8;
  float acc[8][4] = {};
  const size_t rowbase = ((size_t)(b * cL + c * cCK)) * cCD;
  for (int lt = 0; lt < 4; ++lt) {
    #pragma unroll
    for (int q = 0; q < 4; ++q) {
      int i = tid + q * 256;
      int lr = i >> 5, nq = i & 31;
      int gl = lt * 32 + lr;
      float4 v = *(const float4*)(&g_xbc[rowbase + (size_t)gl * cCD + cDS + nq * 4]);
      *(float4*)&Bt[lr][nq * 4] = v;
    }
    #pragma unroll
    for (int q = 0; q < 2; ++q) {
      int i = tid + q * 256;
      int lr = i >> 4, pq = i & 15;
      int gl = lt * 32 + lr;
      float dtv = g_dt[acb + gl];
      float dec = fexp(T - acs[gl]);
      float sc = dtv * dec;
      float4 x = *(const float4*)(&g_xbc[rowbase + (size_t)gl * cCD + h * cHD + pq * 4]);
      x.x *= sc; x.y *= sc; x.z *= sc; x.w *= sc;
      *(float4*)&Xt[lr][pq * 4] = x;
    }
    __syncthreads();
    #pragma unroll
    for (int l = 0; l < 32; ++l) {
      float4 a0 = *(const float4*)&Bt[l][n0];
      float4 a1 = *(const float4*)&Bt[l][n0 + 4];
      float4 bv = *(const float4*)&Xt[l][p0];
      float a[8] = {a0.x, a0.y, a0.z, a0.w, a1.x, a1.y, a1.z, a1.w};
      #pragma unroll
      for (int i = 0; i < 8; ++i) {
        acc[i][0] += a[i] * bv.x; acc[i][1] += a[i] * bv.y;
        acc[i][2] += a[i] * bv.z; acc[i][3] += a[i] * bv.w;
      }
    }
    __syncthreads();
  }
  const size_t ob = (((size_t)b * cNC + c) * cNH + h) * (cST * cHD);
  #pragma unroll
  for (int i = 0; i < 8; ++i) {
    float4 v = make_float4(acc[i][0], acc[i][1], acc[i][2], acc[i][3]);
    *(float4*)&g_cs[ob + (size_t)(n0 + i) * cHD + p0] = v;
  }
}

// ============= K5: inter-chunk carry scan =================================
__global__ void __launch_bounds__(256) k_carry()
{
  const int bh = blockIdx.x;          // b*NH + h
  const int b = bh >> 6, h = bh & 63;
  const int tid = threadIdx.x;
  float carry[32];
  #pragma unroll
  for (int j = 0; j < 32; ++j) carry[j] = 0.0f;
  for (int c = 0; c < cNC; ++c) {
    if (c > 0) {
      float eT = fexp(g_T[(size_t)bh * cNC + (c - 1)]);
      const size_t inb = (((size_t)b * cNC + (c - 1)) * cNH + h) * (cST * cHD);
      #pragma unroll
      for (int j = 0; j < 32; ++j)
        carry[j] = carry[j] * eT + g_cs[inb + tid + j * 256];
    }
    const size_t ob = (((size_t)b * cNC + c) * cNH + h) * (cST * cHD);
    #pragma unroll
    for (int j = 0; j < 32; ++j)
      g_pv[ob + tid + j * 256] = carry[j];
  }
}

// ============= K6: SSD Y kernel (diag + off + D term) =====================
__global__ void __launch_bounds__(256) k_ssd_y(const float* __restrict__ Dv)
{
  extern __shared__ float sm[];
  float* Ct  = sm;                        // [n][l] stride 132 (C transposed)
  float* Bt  = sm + 128 * 132;            // [n][l] then Gs[l][s] stride 132
  float* Xs  = sm + 2 * 128 * 132;        // [s][p] stride 68, then Pn[n][p]
  float* acs = sm + 2 * 128 * 132 + 128 * 68;
  const int h = blockIdx.x, c = blockIdx.y, b = blockIdx.z;
  const int tid = threadIdx.x;
  const size_t rowbase = ((size_t)(b * cL + c * cCK)) * cCD;
  const size_t acb = ((size_t)b * cNH + h) * cL + c * cCK;
  if (tid < 128) acs[tid] = g_ac[acb + tid];
  // load C,B transposed into [n][l]
  #pragma unroll 1
  for (int q = 0; q < 16; ++q) {
    int i = tid + q * 256;
    int l = i >> 5, nq = i & 31;
    const float* src = &g_xbc[rowbase + (size_t)l * cCD];
    float4 cv = *(const float4*)(src + cDS + cST + nq * 4);
    float4 bv = *(const float4*)(src + cDS + nq * 4);
    int n = nq * 4;
    Ct[(n+0)*132 + l] = cv.x; Ct[(n+1)*132 + l] = cv.y;
    Ct[(n+2)*132 + l] = cv.z; Ct[(n+3)*132 + l] = cv.w;
    Bt[(n+0)*132 + l] = bv.x; Bt[(n+1)*132 + l] = bv.y;
    Bt[(n+2)*132 + l] = bv.z; Bt[(n+3)*132 + l] = bv.w;
  }
  __syncthreads();
  // phase 1: G[l][s] = sum_n C[l,n] B[s,n]
  const int ty = tid >> 4, tx = tid & 15;
  const int l0 = ty * 8, s0 = tx * 8;
  float accG[8][8] = {};
  for (int n = 0; n < cST; ++n) {
    float4 a0 = *(const float4*)&Ct[n*132 + l0];
    float4 a1 = *(const float4*)&Ct[n*132 + l0 + 4];
    float4 b0 = *(const float4*)&Bt[n*132 + s0];
    float4 b1 = *(const float4*)&Bt[n*132 + s0 + 4];
    float a[8]  = {a0.x, a0.y, a0.z, a0.w, a1.x, a1.y, a1.z, a1.w};
    float bb[8] = {b0.x, b0.y, b0.z, b0.w, b1.x, b1.y, b1.z, b1.w};
    #pragma unroll
    for (int i = 0; i < 8; ++i)
      #pragma unroll
      for (int j = 0; j < 8; ++j) accG[i][j] += a[i] * bb[j];
  }
  __syncthreads();
  // phase 1.5: masked decayed G -> Gs (Bt region) ; load Xs = x*dt
  #pragma unroll
  for (int i = 0; i < 8; ++i) {
    int l = l0 + i;
    float al = acs[l];
    #pragma unroll
    for (int j = 0; j < 8; ++j) {
      int s = s0 + j;
      float m = (s <= l) ? fexp(al - acs[s]) : 0.0f;
      Bt[l*132 + s] = accG[i][j] * m;
    }
  }
  #pragma unroll 1
  for (int q = 0; q < 8; ++q) {
    int i = tid + q * 256;
    int s = i >> 4, pq = i & 15;
    float dtv = g_dt[acb + s];
    float4 x = *(const float4*)(&g_xbc[rowbase + (size_t)s * cCD + h * cHD + pq * 4]);
    x.x *= dtv; x.y *= dtv; x.z *= dtv; x.w *= dtv;
    *(float4*)&Xs[s*68 + pq*4] = x;
  }
  __syncthreads();
  // phase 2: Y_diag[l][p] = sum_s Gs[l][s] Xs[s][p]
  const int ly = tid & 15, px = tid >> 4;
  const int p0 = px * 4;
  float acc2[8][4] = {};
  for (int s = 0; s < cCK; s += 4) {
    float4 x0 = *(const float4*)&Xs[(s+0)*68 + p0];
    float4 x1 = *(const float4*)&Xs[(s+1)*68 + p0];
    float4 x2 = *(const float4*)&Xs[(s+2)*68 + p0];
    float4 x3 = *(const float4*)&Xs[(s+3)*68 + p0];
    #pragma unroll
    for (int i = 0; i < 8; ++i) {
      int l = ly + 16 * i;
      float4 g = *(const float4*)&Bt[l*132 + s];
      acc2[i][0] += g.x*x0.x + g.y*x1.x + g.z*x2.x + g.w*x3.x;
      acc2[i][1] += g.x*x0.y + g.y*x1.y + g.z*x2.y + g.w*x3.y;
      acc2[i][2] += g.x*x0.z + g.y*x1.z + g.z*x2.z + g.w*x3.z;
      acc2[i][3] += g.x*x0.w + g.y*x1.w + g.z*x2.w + g.w*x3.w;
    }
  }
  __syncthreads();
  // load prev states Pn[n][p] into Xs region
  {
    const size_t pb = (((size_t)b * cNC + c) * cNH + h) * (cST * cHD);
    #pragma unroll 1
    for (int q = 0; q < 8; ++q) {
      int i = tid + q * 256;
      int n = i >> 4, pq = i & 15;
      float4 v = *(const float4*)(&g_pv[pb + (size_t)n * cHD + pq * 4]);
      *(float4*)&Xs[n*68 + pq*4] = v;
    }
  }
  __syncthreads();
  // phase 3: Y_off[l][p] = sum_n C[l,n] Pn[n][p]  (scaled by exp(ac[l]) later)
  float acc3[8][4] = {};
  for (int n = 0; n < cST; ++n) {
    float4 pv = *(const float4*)&Xs[n*68 + p0];
    const float* crow = &Ct[n*132 + ly];
    #pragma unroll
    for (int i = 0; i < 8; ++i) {
      float a = crow[16 * i];
      acc3[i][0] += a * pv.x; acc3[i][1] += a * pv.y;
      acc3[i][2] += a * pv.z; acc3[i][3] += a * pv.w;
    }
  }
  // epilogue
  const float Dh = Dv[h];
  #pragma unroll
  for (int i = 0; i < 8; ++i) {
    int l = ly + 16 * i;
    int gl = c * cCK + l;
    float eAl = fexp(acs[l]);
    float4 xv = *(const float4*)(&g_xbc[rowbase + (size_t)l * cCD + h * cHD + p0]);
    float4 o;
    o.x = acc2[i][0] + eAl * acc3[i][0] + Dh * xv.x;
    o.y = acc2[i][1] + eAl * acc3[i][1] + Dh * xv.y;
    o.z = acc2[i][2] + eAl * acc3[i][2] + Dh * xv.z;
    o.w = acc2[i][3] + eAl * acc3[i][3] + Dh * xv.w;
    *(float4*)&g_y[((size_t)(b * cL + gl)) * cDS + h * cHD + p0] = o;
  }
}

// ============= K7: gate (silu(z)) + RMSNorm ===============================
__global__ void __launch_bounds__(256) k_gate_norm(const float* __restrict__ norm_w)
{
  const int row = blockIdx.x;          // b*L + l
  const int tid = threadIdx.x;
  const size_t zb = (size_t)row * cDP;
  const size_t yb = (size_t)row * cDS;
  float v[16];
  float ss = 0.0f;
  #pragma unroll
  for (int q = 0; q < 16; ++q) {
    int i = tid + q * 256;
    float z = g_zx[zb + i];
    float y = g_y[yb + i];
    float t = y * z * fsig(z);
    v[q] = t;
    ss += t * t;
  }
  #pragma unroll
  for (int o = 16; o > 0; o >>= 1) ss += __shfl_xor_sync(0xffffffffu, ss, o);
  __shared__ float red[8];
  if ((tid & 31) == 0) red[tid >> 5] = ss;
  __syncthreads();
  float tot = 0.0f;
  #pragma unroll
  for (int j = 0; j < 8; ++j) tot += red[j];
  const float scale = rsqrtf(tot / (float)cDS + cEPS);
  #pragma unroll
  for (int q = 0; q < 16; ++q) {
    int i = tid + q * 256;
    g_y[yb + i] = v[q] * scale * norm_w[i];
  }
}

// ============= K9: out + reverse(out) =====================================
__global__ void __launch_bounds__(256) k_revadd(float* __restrict__ out)
{
  const int idx4 = blockIdx.x * 256 + threadIdx.x;    // float4 index
  const int tot4 = cB * cL * cDM / 4;
  if (idx4 >= tot4) return;
  const int i = idx4 * 4;
  const int b = i / (cL * cDM);
  const int r = i - b * (cL * cDM);
  const int l = r / cDM;
  const int d = r - l * cDM;
  const size_t rev = ((size_t)b * cL + (cL - 1 - l)) * cDM + d;
  float4 a = *(const float4*)(&g_o[i]);
  float4 c = *(const float4*)(&g_o[rev]);
  a.x += c.x; a.y += c.y; a.z += c.z; a.w += c.w;
  *(float4*)(out + i) = a;
}

// ==========================================================================
extern "C" void kernel_launch(void* const* d_in, const int* in_sizes, int n_in,
                              void* d_out, int out_size) {
  const float* u       = (const float*)d_in[0];
  const float* W_in    = (const float*)d_in[1];
  const float* conv_w  = (const float*)d_in[2];
  const float* conv_b  = (const float*)d_in[3];
  const float* dt_bias = (const float*)d_in[4];
  const float* A_log   = (const float*)d_in[5];
  const float* Dv      = (const float*)d_in[6];
  const float* norm_w  = (const float*)d_in[7];
  const float* W_out   = (const float*)d_in[8];
  float* out = (float*)d_out;

  float* zx; cudaGetSymbolAddress((void**)&zx, g_zx);
  float* yb; cudaGetSymbolAddress((void**)&yb, g_y);
  float* ob; cudaGetSymbolAddress((void**)&ob, g_o);

  static bool attr_done = false;
  if (!attr_done) {
    cudaFuncSetAttribute(k_ssd_y, cudaFuncAttributeMaxDynamicSharedMemorySize,
                         (2*128*132 + 128*68 + 128) * 4);
    attr_done = true;
  }

  // K1: in-proj  zx[4096, 8512] = u[4096,2048] @ W_in[8512,2048]^T
  {
    dim3 grid((cDP + 127) / 128, (cB * cL) / 128);
    sgemm_tn<<<grid, 256>>>(u, W_in, zx, cB * cL, cDP, cDM);
  }
  // K2: conv + silu + dt
  k_conv<<<cB * cL, 256>>>(conv_w, conv_b, dt_bias);
  // K3: per-chunk cumsum
  { dim3 grid(cNH, cNC, cB); k_scan<<<grid, 128>>>(A_log); }
  // K4: chunk states
  { dim3 grid(cNH, cNC, cB); k_states<<<grid, 256>>>(); }
  // K5: carry scan
  k_carry<<<cB * cNH, 256>>>();
  // K6: Y
  { dim3 grid(cNH, cNC, cB);
    k_ssd_y<<<grid, 256, (2*128*132 + 128*68 + 128) * 4>>>(Dv); }
  // K7: gate + rmsnorm
  k_gate_norm<<<cB * cL, 256>>>(norm_w);
  // K8: out-proj  o[4096,2048] = y[4096,4096] @ W_out[2048,4096]^T
  {
    dim3 grid(cDM / 128, (cB * cL) / 128);
    sgemm_tn<<<grid, 256>>>(yb, W_out, ob, cB * cL, cDM, cDS);
  }
  // K9: out + reverse(out)
  k_revadd<<<(cB * cL * cDM / 4 + 255) / 256, 256>>>(out);
}

// round 5
// speedup vs baseline: 2.1010x; 2.1010x over previous
#include <cuda_runtime.h>
#include <cuda_bf16.h>
#include <cstdint>

#define DEVFN static __device__ __forceinline__

constexpr int cB  = 2;
constexpr int cL  = 2048;
constexpr int cDM = 2048;            // D_MODEL
constexpr int cDS = 4096;            // D_SSM
constexpr int cST = 128;             // D_STATE
constexpr int cNH = 64;              // NHEADS
constexpr int cHD = 64;              // HEADDIM
constexpr int cCK = 128;             // CHUNK
constexpr int cNC = cL / cCK;        // 16
constexpr int cDP = 2*cDS + 2*cST + cNH;   // 8512
constexpr int cCD = cDS + 2*cST;           // 4352
constexpr float cEPS = 1e-5f;

constexpr int cNPAD1 = 8704;         // padded N for GEMM1 (68 * 128)

// ---------------- scratch (static device globals; no allocation) ----------
__device__ float g_zx [(size_t)cB*cL*cDP];           // in-proj output
__device__ float g_xbc[(size_t)cB*cL*cCD];           // conv+silu output
__device__ float g_dt [(size_t)cB*cNH*cL];           // softplus dt, [b][h][l]
__device__ float g_ac [(size_t)cB*cNH*cL];           // per-chunk cumsum, [b][h][l]
__device__ float g_T  [(size_t)cB*cNH*cNC];          // chunk totals
__device__ float g_cs [(size_t)cB*cNC*cNH*cST*cHD];  // per-chunk states
__device__ float g_pv [(size_t)cB*cNC*cNH*cST*cHD];  // carried states
__device__ float g_y  [(size_t)cB*cL*cDS];           // y buffer
__device__ float g_o  [(size_t)cB*cL*cDM];           // out-proj output
// split-bf16 operand buffers (hi/lo)
__device__ unsigned short g_ah[(size_t)4096*4096];
__device__ unsigned short g_al[(size_t)4096*4096];
__device__ unsigned short g_bh[(size_t)cNPAD1*2048];
__device__ unsigned short g_bl[(size_t)cNPAD1*2048];

// ---------------- math helpers --------------------------------------------
DEVFN float fexp(float x) {          // exp(x), FFMA-only
  float t = x * 1.44269504088896340736f;
  t = fminf(fmaxf(t, -126.0f), 126.0f);
  float fi = rintf(t);
  float f  = t - fi;
  float p = 1.5403530393381610e-4f;
  p = fmaf(p, f, 1.3333558146428443e-3f);
  p = fmaf(p, f, 9.6181291076284772e-3f);
  p = fmaf(p, f, 5.5504108664821580e-2f);
  p = fmaf(p, f, 2.4022650695910071e-1f);
  p = fmaf(p, f, 6.9314718055994531e-1f);
  p = fmaf(p, f, 1.0f);
  int i = (int)fi;
  return __int_as_float((i + 127) << 23) * p;
}
DEVFN float fsig(float x) { return 1.0f / (1.0f + fexp(-x)); }

DEVFN uint32_t smem_to_u32(const void* p) {
  uint32_t a;
  asm("{ .reg .u64 t; cvta.to.shared.u64 t, %1; cvt.u32.u64 %0, t; }"
      : "=r"(a) : "l"(p));
  return a;
}
DEVFN void cp16(uint32_t saddr, const void* gptr) {
  asm volatile("cp.async.cg.shared.global [%0], [%1], 16;"
               :: "r"(saddr), "l"(gptr) : "memory");
}
DEVFN void ldsm4(uint32_t (&r)[4], uint32_t a) {
  asm volatile("ldmatrix.sync.aligned.m8n8.x4.shared.b16 {%0,%1,%2,%3}, [%4];"
    : "=r"(r[0]), "=r"(r[1]), "=r"(r[2]), "=r"(r[3]) : "r"(a));
}
DEVFN void mma16816(float (&d)[4], const uint32_t (&a)[4], uint32_t b0, uint32_t b1) {
  asm volatile("mma.sync.aligned.m16n8k16.row.col.f32.bf16.bf16.f32 "
    "{%0,%1,%2,%3},{%4,%5,%6,%7},{%8,%9},{%0,%1,%2,%3};"
    : "+f"(d[0]), "+f"(d[1]), "+f"(d[2]), "+f"(d[3])
    : "r"(a[0]), "r"(a[1]), "r"(a[2]), "r"(a[3]), "r"(b0), "r"(b1));
}

// ============= K0: fp32 -> (hi, lo) bf16 split, with row zero-padding ======
__global__ void __launch_bounds__(256) k_cvt(
    const float* __restrict__ src, unsigned short* __restrict__ hi,
    unsigned short* __restrict__ lo, int srcRows, int K, long tot)
{
  long i = ((long)blockIdx.x * 256 + threadIdx.x) * 4;
  if (i >= tot) return;
  long row = i / K;
  float4 v = make_float4(0.f, 0.f, 0.f, 0.f);
  if (row < srcRows) v = *(const float4*)(src + i);
  __nv_bfloat16 h0 = __float2bfloat16_rn(v.x);
  __nv_bfloat16 h1 = __float2bfloat16_rn(v.y);
  __nv_bfloat16 h2 = __float2bfloat16_rn(v.z);
  __nv_bfloat16 h3 = __float2bfloat16_rn(v.w);
  __nv_bfloat16 l0 = __float2bfloat16_rn(v.x - __bfloat162float(h0));
  __nv_bfloat16 l1 = __float2bfloat16_rn(v.y - __bfloat162float(h1));
  __nv_bfloat16 l2 = __float2bfloat16_rn(v.z - __bfloat162float(h2));
  __nv_bfloat16 l3 = __float2bfloat16_rn(v.w - __bfloat162float(h3));
  ushort4 hv, lv;
  hv.x = *(unsigned short*)&h0; hv.y = *(unsigned short*)&h1;
  hv.z = *(unsigned short*)&h2; hv.w = *(unsigned short*)&h3;
  lv.x = *(unsigned short*)&l0; lv.y = *(unsigned short*)&l1;
  lv.z = *(unsigned short*)&l2; lv.w = *(unsigned short*)&l3;
  *(ushort4*)(hi + i) = hv;
  *(ushort4*)(lo + i) = lv;
}

// ============= split-bf16 mma.sync GEMM: C[M,N] = A[M,K] * B[N,K]^T ========
// 128x128x32 CTA tile, 8 warps (4Mx2N), warp tile 32x64, cp.async double buf.
constexpr int ROWB  = 80;                 // smem bytes per 32-col bf16 row (+pad)
constexpr int TILEB = 128 * ROWB;         // 10240 bytes per operand tile
constexpr int BUFB  = 4 * TILEB;          // Ah|Al|Bh|Bl
constexpr int SMEM_GEMM = 2 * BUFB;       // 81920

__global__ void __launch_bounds__(256, 2) gemm_mma(
    const __nv_bfloat16* __restrict__ Ah, const __nv_bfloat16* __restrict__ Al,
    const __nv_bfloat16* __restrict__ Bh, const __nv_bfloat16* __restrict__ Bl,
    float* __restrict__ C, int M, int N, int K)
{
  extern __shared__ char smem[];
  const uint32_t sb0 = smem_to_u32(smem);
  const int tid = threadIdx.x;
  const int lane = tid & 31, wid = tid >> 5;
  const int bm = blockIdx.y * 128, bn = blockIdx.x * 128;
  const int wm = (wid >> 1) * 32, wn = (wid & 1) * 64;

  float acc[2][8][4];
  #pragma unroll
  for (int i = 0; i < 2; ++i)
    #pragma unroll
    for (int j = 0; j < 8; ++j)
      #pragma unroll
      for (int q = 0; q < 4; ++q) acc[i][j][q] = 0.0f;

  auto load_tile = [&](int kt, int buf) {
    const uint32_t sb = sb0 + buf * BUFB;
    const long kb = (long)kt * 32;
    #pragma unroll
    for (int i = 0; i < 2; ++i) {
      int o = tid + 256 * i;
      int row = o >> 2, seg = o & 3;
      uint32_t soff = row * ROWB + seg * 16;
      long ga = (long)(bm + row) * K + kb + seg * 8;
      long gb = (long)(bn + row) * K + kb + seg * 8;
      cp16(sb + soff,             Ah + ga);
      cp16(sb + TILEB + soff,     Al + ga);
      cp16(sb + 2*TILEB + soff,   Bh + gb);
      cp16(sb + 3*TILEB + soff,   Bl + gb);
    }
    asm volatile("cp.async.commit_group;" ::: "memory");
  };

  load_tile(0, 0);
  const int KT = K >> 5;
  for (int kt = 0; kt < KT; ++kt) {
    const int buf = kt & 1;
    if (kt + 1 < KT) {
      load_tile(kt + 1, buf ^ 1);
      asm volatile("cp.async.wait_group 1;" ::: "memory");
    } else {
      asm volatile("cp.async.wait_group 0;" ::: "memory");
    }
    __syncthreads();
    const uint32_t sb = sb0 + buf * BUFB;
    #pragma unroll
    for (int h = 0; h < 2; ++h) {           // two k16 halves of BK=32
      uint32_t ah[2][4], al[2][4];
      #pragma unroll
      for (int mi = 0; mi < 2; ++mi) {
        uint32_t ad = sb + (uint32_t)(wm + mi*16 + (lane & 15)) * ROWB
                         + h*32 + (lane >> 4) * 16;
        ldsm4(ah[mi], ad);
        ldsm4(al[mi], ad + TILEB);
      }
      #pragma unroll
      for (int nj2 = 0; nj2 < 4; ++nj2) {   // 16-wide n chunks
        uint32_t bd = sb + 2*TILEB
          + (uint32_t)(wn + nj2*16 + (lane & 7) + ((lane >> 4) << 3)) * ROWB
          + h*32 + ((lane >> 3) & 1) * 16;
        uint32_t bh4[4], bl4[4];
        ldsm4(bh4, bd);
        ldsm4(bl4, bd + TILEB);
        #pragma unroll
        for (int mi = 0; mi < 2; ++mi) {
          #pragma unroll
          for (int s = 0; s < 2; ++s) {
            int nj = nj2 * 2 + s;
            mma16816(acc[mi][nj], ah[mi], bh4[2*s], bh4[2*s+1]);
            mma16816(acc[mi][nj], ah[mi], bl4[2*s], bl4[2*s+1]);
            mma16816(acc[mi][nj], al[mi], bh4[2*s], bh4[2*s+1]);
          }
        }
      }
    }
    __syncthreads();
  }

  // epilogue: acc -> C (fp32), guard col < N (B rows zero-padded)
  #pragma unroll
  for (int mi = 0; mi < 2; ++mi) {
    int row = bm + wm + mi*16 + (lane >> 2);
    #pragma unroll
    for (int nj = 0; nj < 8; ++nj) {
      int col = bn + wn + nj*8 + (lane & 3)*2;
      if (col < N) {
        *(float2*)(C + (long)row * N + col) =
            make_float2(acc[mi][nj][0], acc[mi][nj][1]);
        *(float2*)(C + (long)(row + 8) * N + col) =
            make_float2(acc[mi][nj][2], acc[mi][nj][3]);
      }
    }
  }
}

// ============= K2: conv1d + SiLU + softplus(dt) ===========================
__global__ void __launch_bounds__(256) k_conv(
    const float* __restrict__ conv_w, const float* __restrict__ conv_b,
    const float* __restrict__ dt_bias)
{
  const int row = blockIdx.x;           // b*L + l
  const int b = row / cL, l = row % cL;
  const int tid = threadIdx.x;
  const size_t base0 = (size_t)row * cDP + cDS;
  const size_t obase = (size_t)row * cCD;
  #pragma unroll 1
  for (int q = 0; q < cCD / 256; ++q) {
    int c = tid + q * 256;
    float w0 = conv_w[c*3 + 0], w1 = conv_w[c*3 + 1], w2 = conv_w[c*3 + 2];
    float s = conv_b[c];
    if (l >= 2) s += g_zx[base0 - 2*(size_t)cDP + c] * w0;
    if (l >= 1) s += g_zx[base0 -   (size_t)cDP + c] * w1;
    s += g_zx[base0 + c] * w2;
    s = s * fsig(s);
    g_xbc[obase + c] = s;
  }
  if (tid < cNH) {
    float v = g_zx[(size_t)row * cDP + (cDP - cNH) + tid] + dt_bias[tid];
    float sp = (v > 15.0f) ? v : log1pf(expf(v));
    g_dt[((size_t)b * cNH + tid) * cL + l] = sp;
  }
}

// ============= K3: per-chunk inclusive cumsum of dt*A =====================
__global__ void __launch_bounds__(128) k_scan(const float* __restrict__ A_log)
{
  const int h = blockIdx.x, c = blockIdx.y, b = blockIdx.z;
  const int l = threadIdx.x;
  const float ah = -expf(A_log[h]);
  const size_t base = ((size_t)b * cNH + h) * cL + c * cCK;
  __shared__ float s[128];
  s[l] = g_dt[base + l] * ah;
  __syncthreads();
  #pragma unroll
  for (int off = 1; off < 128; off <<= 1) {
    float t = (l >= off) ? s[l - off] : 0.0f;
    __syncthreads();
    s[l] += t;
    __syncthreads();
  }
  g_ac[base + l] = s[l];
  if (l == 127) g_T[((size_t)b * cNH + h) * cNC + c] = s[127];
}

// ============= K4: chunk states ===========================================
__global__ void __launch_bounds__(256) k_states()
{
  const int h = blockIdx.x, c = blockIdx.y, b = blockIdx.z;
  const int tid = threadIdx.x;
  __shared__ float Bt[32][132];
  __shared__ float Xt[32][68];
  __shared__ float acs[128];
  __shared__ float Tsh;
  const size_t acb = ((size_t)b * cNH + h) * cL + c * cCK;
  if (tid < 128) acs[tid] = g_ac[acb + tid];
  if (tid == 0)  Tsh = g_T[((size_t)b * cNH + h) * cNC + c];
  __syncthreads();
  const float T = Tsh;
  const int px = tid & 15, ny = tid >> 4;
  const int p0 = px * 4, n0 = ny * 8;
  float acc[8][4] = {};
  const size_t rowbase = ((size_t)(b * cL + c * cCK)) * cCD;
  for (int lt = 0; lt < 4; ++lt) {
    #pragma unroll
    for (int q = 0; q < 4; ++q) {
      int i = tid + q * 256;
      int lr = i >> 5, nq = i & 31;
      int gl = lt * 32 + lr;
      float4 v = *(const float4*)(&g_xbc[rowbase + (size_t)gl * cCD + cDS + nq * 4]);
      *(float4*)&Bt[lr][nq * 4] = v;
    }
    #pragma unroll
    for (int q = 0; q < 2; ++q) {
      int i = tid + q * 256;
      int lr = i >> 4, pq = i & 15;
      int gl = lt * 32 + lr;
      float dtv = g_dt[acb + gl];
      float dec = fexp(T - acs[gl]);
      float sc = dtv * dec;
      float4 x = *(const float4*)(&g_xbc[rowbase + (size_t)gl * cCD + h * cHD + pq * 4]);
      x.x *= sc; x.y *= sc; x.z *= sc; x.w *= sc;
      *(float4*)&Xt[lr][pq * 4] = x;
    }
    __syncthreads();
    #pragma unroll
    for (int l = 0; l < 32; ++l) {
      float4 a0 = *(const float4*)&Bt[l][n0];
      float4 a1 = *(const float4*)&Bt[l][n0 + 4];
      float4 bv = *(const float4*)&Xt[l][p0];
      float a[8] = {a0.x, a0.y, a0.z, a0.w, a1.x, a1.y, a1.z, a1.w};
      #pragma unroll
      for (int i = 0; i < 8; ++i) {
        acc[i][0] += a[i] * bv.x; acc[i][1] += a[i] * bv.y;
        acc[i][2] += a[i] * bv.z; acc[i][3] += a[i] * bv.w;
      }
    }
    __syncthreads();
  }
  const size_t ob = (((size_t)b * cNC + c) * cNH + h) * (cST * cHD);
  #pragma unroll
  for (int i = 0; i < 8; ++i) {
    float4 v = make_float4(acc[i][0], acc[i][1], acc[i][2], acc[i][3]);
    *(float4*)&g_cs[ob + (size_t)(n0 + i) * cHD + p0] = v;
  }
}

// ============= K5: inter-chunk carry scan =================================
__global__ void __launch_bounds__(256) k_carry()
{
  const int bh = blockIdx.x;
  const int b = bh >> 6, h = bh & 63;
  const int tid = threadIdx.x;
  float carry[32];
  #pragma unroll
  for (int j = 0; j < 32; ++j) carry[j] = 0.0f;
  for (int c = 0; c < cNC; ++c) {
    if (c > 0) {
      float eT = fexp(g_T[(size_t)bh * cNC + (c - 1)]);
      const size_t inb = (((size_t)b * cNC + (c - 1)) * cNH + h) * (cST * cHD);
      #pragma unroll
      for (int j = 0; j < 32; ++j)
        carry[j] = carry[j] * eT + g_cs[inb + tid + j * 256];
    }
    const size_t ob = (((size_t)b * cNC + c) * cNH + h) * (cST * cHD);
    #pragma unroll
    for (int j = 0; j < 32; ++j)
      g_pv[ob + tid + j * 256] = carry[j];
  }
}

// ============= K6: SSD Y kernel ===========================================
__global__ void __launch_bounds__(256) k_ssd_y(const float* __restrict__ Dv)
{
  extern __shared__ float sm[];
  float* Ct  = sm;
  float* Bt  = sm + 128 * 132;
  float* Xs  = sm + 2 * 128 * 132;
  float* acs = sm + 2 * 128 * 132 + 128 * 68;
  const int h = blockIdx.x, c = blockIdx.y, b = blockIdx.z;
  const int tid = threadIdx.x;
  const size_t rowbase = ((size_t)(b * cL + c * cCK)) * cCD;
  const size_t acb = ((size_t)b * cNH + h) * cL + c * cCK;
  if (tid < 128) acs[tid] = g_ac[acb + tid];
  #pragma unroll 1
  for (int q = 0; q < 16; ++q) {
    int i = tid + q * 256;
    int l = i >> 5, nq = i & 31;
    const float* src = &g_xbc[rowbase + (size_t)l * cCD];
    float4 cv = *(const float4*)(src + cDS + cST + nq * 4);
    float4 bv = *(const float4*)(src + cDS + nq * 4);
    int n = nq * 4;
    Ct[(n+0)*132 + l] = cv.x; Ct[(n+1)*132 + l] = cv.y;
    Ct[(n+2)*132 + l] = cv.z; Ct[(n+3)*132 + l] = cv.w;
    Bt[(n+0)*132 + l] = bv.x; Bt[(n+1)*132 + l] = bv.y;
    Bt[(n+2)*132 + l] = bv.z; Bt[(n+3)*132 + l] = bv.w;
  }
  __syncthreads();
  const int ty = tid >> 4, tx = tid & 15;
  const int l0 = ty * 8, s0 = tx * 8;
  float accG[8][8] = {};
  for (int n = 0; n < cST; ++n) {
    float4 a0 = *(const float4*)&Ct[n*132 + l0];
    float4 a1 = *(const float4*)&Ct[n*132 + l0 + 4];
    float4 b0 = *(const float4*)&Bt[n*132 + s0];
    float4 b1 = *(const float4*)&Bt[n*132 + s0 + 4];
    float a[8]  = {a0.x, a0.y, a0.z, a0.w, a1.x, a1.y, a1.z, a1.w};
    float bb[8] = {b0.x, b0.y, b0.z, b0.w, b1.x, b1.y, b1.z, b1.w};
    #pragma unroll
    for (int i = 0; i < 8; ++i)
      #pragma unroll
      for (int j = 0; j < 8; ++j) accG[i][j] += a[i] * bb[j];
  }
  __syncthreads();
  #pragma unroll
  for (int i = 0; i < 8; ++i) {
    int l = l0 + i;
    float al = acs[l];
    #pragma unroll
    for (int j = 0; j < 8; ++j) {
      int s = s0 + j;
      float m = (s <= l) ? fexp(al - acs[s]) : 0.0f;
      Bt[l*132 + s] = accG[i][j] * m;
    }
  }
  #pragma unroll 1
  for (int q = 0; q < 8; ++q) {
    int i = tid + q * 256;
    int s = i >> 4, pq = i & 15;
    float dtv = g_dt[acb + s];
    float4 x = *(const float4*)(&g_xbc[rowbase + (size_t)s * cCD + h * cHD + pq * 4]);
    x.x *= dtv; x.y *= dtv; x.z *= dtv; x.w *= dtv;
    *(float4*)&Xs[s*68 + pq*4] = x;
  }
  __syncthreads();
  const int ly = tid & 15, px = tid >> 4;
  const int p0 = px * 4;
  float acc2[8][4] = {};
  for (int s = 0; s < cCK; s += 4) {
    float4 x0 = *(const float4*)&Xs[(s+0)*68 + p0];
    float4 x1 = *(const float4*)&Xs[(s+1)*68 + p0];
    float4 x2 = *(const float4*)&Xs[(s+2)*68 + p0];
    float4 x3 = *(const float4*)&Xs[(s+3)*68 + p0];
    #pragma unroll
    for (int i = 0; i < 8; ++i) {
      int l = ly + 16 * i;
      float4 g = *(const float4*)&Bt[l*132 + s];
      acc2[i][0] += g.x*x0.x + g.y*x1.x + g.z*x2.x + g.w*x3.x;
      acc2[i][1] += g.x*x0.y + g.y*x1.y + g.z*x2.y + g.w*x3.y;
      acc2[i][2] += g.x*x0.z + g.y*x1.z + g.z*x2.z + g.w*x3.z;
      acc2[i][3] += g.x*x0.w + g.y*x1.w + g.z*x2.w + g.w*x3.w;
    }
  }
  __syncthreads();
  {
    const size_t pb = (((size_t)b * cNC + c) * cNH + h) * (cST * cHD);
    #pragma unroll 1
    for (int q = 0; q < 8; ++q) {
      int i = tid + q * 256;
      int n = i >> 4, pq = i & 15;
      float4 v = *(const float4*)(&g_pv[pb + (size_t)n * cHD + pq * 4]);
      *(float4*)&Xs[n*68 + pq*4] = v;
    }
  }
  __syncthreads();
  float acc3[8][4] = {};
  for (int n = 0; n < cST; ++n) {
    float4 pv = *(const float4*)&Xs[n*68 + p0];
    const float* crow = &Ct[n*132 + ly];
    #pragma unroll
    for (int i = 0; i < 8; ++i) {
      float a = crow[16 * i];
      acc3[i][0] += a * pv.x; acc3[i][1] += a * pv.y;
      acc3[i][2] += a * pv.z; acc3[i][3] += a * pv.w;
    }
  }
  const float Dh = Dv[h];
  #pragma unroll
  for (int i = 0; i < 8; ++i) {
    int l = ly + 16 * i;
    int gl = c * cCK + l;
    float eAl = fexp(acs[l]);
    float4 xv = *(const float4*)(&g_xbc[rowbase + (size_t)l * cCD + h * cHD + p0]);
    float4 o;
    o.x = acc2[i][0] + eAl * acc3[i][0] + Dh * xv.x;
    o.y = acc2[i][1] + eAl * acc3[i][1] + Dh * xv.y;
    o.z = acc2[i][2] + eAl * acc3[i][2] + Dh * xv.z;
    o.w = acc2[i][3] + eAl * acc3[i][3] + Dh * xv.w;
    *(float4*)&g_y[((size_t)(b * cL + gl)) * cDS + h * cHD + p0] = o;
  }
}

// ============= K7: gate (silu(z)) + RMSNorm ===============================
__global__ void __launch_bounds__(256) k_gate_norm(const float* __restrict__ norm_w)
{
  const int row = blockIdx.x;
  const int tid = threadIdx.x;
  const size_t zb = (size_t)row * cDP;
  const size_t yb = (size_t)row * cDS;
  float v[16];
  float ss = 0.0f;
  #pragma unroll
  for (int q = 0; q < 16; ++q) {
    int i = tid + q * 256;
    float z = g_zx[zb + i];
    float y = g_y[yb + i];
    float t = y * z * fsig(z);
    v[q] = t;
    ss += t * t;
  }
  #pragma unroll
  for (int o = 16; o > 0; o >>= 1) ss += __shfl_xor_sync(0xffffffffu, ss, o);
  __shared__ float red[8];
  if ((tid & 31) == 0) red[tid >> 5] = ss;
  __syncthreads();
  float tot = 0.0f;
  #pragma unroll
  for (int j = 0; j < 8; ++j) tot += red[j];
  const float scale = rsqrtf(tot / (float)cDS + cEPS);
  #pragma unroll
  for (int q = 0; q < 16; ++q) {
    int i = tid + q * 256;
    g_y[yb + i] = v[q] * scale * norm_w[i];
  }
}

// ============= K9: out + reverse(out) =====================================
__global__ void __launch_bounds__(256) k_revadd(float* __restrict__ out)
{
  const int idx4 = blockIdx.x * 256 + threadIdx.x;
  const int tot4 = cB * cL * cDM / 4;
  if (idx4 >= tot4) return;
  const int i = idx4 * 4;
  const int b = i / (cL * cDM);
  const int r = i - b * (cL * cDM);
  const int l = r / cDM;
  const int d = r - l * cDM;
  const size_t rev = ((size_t)b * cL + (cL - 1 - l)) * cDM + d;
  float4 a = *(const float4*)(&g_o[i]);
  float4 c = *(const float4*)(&g_o[rev]);
  a.x += c.x; a.y += c.y; a.z += c.z; a.w += c.w;
  *(float4*)(out + i) = a;
}

// ==========================================================================
extern "C" void kernel_launch(void* const* d_in, const int* in_sizes, int n_in,
                              void* d_out, int out_size) {
  const float* u       = (const float*)d_in[0];
  const float* W_in    = (const float*)d_in[1];
  const float* conv_w  = (const float*)d_in[2];
  const float* conv_b  = (const float*)d_in[3];
  const float* dt_bias = (const float*)d_in[4];
  const float* A_log   = (const float*)d_in[5];
  const float* Dv      = (const float*)d_in[6];
  const float* norm_w  = (const float*)d_in[7];
  const float* W_out   = (const float*)d_in[8];
  float* out = (float*)d_out;

  float* zx; cudaGetSymbolAddress((void**)&zx, g_zx);
  float* yb; cudaGetSymbolAddress((void**)&yb, g_y);
  float* ob; cudaGetSymbolAddress((void**)&ob, g_o);
  unsigned short *ah, *al, *bh, *bl;
  cudaGetSymbolAddress((void**)&ah, g_ah);
  cudaGetSymbolAddress((void**)&al, g_al);
  cudaGetSymbolAddress((void**)&bh, g_bh);
  cudaGetSymbolAddress((void**)&bl, g_bl);

  cudaFuncSetAttribute(k_ssd_y, cudaFuncAttributeMaxDynamicSharedMemorySize,
                       (2*128*132 + 128*68 + 128) * 4);
  cudaFuncSetAttribute(gemm_mma, cudaFuncAttributeMaxDynamicSharedMemorySize,
                       SMEM_GEMM);

  const int M = cB * cL;   // 4096

  // --- GEMM1 prep: u -> (ah, al); W_in -> (bh, bl) padded to 8704 rows ---
  {
    long totA = (long)M * cDM;
    k_cvt<<<(unsigned)((totA/4 + 255)/256), 256>>>(u, ah, al, M, cDM, totA);
    long totB = (long)cNPAD1 * cDM;
    k_cvt<<<(unsigned)((totB/4 + 255)/256), 256>>>(W_in, bh, bl, cDP, cDM, totB);
  }
  // --- GEMM1: zx[4096, 8512] ---
  {
    dim3 grid(cNPAD1 / 128, M / 128);
    gemm_mma<<<grid, 256, SMEM_GEMM>>>(
        (const __nv_bfloat16*)ah, (const __nv_bfloat16*)al,
        (const __nv_bfloat16*)bh, (const __nv_bfloat16*)bl, zx, M, cDP, cDM);
  }
  // --- conv + silu + dt ---
  k_conv<<<cB * cL, 256>>>(conv_w, conv_b, dt_bias);
  // --- per-chunk cumsum ---
  { dim3 grid(cNH, cNC, cB); k_scan<<<grid, 128>>>(A_log); }
  // --- chunk states ---
  { dim3 grid(cNH, cNC, cB); k_states<<<grid, 256>>>(); }
  // --- carry scan ---
  k_carry<<<cB * cNH, 256>>>();
  // --- Y ---
  { dim3 grid(cNH, cNC, cB);
    k_ssd_y<<<grid, 256, (2*128*132 + 128*68 + 128) * 4>>>(Dv); }
  // --- gate + rmsnorm ---
  k_gate_norm<<<cB * cL, 256>>>(norm_w);
  // --- GEMM2 prep: y -> (ah, al); W_out -> (bh, bl) ---
  {
    long totA = (long)M * cDS;
    k_cvt<<<(unsigned)((totA/4 + 255)/256), 256>>>(yb, ah, al, M, cDS, totA);
    long totB = (long)cDM * cDS;
    k_cvt<<<(unsigned)((totB/4 + 255)/256), 256>>>(W_out, bh, bl, cDM, cDS, totB);
  }
  // --- GEMM2: o[4096, 2048] ---
  {
    dim3 grid(cDM / 128, M / 128);
    gemm_mma<<<grid, 256, SMEM_GEMM>>>(
        (const __nv_bfloat16*)ah, (const __nv_bfloat16*)al,
        (const __nv_bfloat16*)bh, (const __nv_bfloat16*)bl, ob, M, cDM, cDS);
  }
  // --- out + reverse(out) ---
  k_revadd<<<(cB * cL * cDM / 4 + 255) / 256, 256>>>(out);
}

// round 7
// speedup vs baseline: 2.5362x; 1.2071x over previous
#include <cuda_runtime.h>
#include <cuda_bf16.h>
#include <cstdint>

#define DEVFN static __device__ __forceinline__

constexpr int cB  = 2;
constexpr int cL  = 2048;
constexpr int cDM = 2048;            // D_MODEL
constexpr int cDS = 4096;            // D_SSM
constexpr int cST = 128;             // D_STATE
constexpr int cNH = 64;              // NHEADS
constexpr int cHD = 64;              // HEADDIM
constexpr int cCK = 128;             // CHUNK
constexpr int cNC = cL / cCK;        // 16
constexpr int cDP = 2*cDS + 2*cST + cNH;   // 8512
constexpr int cCD = cDS + 2*cST;           // 4352
constexpr float cEPS = 1e-5f;

constexpr int cNPAD1 = 8704;         // padded N for GEMM1 (68 * 128)

// ---------------- scratch (static device globals; no allocation) ----------
__device__ float g_zx [(size_t)cB*cL*cDP];           // in-proj output
__device__ float g_xbc[(size_t)cB*cL*cCD];           // conv+silu output
__device__ float g_dt [(size_t)cB*cNH*cL];           // softplus dt, [b][h][l]
__device__ float g_ac [(size_t)cB*cNH*cL];           // per-chunk cumsum, [b][h][l]
__device__ float g_T  [(size_t)cB*cNH*cNC];          // chunk totals
__device__ float g_cs [(size_t)cB*cNC*cNH*cST*cHD];  // per-chunk states
__device__ float g_pv [(size_t)cB*cNC*cNH*cST*cHD];  // carried states
__device__ float g_gm [(size_t)cB*cNC*cCK*cCK];      // unmasked G per (b,c)
__device__ float g_y  [(size_t)cB*cL*cDS];           // y buffer
__device__ float g_o  [(size_t)cB*cL*cDM];           // out-proj output
// split-bf16 operand buffers (hi/lo)
__device__ unsigned short g_ah[(size_t)4096*4096];
__device__ unsigned short g_al[(size_t)4096*4096];
__device__ unsigned short g_bh[(size_t)cNPAD1*2048];
__device__ unsigned short g_bl[(size_t)cNPAD1*2048];

// ---------------- math helpers --------------------------------------------
DEVFN float fexp(float x) {          // exp(x), FFMA-only
  float t = x * 1.44269504088896340736f;
  t = fminf(fmaxf(t, -126.0f), 126.0f);
  float fi = rintf(t);
  float f  = t - fi;
  float p = 1.5403530393381610e-4f;
  p = fmaf(p, f, 1.3333558146428443e-3f);
  p = fmaf(p, f, 9.6181291076284772e-3f);
  p = fmaf(p, f, 5.5504108664821580e-2f);
  p = fmaf(p, f, 2.4022650695910071e-1f);
  p = fmaf(p, f, 6.9314718055994531e-1f);
  p = fmaf(p, f, 1.0f);
  int i = (int)fi;
  return __int_as_float((i + 127) << 23) * p;
}
DEVFN float fsig(float x) { return 1.0f / (1.0f + fexp(-x)); }

DEVFN uint32_t smem_to_u32(const void* p) {
  uint32_t a;
  asm("{ .reg .u64 t; cvta.to.shared.u64 t, %1; cvt.u32.u64 %0, t; }"
      : "=r"(a) : "l"(p));
  return a;
}
DEVFN void cp16(uint32_t saddr, const void* gptr) {
  asm volatile("cp.async.cg.shared.global [%0], [%1], 16;"
               :: "r"(saddr), "l"(gptr) : "memory");
}
DEVFN void ldsm4(uint32_t (&r)[4], uint32_t a) {
  asm volatile("ldmatrix.sync.aligned.m8n8.x4.shared.b16 {%0,%1,%2,%3}, [%4];"
    : "=r"(r[0]), "=r"(r[1]), "=r"(r[2]), "=r"(r[3]) : "r"(a));
}
DEVFN void ldsm4t(uint32_t (&r)[4], uint32_t a) {
  asm volatile("ldmatrix.sync.aligned.m8n8.x4.trans.shared.b16 {%0,%1,%2,%3}, [%4];"
    : "=r"(r[0]), "=r"(r[1]), "=r"(r[2]), "=r"(r[3]) : "r"(a));
}
DEVFN void mma16816(float (&d)[4], const uint32_t (&a)[4], uint32_t b0, uint32_t b1) {
  asm volatile("mma.sync.aligned.m16n8k16.row.col.f32.bf16.bf16.f32 "
    "{%0,%1,%2,%3},{%4,%5,%6,%7},{%8,%9},{%0,%1,%2,%3};"
    : "+f"(d[0]), "+f"(d[1]), "+f"(d[2]), "+f"(d[3])
    : "r"(a[0]), "r"(a[1]), "r"(a[2]), "r"(a[3]), "r"(b0), "r"(b1));
}
DEVFN void bsplit(float v, __nv_bfloat16& h, __nv_bfloat16& l) {
  h = __float2bfloat16_rn(v);
  l = __float2bfloat16_rn(v - __bfloat162float(h));
}

// single shared dynamic-smem declaration for all kernels
extern __shared__ char dyn_smem[];

// ============= K0: fp32 -> (hi, lo) bf16 split, with row zero-padding ======
__global__ void __launch_bounds__(256) k_cvt(
    const float* __restrict__ src, unsigned short* __restrict__ hi,
    unsigned short* __restrict__ lo, int srcRows, int K, long tot)
{
  long i = ((long)blockIdx.x * 256 + threadIdx.x) * 4;
  if (i >= tot) return;
  long row = i / K;
  float4 v = make_float4(0.f, 0.f, 0.f, 0.f);
  if (row < srcRows) v = *(const float4*)(src + i);
  __nv_bfloat16 h0, h1, h2, h3, l0, l1, l2, l3;
  bsplit(v.x, h0, l0); bsplit(v.y, h1, l1);
  bsplit(v.z, h2, l2); bsplit(v.w, h3, l3);
  ushort4 hv, lv;
  hv.x = *(unsigned short*)&h0; hv.y = *(unsigned short*)&h1;
  hv.z = *(unsigned short*)&h2; hv.w = *(unsigned short*)&h3;
  lv.x = *(unsigned short*)&l0; lv.y = *(unsigned short*)&l1;
  lv.z = *(unsigned short*)&l2; lv.w = *(unsigned short*)&l3;
  *(ushort4*)(hi + i) = hv;
  *(ushort4*)(lo + i) = lv;
}

// ============= split-bf16 mma.sync GEMM: C[M,N] = A[M,K] * B[N,K]^T ========
constexpr int ROWB  = 80;
constexpr int TILEB = 128 * ROWB;
constexpr int BUFB  = 4 * TILEB;
constexpr int SMEM_GEMM = 2 * BUFB;       // 81920

__global__ void __launch_bounds__(256, 2) gemm_mma(
    const __nv_bfloat16* __restrict__ Ah, const __nv_bfloat16* __restrict__ Al,
    const __nv_bfloat16* __restrict__ Bh, const __nv_bfloat16* __restrict__ Bl,
    float* __restrict__ C, int M, int N, int K)
{
  char* smem = dyn_smem;
  const uint32_t sb0 = smem_to_u32(smem);
  const int tid = threadIdx.x;
  const int lane = tid & 31, wid = tid >> 5;
  const int bm = blockIdx.y * 128, bn = blockIdx.x * 128;
  const int wm = (wid >> 1) * 32, wn = (wid & 1) * 64;

  float acc[2][8][4];
  #pragma unroll
  for (int i = 0; i < 2; ++i)
    #pragma unroll
    for (int j = 0; j < 8; ++j)
      #pragma unroll
      for (int q = 0; q < 4; ++q) acc[i][j][q] = 0.0f;

  auto load_tile = [&](int kt, int buf) {
    const uint32_t sb = sb0 + buf * BUFB;
    const long kb = (long)kt * 32;
    #pragma unroll
    for (int i = 0; i < 2; ++i) {
      int o = tid + 256 * i;
      int row = o >> 2, seg = o & 3;
      uint32_t soff = row * ROWB + seg * 16;
      long ga = (long)(bm + row) * K + kb + seg * 8;
      long gb = (long)(bn + row) * K + kb + seg * 8;
      cp16(sb + soff,             Ah + ga);
      cp16(sb + TILEB + soff,     Al + ga);
      cp16(sb + 2*TILEB + soff,   Bh + gb);
      cp16(sb + 3*TILEB + soff,   Bl + gb);
    }
    asm volatile("cp.async.commit_group;" ::: "memory");
  };

  load_tile(0, 0);
  const int KT = K >> 5;
  for (int kt = 0; kt < KT; ++kt) {
    const int buf = kt & 1;
    if (kt + 1 < KT) {
      load_tile(kt + 1, buf ^ 1);
      asm volatile("cp.async.wait_group 1;" ::: "memory");
    } else {
      asm volatile("cp.async.wait_group 0;" ::: "memory");
    }
    __syncthreads();
    const uint32_t sb = sb0 + buf * BUFB;
    #pragma unroll
    for (int h = 0; h < 2; ++h) {
      uint32_t ah[2][4], al[2][4];
      #pragma unroll
      for (int mi = 0; mi < 2; ++mi) {
        uint32_t ad = sb + (uint32_t)(wm + mi*16 + (lane & 15)) * ROWB
                         + h*32 + (lane >> 4) * 16;
        ldsm4(ah[mi], ad);
        ldsm4(al[mi], ad + TILEB);
      }
      #pragma unroll
      for (int nj2 = 0; nj2 < 4; ++nj2) {
        uint32_t bd = sb + 2*TILEB
          + (uint32_t)(wn + nj2*16 + (lane & 7) + ((lane >> 4) << 3)) * ROWB
          + h*32 + ((lane >> 3) & 1) * 16;
        uint32_t bh4[4], bl4[4];
        ldsm4(bh4, bd);
        ldsm4(bl4, bd + TILEB);
        #pragma unroll
        for (int mi = 0; mi < 2; ++mi) {
          #pragma unroll
          for (int s = 0; s < 2; ++s) {
            int nj = nj2 * 2 + s;
            mma16816(acc[mi][nj], ah[mi], bh4[2*s], bh4[2*s+1]);
            mma16816(acc[mi][nj], ah[mi], bl4[2*s], bl4[2*s+1]);
            mma16816(acc[mi][nj], al[mi], bh4[2*s], bh4[2*s+1]);
          }
        }
      }
    }
    __syncthreads();
  }

  #pragma unroll
  for (int mi = 0; mi < 2; ++mi) {
    int row = bm + wm + mi*16 + (lane >> 2);
    #pragma unroll
    for (int nj = 0; nj < 8; ++nj) {
      int col = bn + wn + nj*8 + (lane & 3)*2;
      if (col < N) {
        *(float2*)(C + (long)row * N + col) =
            make_float2(acc[mi][nj][0], acc[mi][nj][1]);
        *(float2*)(C + (long)(row + 8) * N + col) =
            make_float2(acc[mi][nj][2], acc[mi][nj][3]);
      }
    }
  }
}

// ============= K2: conv1d + SiLU + softplus(dt) ===========================
__global__ void __launch_bounds__(256) k_conv(
    const float* __restrict__ conv_w, const float* __restrict__ conv_b,
    const float* __restrict__ dt_bias)
{
  const int row = blockIdx.x;
  const int b = row / cL, l = row % cL;
  const int tid = threadIdx.x;
  const size_t base0 = (size_t)row * cDP + cDS;
  const size_t obase = (size_t)row * cCD;
  #pragma unroll 1
  for (int q = 0; q < cCD / 256; ++q) {
    int c = tid + q * 256;
    float w0 = conv_w[c*3 + 0], w1 = conv_w[c*3 + 1], w2 = conv_w[c*3 + 2];
    float s = conv_b[c];
    if (l >= 2) s += g_zx[base0 - 2*(size_t)cDP + c] * w0;
    if (l >= 1) s += g_zx[base0 -   (size_t)cDP + c] * w1;
    s += g_zx[base0 + c] * w2;
    s = s * fsig(s);
    g_xbc[obase + c] = s;
  }
  if (tid < cNH) {
    float v = g_zx[(size_t)row * cDP + (cDP - cNH) + tid] + dt_bias[tid];
    float sp = (v > 15.0f) ? v : log1pf(expf(v));
    g_dt[((size_t)b * cNH + tid) * cL + l] = sp;
  }
}

// ============= K3: per-chunk inclusive cumsum of dt*A =====================
__global__ void __launch_bounds__(128) k_scan(const float* __restrict__ A_log)
{
  const int h = blockIdx.x, c = blockIdx.y, b = blockIdx.z;
  const int l = threadIdx.x;
  const float ah = -expf(A_log[h]);
  const size_t base = ((size_t)b * cNH + h) * cL + c * cCK;
  __shared__ float s[128];
  s[l] = g_dt[base + l] * ah;
  __syncthreads();
  #pragma unroll
  for (int off = 1; off < 128; off <<= 1) {
    float t = (l >= off) ? s[l - off] : 0.0f;
    __syncthreads();
    s[l] += t;
    __syncthreads();
  }
  g_ac[base + l] = s[l];
  if (l == 127) g_T[((size_t)b * cNH + h) * cNC + c] = s[127];
}

// ============= K4: chunk states ===========================================
__global__ void __launch_bounds__(256) k_states()
{
  const int h = blockIdx.x, c = blockIdx.y, b = blockIdx.z;
  const int tid = threadIdx.x;
  __shared__ float Bt[32][132];
  __shared__ float Xt[32][68];
  __shared__ float acs[128];
  __shared__ float Tsh;
  const size_t acb = ((size_t)b * cNH + h) * cL + c * cCK;
  if (tid < 128) acs[tid] = g_ac[acb + tid];
  if (tid == 0)  Tsh = g_T[((size_t)b * cNH + h) * cNC + c];
  __syncthreads();
  const float T = Tsh;
  const int px = tid & 15, ny = tid >> 4;
  const int p0 = px * 4, n0 = ny * 8;
  float acc[8][4] = {};
  const size_t rowbase = ((size_t)(b * cL + c * cCK)) * cCD;
  for (int lt = 0; lt < 4; ++lt) {
    #pragma unroll
    for (int q = 0; q < 4; ++q) {
      int i = tid + q * 256;
      int lr = i >> 5, nq = i & 31;
      int gl = lt * 32 + lr;
      float4 v = *(const float4*)(&g_xbc[rowbase + (size_t)gl * cCD + cDS + nq * 4]);
      *(float4*)&Bt[lr][nq * 4] = v;
    }
    #pragma unroll
    for (int q = 0; q < 2; ++q) {
      int i = tid + q * 256;
      int lr = i >> 4, pq = i & 15;
      int gl = lt * 32 + lr;
      float dtv = g_dt[acb + gl];
      float dec = fexp(T - acs[gl]);
      float sc = dtv * dec;
      float4 x = *(const float4*)(&g_xbc[rowbase + (size_t)gl * cCD + h * cHD + pq * 4]);
      x.x *= sc; x.y *= sc; x.z *= sc; x.w *= sc;
      *(float4*)&Xt[lr][pq * 4] = x;
    }
    __syncthreads();
    #pragma unroll
    for (int l = 0; l < 32; ++l) {
      float4 a0 = *(const float4*)&Bt[l][n0];
      float4 a1 = *(const float4*)&Bt[l][n0 + 4];
      float4 bv = *(const float4*)&Xt[l][p0];
      float a[8] = {a0.x, a0.y, a0.z, a0.w, a1.x, a1.y, a1.z, a1.w};
      #pragma unroll
      for (int i = 0; i < 8; ++i) {
        acc[i][0] += a[i] * bv.x; acc[i][1] += a[i] * bv.y;
        acc[i][2] += a[i] * bv.z; acc[i][3] += a[i] * bv.w;
      }
    }
    __syncthreads();
  }
  const size_t ob = (((size_t)b * cNC + c) * cNH + h) * (cST * cHD);
  #pragma unroll
  for (int i = 0; i < 8; ++i) {
    float4 v = make_float4(acc[i][0], acc[i][1], acc[i][2], acc[i][3]);
    *(float4*)&g_cs[ob + (size_t)(n0 + i) * cHD + p0] = v;
  }
}

// ============= K5: inter-chunk carry scan =================================
__global__ void __launch_bounds__(256) k_carry()
{
  const int bh = blockIdx.x;
  const int b = bh >> 6, h = bh & 63;
  const int tid = threadIdx.x;
  float carry[32];
  #pragma unroll
  for (int j = 0; j < 32; ++j) carry[j] = 0.0f;
  for (int c = 0; c < cNC; ++c) {
    if (c > 0) {
      float eT = fexp(g_T[(size_t)bh * cNC + (c - 1)]);
      const size_t inb = (((size_t)b * cNC + (c - 1)) * cNH + h) * (cST * cHD);
      #pragma unroll
      for (int j = 0; j < 32; ++j)
        carry[j] = carry[j] * eT + g_cs[inb + tid + j * 256];
    }
    const size_t ob = (((size_t)b * cNC + c) * cNH + h) * (cST * cHD);
    #pragma unroll
    for (int j = 0; j < 32; ++j)
      g_pv[ob + tid + j * 256] = carry[j];
  }
}

// ============= K5.5: unmasked G = C * B^T per (b,c) =======================
__global__ void __launch_bounds__(256) k_gmat()
{
  float* smf = (float*)dyn_smem;
  float* Ct = smf;                 // [n][l] stride 132
  float* Bt = smf + 128 * 132;
  const int c = blockIdx.x, b = blockIdx.y;
  const int tid = threadIdx.x;
  const size_t rowbase = ((size_t)(b * cL + c * cCK)) * cCD;
  #pragma unroll 1
  for (int q = 0; q < 16; ++q) {
    int i = tid + q * 256;
    int l = i >> 5, nq = i & 31;
    const float* src = &g_xbc[rowbase + (size_t)l * cCD];
    float4 cv = *(const float4*)(src + cDS + cST + nq * 4);
    float4 bv = *(const float4*)(src + cDS + nq * 4);
    int n = nq * 4;
    Ct[(n+0)*132 + l] = cv.x; Ct[(n+1)*132 + l] = cv.y;
    Ct[(n+2)*132 + l] = cv.z; Ct[(n+3)*132 + l] = cv.w;
    Bt[(n+0)*132 + l] = bv.x; Bt[(n+1)*132 + l] = bv.y;
    Bt[(n+2)*132 + l] = bv.z; Bt[(n+3)*132 + l] = bv.w;
  }
  __syncthreads();
  const int ty = tid >> 4, tx = tid & 15;
  const int l0 = ty * 8, s0 = tx * 8;
  float accG[8][8] = {};
  for (int n = 0; n < cST; ++n) {
    float4 a0 = *(const float4*)&Ct[n*132 + l0];
    float4 a1 = *(const float4*)&Ct[n*132 + l0 + 4];
    float4 b0 = *(const float4*)&Bt[n*132 + s0];
    float4 b1 = *(const float4*)&Bt[n*132 + s0 + 4];
    float a[8]  = {a0.x, a0.y, a0.z, a0.w, a1.x, a1.y, a1.z, a1.w};
    float bb[8] = {b0.x, b0.y, b0.z, b0.w, b1.x, b1.y, b1.z, b1.w};
    #pragma unroll
    for (int i = 0; i < 8; ++i)
      #pragma unroll
      for (int j = 0; j < 8; ++j) accG[i][j] += a[i] * bb[j];
  }
  const size_t gb = ((size_t)(b * cNC + c)) * (cCK * cCK);
  #pragma unroll
  for (int i = 0; i < 8; ++i) {
    #pragma unroll
    for (int j = 0; j < 4; ++j) {
      *(float2*)&g_gm[gb + (size_t)(l0 + i) * cCK + s0 + 2*j] =
          make_float2(accG[i][2*j], accG[i][2*j+1]);
    }
  }
}

// ============= K6: SSD Y kernel (mma.sync, 2 passes) ======================
constexpr int Y_AS = 136;                 // A row stride (elems) -> 272B
constexpr int Y_BS = 72;                  // B row stride (elems) -> 144B
constexpr int Y_AH = 0;
constexpr int Y_AL = Y_AH + 128 * Y_AS * 2;   // 34816
constexpr int Y_BH = Y_AL + 128 * Y_AS * 2;   // 69632
constexpr int Y_BL = Y_BH + 128 * Y_BS * 2;   // 88064
constexpr int Y_ACS = Y_BL + 128 * Y_BS * 2;  // 106496
constexpr int Y_DTS = Y_ACS + 512;            // 107008
constexpr int Y_SMEM = Y_DTS + 512;           // 107520

__global__ void __launch_bounds__(256, 2) k_ssd_y(const float* __restrict__ Dv)
{
  char* sm = dyn_smem;
  __nv_bfloat16* Ah = (__nv_bfloat16*)(sm + Y_AH);
  __nv_bfloat16* Al = (__nv_bfloat16*)(sm + Y_AL);
  __nv_bfloat16* Bh = (__nv_bfloat16*)(sm + Y_BH);
  __nv_bfloat16* Bl = (__nv_bfloat16*)(sm + Y_BL);
  float* acs = (float*)(sm + Y_ACS);
  float* dts = (float*)(sm + Y_DTS);
  const uint32_t sb = smem_to_u32(sm);
  const int h = blockIdx.x, c = blockIdx.y, b = blockIdx.z;
  const int tid = threadIdx.x, lane = tid & 31, wid = tid >> 5;
  const size_t rowbase = ((size_t)(b * cL + c * cCK)) * cCD;
  const size_t acb = ((size_t)b * cNH + h) * cL + c * cCK;
  if (tid < 128) { acs[tid] = g_ac[acb + tid]; dts[tid] = g_dt[acb + tid]; }
  __syncthreads();

  // ---- stage Gm (masked, decayed, split) into A region ----
  const size_t gb = ((size_t)(b * cNC + c)) * (cCK * cCK);
  #pragma unroll 1
  for (int q = 0; q < 16; ++q) {
    int i = (tid + q * 256) * 4;
    int l = i >> 7, s = i & 127;
    float4 g = *(const float4*)&g_gm[gb + i];
    float al = acs[l];
    float gv[4] = {g.x, g.y, g.z, g.w};
    #pragma unroll
    for (int j = 0; j < 4; ++j) {
      int ss = s + j;
      float m = (ss <= l) ? fexp(al - acs[ss]) : 0.0f;
      __nv_bfloat16 hh, ll;
      bsplit(gv[j] * m, hh, ll);
      Ah[l * Y_AS + ss] = hh; Al[l * Y_AS + ss] = ll;
    }
  }
  // ---- stage X' = x * dt into B region (natural [s][p]) ----
  #pragma unroll 1
  for (int q = 0; q < 8; ++q) {
    int i = (tid + q * 256) * 4;
    int s = i >> 6, p = i & 63;
    float4 x = *(const float4*)&g_xbc[rowbase + (size_t)s * cCD + h * cHD + p];
    float dv = dts[s];
    float xv[4] = {x.x * dv, x.y * dv, x.z * dv, x.w * dv};
    #pragma unroll
    for (int j = 0; j < 4; ++j) {
      __nv_bfloat16 hh, ll;
      bsplit(xv[j], hh, ll);
      Bh[s * Y_BS + p + j] = hh; Bl[s * Y_BS + p + j] = ll;
    }
  }
  __syncthreads();

  const int wm = (wid >> 1) * 32, wn = (wid & 1) * 32;
  float acc[2][4][4];
  #pragma unroll
  for (int mi = 0; mi < 2; ++mi)
    #pragma unroll
    for (int nj = 0; nj < 4; ++nj)
      #pragma unroll
      for (int q = 0; q < 4; ++q) acc[mi][nj][q] = 0.0f;

  auto mma_pass = [&]() {
    #pragma unroll
    for (int kk = 0; kk < 8; ++kk) {
      uint32_t ah4[2][4], al4[2][4];
      #pragma unroll
      for (int mi = 0; mi < 2; ++mi) {
        uint32_t ad = sb + Y_AH
          + (uint32_t)(wm + mi*16 + (lane & 15)) * (Y_AS * 2)
          + kk*32 + (lane >> 4) * 16;
        ldsm4(ah4[mi], ad);
        ldsm4(al4[mi], ad + (Y_AL - Y_AH));
      }
      #pragma unroll
      for (int nj2 = 0; nj2 < 2; ++nj2) {
        uint32_t bd = sb + Y_BH
          + (uint32_t)(kk*16 + (lane & 15)) * (Y_BS * 2)
          + (uint32_t)(wn + nj2*16 + ((lane >> 4) << 3)) * 2;
        uint32_t bh4[4], bl4[4];
        ldsm4t(bh4, bd);
        ldsm4t(bl4, bd + (Y_BL - Y_BH));
        #pragma unroll
        for (int mi = 0; mi < 2; ++mi) {
          #pragma unroll
          for (int s2 = 0; s2 < 2; ++s2) {
            int nj = nj2 * 2 + s2;
            mma16816(acc[mi][nj], ah4[mi], bh4[2*s2], bh4[2*s2+1]);
            mma16816(acc[mi][nj], ah4[mi], bl4[2*s2], bl4[2*s2+1]);
            mma16816(acc[mi][nj], al4[mi], bh4[2*s2], bh4[2*s2+1]);
          }
        }
      }
    }
  };
  mma_pass();          // Y += Gm @ X'
  __syncthreads();

  // ---- stage Ce = C * exp(ac_l) into A region ----
  #pragma unroll 1
  for (int q = 0; q < 16; ++q) {
    int i = (tid + q * 256) * 4;
    int l = i >> 7, n = i & 127;
    float4 cv = *(const float4*)&g_xbc[rowbase + (size_t)l * cCD + cDS + cST + n];
    float e = fexp(acs[l]);
    float cvv[4] = {cv.x * e, cv.y * e, cv.z * e, cv.w * e};
    #pragma unroll
    for (int j = 0; j < 4; ++j) {
      __nv_bfloat16 hh, ll;
      bsplit(cvv[j], hh, ll);
      Ah[l * Y_AS + n + j] = hh; Al[l * Y_AS + n + j] = ll;
    }
  }
  // ---- stage P (prev states, natural [n][p]) into B region ----
  {
    const size_t pb = (((size_t)b * cNC + c) * cNH + h) * (cST * cHD);
    #pragma unroll 1
    for (int q = 0; q < 8; ++q) {
      int i = (tid + q * 256) * 4;
      int n = i >> 6, p = i & 63;
      float4 pv = *(const float4*)&g_pv[pb + i];
      float pvv[4] = {pv.x, pv.y, pv.z, pv.w};
      #pragma unroll
      for (int j = 0; j < 4; ++j) {
        __nv_bfloat16 hh, ll;
        bsplit(pvv[j], hh, ll);
        Bh[n * Y_BS + p + j] = hh; Bl[n * Y_BS + p + j] = ll;
      }
    }
  }
  __syncthreads();
  mma_pass();          // Y += Ce @ P

  // ---- epilogue: Y + D*x -> g_y ----
  const float Dh = Dv[h];
  #pragma unroll
  for (int mi = 0; mi < 2; ++mi) {
    int row = wm + mi*16 + (lane >> 2);
    #pragma unroll
    for (int nj = 0; nj < 4; ++nj) {
      int col = wn + nj*8 + (lane & 3)*2;
      float2 x0 = *(const float2*)&g_xbc[rowbase + (size_t)row * cCD + h * cHD + col];
      float2 x1 = *(const float2*)&g_xbc[rowbase + (size_t)(row+8) * cCD + h * cHD + col];
      size_t y0 = ((size_t)(b * cL + c * cCK + row)) * cDS + h * cHD + col;
      size_t y1 = ((size_t)(b * cL + c * cCK + row + 8)) * cDS + h * cHD + col;
      *(float2*)&g_y[y0] = make_float2(acc[mi][nj][0] + Dh * x0.x,
                                       acc[mi][nj][1] + Dh * x0.y);
      *(float2*)&g_y[y1] = make_float2(acc[mi][nj][2] + Dh * x1.x,
                                       acc[mi][nj][3] + Dh * x1.y);
    }
  }
}

// ============= K7: gate (silu(z)) + RMSNorm + bf16 split (fused) ==========
__global__ void __launch_bounds__(256) k_gate_norm(const float* __restrict__ norm_w)
{
  const int row = blockIdx.x;
  const int tid = threadIdx.x;
  const size_t zb = (size_t)row * cDP;
  const size_t yb = (size_t)row * cDS;
  float v[16];
  float ss = 0.0f;
  #pragma unroll
  for (int q = 0; q < 16; ++q) {
    int i = tid + q * 256;
    float z = g_zx[zb + i];
    float y = g_y[yb + i];
    float t = y * z * fsig(z);
    v[q] = t;
    ss += t * t;
  }
  #pragma unroll
  for (int o = 16; o > 0; o >>= 1) ss += __shfl_xor_sync(0xffffffffu, ss, o);
  __shared__ float red[8];
  if ((tid & 31) == 0) red[tid >> 5] = ss;
  __syncthreads();
  float tot = 0.0f;
  #pragma unroll
  for (int j = 0; j < 8; ++j) tot += red[j];
  const float scale = rsqrtf(tot / (float)cDS + cEPS);
  #pragma unroll
  for (int q = 0; q < 16; ++q) {
    int i = tid + q * 256;
    float t = v[q] * scale * norm_w[i];
    __nv_bfloat16 hh, ll;
    bsplit(t, hh, ll);
    g_ah[yb + i] = *(unsigned short*)&hh;
    g_al[yb + i] = *(unsigned short*)&ll;
  }
}

// ============= K9: out + reverse(out) =====================================
__global__ void __launch_bounds__(256) k_revadd(float* __restrict__ out)
{
  const int idx4 = blockIdx.x * 256 + threadIdx.x;
  const int tot4 = cB * cL * cDM / 4;
  if (idx4 >= tot4) return;
  const int i = idx4 * 4;
  const int b = i / (cL * cDM);
  const int r = i - b * (cL * cDM);
  const int l = r / cDM;
  const int d = r - l * cDM;
  const size_t rev = ((size_t)b * cL + (cL - 1 - l)) * cDM + d;
  float4 a = *(const float4*)(&g_o[i]);
  float4 c = *(const float4*)(&g_o[rev]);
  a.x += c.x; a.y += c.y; a.z += c.z; a.w += c.w;
  *(float4*)(out + i) = a;
}

// ==========================================================================
extern "C" void kernel_launch(void* const* d_in, const int* in_sizes, int n_in,
                              void* d_out, int out_size) {
  const float* u       = (const float*)d_in[0];
  const float* W_in    = (const float*)d_in[1];
  const float* conv_w  = (const float*)d_in[2];
  const float* conv_b  = (const float*)d_in[3];
  const float* dt_bias = (const float*)d_in[4];
  const float* A_log   = (const float*)d_in[5];
  const float* Dv      = (const float*)d_in[6];
  const float* norm_w  = (const float*)d_in[7];
  const float* W_out   = (const float*)d_in[8];
  float* out = (float*)d_out;

  float* zx; cudaGetSymbolAddress((void**)&zx, g_zx);
  float* ob; cudaGetSymbolAddress((void**)&ob, g_o);
  unsigned short *ah, *al, *bh, *bl;
  cudaGetSymbolAddress((void**)&ah, g_ah);
  cudaGetSymbolAddress((void**)&al, g_al);
  cudaGetSymbolAddress((void**)&bh, g_bh);
  cudaGetSymbolAddress((void**)&bl, g_bl);

  cudaFuncSetAttribute(gemm_mma, cudaFuncAttributeMaxDynamicSharedMemorySize,
                       SMEM_GEMM);
  cudaFuncSetAttribute(k_gmat, cudaFuncAttributeMaxDynamicSharedMemorySize,
                       2 * 128 * 132 * 4);
  cudaFuncSetAttribute(k_ssd_y, cudaFuncAttributeMaxDynamicSharedMemorySize,
                       Y_SMEM);

  const int M = cB * cL;   // 4096

  // --- GEMM1 prep ---
  {
    long totA = (long)M * cDM;
    k_cvt<<<(unsigned)((totA/4 + 255)/256), 256>>>(u, ah, al, M, cDM, totA);
    long totB = (long)cNPAD1 * cDM;
    k_cvt<<<(unsigned)((totB/4 + 255)/256), 256>>>(W_in, bh, bl, cDP, cDM, totB);
  }
  // --- GEMM1: zx[4096, 8512] ---
  {
    dim3 grid(cNPAD1 / 128, M / 128);
    gemm_mma<<<grid, 256, SMEM_GEMM>>>(
        (const __nv_bfloat16*)ah, (const __nv_bfloat16*)al,
        (const __nv_bfloat16*)bh, (const __nv_bfloat16*)bl, zx, M, cDP, cDM);
  }
  // --- conv + silu + dt ---
  k_conv<<<cB * cL, 256>>>(conv_w, conv_b, dt_bias);
  // --- per-chunk cumsum ---
  { dim3 grid(cNH, cNC, cB); k_scan<<<grid, 128>>>(A_log); }
  // --- chunk states ---
  { dim3 grid(cNH, cNC, cB); k_states<<<grid, 256>>>(); }
  // --- carry scan ---
  k_carry<<<cB * cNH, 256>>>();
  // --- unmasked G ---
  { dim3 grid(cNC, cB); k_gmat<<<grid, 256, 2 * 128 * 132 * 4>>>(); }
  // --- Y (mma) ---
  { dim3 grid(cNH, cNC, cB); k_ssd_y<<<grid, 256, Y_SMEM>>>(Dv); }
  // --- gate + rmsnorm + split (fused) ---
  k_gate_norm<<<cB * cL, 256>>>(norm_w);
  // --- GEMM2 prep: W_out only (y split fused above) ---
  {
    long totB = (long)cDM * cDS;
    k_cvt<<<(unsigned)((totB/4 + 255)/256), 256>>>(W_out, bh, bl, cDM, cDS, totB);
  }
  // --- GEMM2: o[4096, 2048] ---
  {
    dim3 grid(cDM / 128, M / 128);
    gemm_mma<<<grid, 256, SMEM_GEMM>>>(
        (const __nv_bfloat16*)ah, (const __nv_bfloat16*)al,
        (const __nv_bfloat16*)bh, (const __nv_bfloat16*)bl, ob, M, cDM, cDS);
  }
  // --- out + reverse(out) ---
  k_revadd<<<(cB * cL * cDM / 4 + 255) / 256, 256>>>(out);
}

// round 9
// speedup vs baseline: 2.5514x; 1.0060x over previous
#include <cuda_runtime.h>
#include <cuda_bf16.h>
#include <cstdint>

#define DEVFN static __device__ __forceinline__

constexpr int cB  = 2;
constexpr int cL  = 2048;
constexpr int cDM = 2048;            // D_MODEL
constexpr int cDS = 4096;            // D_SSM
constexpr int cST = 128;             // D_STATE
constexpr int cNH = 64;              // NHEADS
constexpr int cHD = 64;              // HEADDIM
constexpr int cCK = 128;             // CHUNK
constexpr int cNC = cL / cCK;        // 16
constexpr int cDP = 2*cDS + 2*cST + cNH;   // 8512
constexpr int cCD = cDS + 2*cST;           // 4352
constexpr float cEPS = 1e-5f;

constexpr int cNPAD1 = 8704;         // padded N for GEMM1 (68 * 128)

// ---------------- scratch (static device globals; no allocation) ----------
__device__ float g_zx [(size_t)cB*cL*cDP];           // in-proj output
__device__ float g_xbc[(size_t)cB*cL*cCD];           // conv+silu output
__device__ float g_dt [(size_t)cB*cNH*cL];           // softplus dt, [b][h][l]
__device__ float g_ac [(size_t)cB*cNH*cL];           // per-chunk cumsum, [b][h][l]
__device__ float g_T  [(size_t)cB*cNH*cNC];          // chunk totals
__device__ float g_cs [(size_t)cB*cNC*cNH*cST*cHD];  // per-chunk states
__device__ float g_pv [(size_t)cB*cNC*cNH*cST*cHD];  // carried states
__device__ float g_gm [(size_t)cB*cNC*cCK*cCK];      // unmasked G per (b,c)
__device__ float g_y  [(size_t)cB*cL*cDS];           // y buffer
__device__ float g_o  [(size_t)cB*cL*cDM];           // out-proj output
// split-bf16 operand buffers (hi/lo)
__device__ unsigned short g_ah [(size_t)4096*4096];
__device__ unsigned short g_al [(size_t)4096*4096];
__device__ unsigned short g_bh [(size_t)cNPAD1*2048];
__device__ unsigned short g_bl [(size_t)cNPAD1*2048];
__device__ unsigned short g_b2h[(size_t)cDM*cDS];    // W_out split (hoisted)
__device__ unsigned short g_b2l[(size_t)cDM*cDS];

// ---------------- math helpers --------------------------------------------
DEVFN float fexp(float x) {          // exp(x), FFMA-only
  float t = x * 1.44269504088896340736f;
  t = fminf(fmaxf(t, -126.0f), 126.0f);
  float fi = rintf(t);
  float f  = t - fi;
  float p = 1.5403530393381610e-4f;
  p = fmaf(p, f, 1.3333558146428443e-3f);
  p = fmaf(p, f, 9.6181291076284772e-3f);
  p = fmaf(p, f, 5.5504108664821580e-2f);
  p = fmaf(p, f, 2.4022650695910071e-1f);
  p = fmaf(p, f, 6.9314718055994531e-1f);
  p = fmaf(p, f, 1.0f);
  int i = (int)fi;
  return __int_as_float((i + 127) << 23) * p;
}
DEVFN float fsig(float x) { return 1.0f / (1.0f + fexp(-x)); }

DEVFN uint32_t smem_to_u32(const void* p) {
  uint32_t a;
  asm("{ .reg .u64 t; cvta.to.shared.u64 t, %1; cvt.u32.u64 %0, t; }"
      : "=r"(a) : "l"(p));
  return a;
}
DEVFN void cp16(uint32_t saddr, const void* gptr) {
  asm volatile("cp.async.cg.shared.global [%0], [%1], 16;"
               :: "r"(saddr), "l"(gptr) : "memory");
}
DEVFN void ldsm4(uint32_t (&r)[4], uint32_t a) {
  asm volatile("ldmatrix.sync.aligned.m8n8.x4.shared.b16 {%0,%1,%2,%3}, [%4];"
    : "=r"(r[0]), "=r"(r[1]), "=r"(r[2]), "=r"(r[3]) : "r"(a));
}
DEVFN void ldsm4t(uint32_t (&r)[4], uint32_t a) {
  asm volatile("ldmatrix.sync.aligned.m8n8.x4.trans.shared.b16 {%0,%1,%2,%3}, [%4];"
    : "=r"(r[0]), "=r"(r[1]), "=r"(r[2]), "=r"(r[3]) : "r"(a));
}
DEVFN void mma16816(float (&d)[4], const uint32_t (&a)[4], uint32_t b0, uint32_t b1) {
  asm volatile("mma.sync.aligned.m16n8k16.row.col.f32.bf16.bf16.f32 "
    "{%0,%1,%2,%3},{%4,%5,%6,%7},{%8,%9},{%0,%1,%2,%3};"
    : "+f"(d[0]), "+f"(d[1]), "+f"(d[2]), "+f"(d[3])
    : "r"(a[0]), "r"(a[1]), "r"(a[2]), "r"(a[3]), "r"(b0), "r"(b1));
}
DEVFN void bsplit(float v, __nv_bfloat16& h, __nv_bfloat16& l) {
  h = __float2bfloat16_rn(v);
  l = __float2bfloat16_rn(v - __bfloat162float(h));
}

// single shared dynamic-smem declaration for all kernels
extern __shared__ char dyn_smem[];

// ============= K0: fp32 -> (hi, lo) bf16 split, with row zero-padding ======
__global__ void __launch_bounds__(256) k_cvt(
    const float* __restrict__ src, unsigned short* __restrict__ hi,
    unsigned short* __restrict__ lo, int srcRows, int K, long tot)
{
  long i = ((long)blockIdx.x * 256 + threadIdx.x) * 4;
  if (i >= tot) return;
  long row = i / K;
  float4 v = make_float4(0.f, 0.f, 0.f, 0.f);
  if (row < srcRows) v = *(const float4*)(src + i);
  __nv_bfloat16 h0, h1, h2, h3, l0, l1, l2, l3;
  bsplit(v.x, h0, l0); bsplit(v.y, h1, l1);
  bsplit(v.z, h2, l2); bsplit(v.w, h3, l3);
  ushort4 hv, lv;
  hv.x = *(unsigned short*)&h0; hv.y = *(unsigned short*)&h1;
  hv.z = *(unsigned short*)&h2; hv.w = *(unsigned short*)&h3;
  lv.x = *(unsigned short*)&l0; lv.y = *(unsigned short*)&l1;
  lv.z = *(unsigned short*)&l2; lv.w = *(unsigned short*)&l3;
  *(ushort4*)(hi + i) = hv;
  *(ushort4*)(lo + i) = lv;
}

// ============= split-bf16 mma.sync GEMM: C[M,N] = A[M,K] * B[N,K]^T ========
constexpr int ROWB  = 80;
constexpr int TILEB = 128 * ROWB;
constexpr int BUFB  = 4 * TILEB;
constexpr int SMEM_GEMM = 2 * BUFB;       // 81920

__global__ void __launch_bounds__(256, 2) gemm_mma(
    const __nv_bfloat16* __restrict__ Ah, const __nv_bfloat16* __restrict__ Al,
    const __nv_bfloat16* __restrict__ Bh, const __nv_bfloat16* __restrict__ Bl,
    float* __restrict__ C, int M, int N, int K)
{
  char* smem = dyn_smem;
  const uint32_t sb0 = smem_to_u32(smem);
  const int tid = threadIdx.x;
  const int lane = tid & 31, wid = tid >> 5;
  const int bm = blockIdx.y * 128, bn = blockIdx.x * 128;
  const int wm = (wid >> 1) * 32, wn = (wid & 1) * 64;

  float acc[2][8][4];
  #pragma unroll
  for (int i = 0; i < 2; ++i)
    #pragma unroll
    for (int j = 0; j < 8; ++j)
      #pragma unroll
      for (int q = 0; q < 4; ++q) acc[i][j][q] = 0.0f;

  auto load_tile = [&](int kt, int buf) {
    const uint32_t sb = sb0 + buf * BUFB;
    const long kb = (long)kt * 32;
    #pragma unroll
    for (int i = 0; i < 2; ++i) {
      int o = tid + 256 * i;
      int row = o >> 2, seg = o & 3;
      uint32_t soff = row * ROWB + seg * 16;
      long ga = (long)(bm + row) * K + kb + seg * 8;
      long gb = (long)(bn + row) * K + kb + seg * 8;
      cp16(sb + soff,             Ah + ga);
      cp16(sb + TILEB + soff,     Al + ga);
      cp16(sb + 2*TILEB + soff,   Bh + gb);
      cp16(sb + 3*TILEB + soff,   Bl + gb);
    }
    asm volatile("cp.async.commit_group;" ::: "memory");
  };

  load_tile(0, 0);
  const int KT = K >> 5;
  for (int kt = 0; kt < KT; ++kt) {
    const int buf = kt & 1;
    if (kt + 1 < KT) {
      load_tile(kt + 1, buf ^ 1);
      asm volatile("cp.async.wait_group 1;" ::: "memory");
    } else {
      asm volatile("cp.async.wait_group 0;" ::: "memory");
    }
    __syncthreads();
    const uint32_t sb = sb0 + buf * BUFB;
    #pragma unroll
    for (int h = 0; h < 2; ++h) {
      uint32_t ah[2][4], al[2][4];
      #pragma unroll
      for (int mi = 0; mi < 2; ++mi) {
        uint32_t ad = sb + (uint32_t)(wm + mi*16 + (lane & 15)) * ROWB
                         + h*32 + (lane >> 4) * 16;
        ldsm4(ah[mi], ad);
        ldsm4(al[mi], ad + TILEB);
      }
      #pragma unroll
      for (int nj2 = 0; nj2 < 4; ++nj2) {
        uint32_t bd = sb + 2*TILEB
          + (uint32_t)(wn + nj2*16 + (lane & 7) + ((lane >> 4) << 3)) * ROWB
          + h*32 + ((lane >> 3) & 1) * 16;
        uint32_t bh4[4], bl4[4];
        ldsm4(bh4, bd);
        ldsm4(bl4, bd + TILEB);
        #pragma unroll
        for (int mi = 0; mi < 2; ++mi) {
          #pragma unroll
          for (int s = 0; s < 2; ++s) {
            int nj = nj2 * 2 + s;
            mma16816(acc[mi][nj], ah[mi], bh4[2*s], bh4[2*s+1]);
            mma16816(acc[mi][nj], ah[mi], bl4[2*s], bl4[2*s+1]);
            mma16816(acc[mi][nj], al[mi], bh4[2*s], bh4[2*s+1]);
          }
        }
      }
    }
    __syncthreads();
  }

  #pragma unroll
  for (int mi = 0; mi < 2; ++mi) {
    int row = bm + wm + mi*16 + (lane >> 2);
    #pragma unroll
    for (int nj = 0; nj < 8; ++nj) {
      int col = bn + wn + nj*8 + (lane & 3)*2;
      if (col < N) {
        *(float2*)(C + (long)row * N + col) =
            make_float2(acc[mi][nj][0], acc[mi][nj][1]);
        *(float2*)(C + (long)(row + 8) * N + col) =
            make_float2(acc[mi][nj][2], acc[mi][nj][3]);
      }
    }
  }
}

// ============= K2: conv1d + SiLU + softplus(dt), float4 ===================
__global__ void __launch_bounds__(256) k_conv(
    const float* __restrict__ conv_w, const float* __restrict__ conv_b,
    const float* __restrict__ dt_bias)
{
  const int row = blockIdx.x;
  const int b = row / cL, l = row % cL;
  const int tid = threadIdx.x;
  const float* z0 = &g_zx[(size_t)row * cDP + cDS];
  float* obp = &g_xbc[(size_t)row * cCD];
  const bool p1 = (l >= 1), p2 = (l >= 2);
  #pragma unroll 1
  for (int q = 0; q < 5; ++q) {
    int c4 = tid + q * 256;
    if (c4 >= cCD / 4) break;
    int c = c4 * 4;
    float4 wa = *(const float4*)(conv_w + c*3);
    float4 wb = *(const float4*)(conv_w + c*3 + 4);
    float4 wc = *(const float4*)(conv_w + c*3 + 8);
    float4 bs = *(const float4*)(conv_b + c);
    float4 x2 = p2 ? *(const float4*)(z0 - 2*(size_t)cDP + c) : make_float4(0,0,0,0);
    float4 x1 = p1 ? *(const float4*)(z0 -   (size_t)cDP + c) : make_float4(0,0,0,0);
    float4 x0 = *(const float4*)(z0 + c);
    float4 s;
    s.x = bs.x + x2.x*wa.x + x1.x*wa.y + x0.x*wa.z;
    s.y = bs.y + x2.y*wa.w + x1.y*wb.x + x0.y*wb.y;
    s.z = bs.z + x2.z*wb.z + x1.z*wb.w + x0.z*wc.x;
    s.w = bs.w + x2.w*wc.y + x1.w*wc.z + x0.w*wc.w;
    s.x *= fsig(s.x); s.y *= fsig(s.y); s.z *= fsig(s.z); s.w *= fsig(s.w);
    *(float4*)(obp + c) = s;
  }
  if (tid < cNH) {
    float v = g_zx[(size_t)row * cDP + (cDP - cNH) + tid] + dt_bias[tid];
    float sp = (v > 15.0f) ? v : log1pf(expf(v));
    g_dt[((size_t)b * cNH + tid) * cL + l] = sp;
  }
}

// ============= K3: per-chunk inclusive cumsum of dt*A =====================
__global__ void __launch_bounds__(128) k_scan(const float* __restrict__ A_log)
{
  const int h = blockIdx.x, c = blockIdx.y, b = blockIdx.z;
  const int l = threadIdx.x;
  const float ah = -expf(A_log[h]);
  const size_t base = ((size_t)b * cNH + h) * cL + c * cCK;
  __shared__ float s[128];
  s[l] = g_dt[base + l] * ah;
  __syncthreads();
  #pragma unroll
  for (int off = 1; off < 128; off <<= 1) {
    float t = (l >= off) ? s[l - off] : 0.0f;
    __syncthreads();
    s[l] += t;
    __syncthreads();
  }
  g_ac[base + l] = s[l];
  if (l == 127) g_T[((size_t)b * cNH + h) * cNC + c] = s[127];
}

// ============= K4: chunk states (mma.sync, split-bf16) ====================
// states[n][p] = sum_l Bmat[l][n] * (dt[l]*exp(T-ac[l])) * x[l][p]
// A operand = Bmat^T from natural [l][n] staging via ldsm.trans;
// B operand = X' from natural [l][p] staging via ldsm.trans.
constexpr int S_AS  = 136;
constexpr int S_BS  = 72;
constexpr int S_AHo = 0;
constexpr int S_ALo = 128 * S_AS * 2;          // 34816
constexpr int S_BHo = 2 * 128 * S_AS * 2;      // 69632
constexpr int S_BLo = S_BHo + 128 * S_BS * 2;  // 88064
constexpr int S_SCo = S_BLo + 128 * S_BS * 2;  // 106496
constexpr int S_SMEM = S_SCo + 512;            // 107008

__global__ void __launch_bounds__(256, 2) k_states()
{
  char* sm = dyn_smem;
  __nv_bfloat16* Ah = (__nv_bfloat16*)(sm + S_AHo);
  __nv_bfloat16* Al = (__nv_bfloat16*)(sm + S_ALo);
  __nv_bfloat16* Bh = (__nv_bfloat16*)(sm + S_BHo);
  __nv_bfloat16* Bl = (__nv_bfloat16*)(sm + S_BLo);
  float* sc = (float*)(sm + S_SCo);
  const uint32_t sb = smem_to_u32(sm);
  const int h = blockIdx.x, c = blockIdx.y, b = blockIdx.z;
  const int tid = threadIdx.x, lane = tid & 31, wid = tid >> 5;
  const size_t rowbase = ((size_t)(b * cL + c * cCK)) * cCD;
  const size_t acb = ((size_t)b * cNH + h) * cL + c * cCK;
  if (tid < 128) {
    float T = g_T[((size_t)b * cNH + h) * cNC + c];
    sc[tid] = g_dt[acb + tid] * fexp(T - g_ac[acb + tid]);
  }
  __syncthreads();
  // stage Bmat [l][n] (natural layout)
  #pragma unroll 1
  for (int q = 0; q < 16; ++q) {
    int i = (tid + q * 256) * 4;
    int l = i >> 7, n = i & 127;
    float4 v = *(const float4*)&g_xbc[rowbase + (size_t)l * cCD + cDS + n];
    float vv[4] = {v.x, v.y, v.z, v.w};
    #pragma unroll
    for (int j = 0; j < 4; ++j) {
      __nv_bfloat16 hh, ll;
      bsplit(vv[j], hh, ll);
      Ah[l * S_AS + n + j] = hh; Al[l * S_AS + n + j] = ll;
    }
  }
  // stage X' [l][p] = x * sc[l]
  #pragma unroll 1
  for (int q = 0; q < 8; ++q) {
    int i = (tid + q * 256) * 4;
    int l = i >> 6, p = i & 63;
    float4 x = *(const float4*)&g_xbc[rowbase + (size_t)l * cCD + h * cHD + p];
    float s = sc[l];
    float xv[4] = {x.x * s, x.y * s, x.z * s, x.w * s};
    #pragma unroll
    for (int j = 0; j < 4; ++j) {
      __nv_bfloat16 hh, ll;
      bsplit(xv[j], hh, ll);
      Bh[l * S_BS + p + j] = hh; Bl[l * S_BS + p + j] = ll;
    }
  }
  __syncthreads();

  const int wm = (wid >> 1) * 32, wn = (wid & 1) * 32;
  float acc[2][4][4];
  #pragma unroll
  for (int mi = 0; mi < 2; ++mi)
    #pragma unroll
    for (int nj = 0; nj < 4; ++nj)
      #pragma unroll
      for (int q = 0; q < 4; ++q) acc[mi][nj][q] = 0.0f;

  #pragma unroll
  for (int kk = 0; kk < 8; ++kk) {
    uint32_t ah4[2][4], al4[2][4];
    #pragma unroll
    for (int mi = 0; mi < 2; ++mi) {
      // A-frag (row-major m16k16) from [k][m] storage via ldsm.trans:
      // row = k0 + (lane&7) + ((lane>>4)<<3), col = m0 + (lane&8)
      uint32_t ad = sb + S_AHo
        + (uint32_t)(kk*16 + (lane & 7) + ((lane >> 4) << 3)) * (S_AS * 2)
        + (uint32_t)(wm + mi*16 + (lane & 8)) * 2;
      ldsm4t(ah4[mi], ad);
      ldsm4t(al4[mi], ad + (S_ALo - S_AHo));
    }
    #pragma unroll
    for (int nj2 = 0; nj2 < 2; ++nj2) {
      uint32_t bd = sb + S_BHo
        + (uint32_t)(kk*16 + (lane & 15)) * (S_BS * 2)
        + (uint32_t)(wn + nj2*16 + ((lane >> 4) << 3)) * 2;
      uint32_t bh4[4], bl4[4];
      ldsm4t(bh4, bd);
      ldsm4t(bl4, bd + (S_BLo - S_BHo));
      #pragma unroll
      for (int mi = 0; mi < 2; ++mi) {
        #pragma unroll
        for (int s2 = 0; s2 < 2; ++s2) {
          int nj = nj2 * 2 + s2;
          mma16816(acc[mi][nj], ah4[mi], bh4[2*s2], bh4[2*s2+1]);
          mma16816(acc[mi][nj], ah4[mi], bl4[2*s2], bl4[2*s2+1]);
          mma16816(acc[mi][nj], al4[mi], bh4[2*s2], bh4[2*s2+1]);
        }
      }
    }
  }

  const size_t ob = (((size_t)b * cNC + c) * cNH + h) * (cST * cHD);
  #pragma unroll
  for (int mi = 0; mi < 2; ++mi) {
    int row = wm + mi*16 + (lane >> 2);
    #pragma unroll
    for (int nj = 0; nj < 4; ++nj) {
      int col = wn + nj*8 + (lane & 3)*2;
      *(float2*)&g_cs[ob + (size_t)row * cHD + col] =
          make_float2(acc[mi][nj][0], acc[mi][nj][1]);
      *(float2*)&g_cs[ob + (size_t)(row + 8) * cHD + col] =
          make_float2(acc[mi][nj][2], acc[mi][nj][3]);
    }
  }
}

// ============= K5: inter-chunk carry scan =================================
__global__ void __launch_bounds__(256) k_carry()
{
  const int bh = blockIdx.x;
  const int b = bh >> 6, h = bh & 63;
  const int tid = threadIdx.x;
  float carry[32];
  #pragma unroll
  for (int j = 0; j < 32; ++j) carry[j] = 0.0f;
  for (int c = 0; c < cNC; ++c) {
    if (c > 0) {
      float eT = fexp(g_T[(size_t)bh * cNC + (c - 1)]);
      const size_t inb = (((size_t)b * cNC + (c - 1)) * cNH + h) * (cST * cHD);
      #pragma unroll
      for (int j = 0; j < 32; ++j)
        carry[j] = carry[j] * eT + g_cs[inb + tid + j * 256];
    }
    const size_t ob = (((size_t)b * cNC + c) * cNH + h) * (cST * cHD);
    #pragma unroll
    for (int j = 0; j < 32; ++j)
      g_pv[ob + tid + j * 256] = carry[j];
  }
}

// ============= K5.5: unmasked G = C * B^T per (b,c) =======================
__global__ void __launch_bounds__(256) k_gmat()
{
  float* smf = (float*)dyn_smem;
  float* Ct = smf;                 // [n][l] stride 132
  float* Bt = smf + 128 * 132;
  const int c = blockIdx.x, b = blockIdx.y;
  const int tid = threadIdx.x;
  const size_t rowbase = ((size_t)(b * cL + c * cCK)) * cCD;
  #pragma unroll 1
  for (int q = 0; q < 16; ++q) {
    int i = tid + q * 256;
    int l = i >> 5, nq = i & 31;
    const float* src = &g_xbc[rowbase + (size_t)l * cCD];
    float4 cv = *(const float4*)(src + cDS + cST + nq * 4);
    float4 bv = *(const float4*)(src + cDS + nq * 4);
    int n = nq * 4;
    Ct[(n+0)*132 + l] = cv.x; Ct[(n+1)*132 + l] = cv.y;
    Ct[(n+2)*132 + l] = cv.z; Ct[(n+3)*132 + l] = cv.w;
    Bt[(n+0)*132 + l] = bv.x; Bt[(n+1)*132 + l] = bv.y;
    Bt[(n+2)*132 + l] = bv.z; Bt[(n+3)*132 + l] = bv.w;
  }
  __syncthreads();
  const int ty = tid >> 4, tx = tid & 15;
  const int l0 = ty * 8, s0 = tx * 8;
  float accG[8][8] = {};
  for (int n = 0; n < cST; ++n) {
    float4 a0 = *(const float4*)&Ct[n*132 + l0];
    float4 a1 = *(const float4*)&Ct[n*132 + l0 + 4];
    float4 b0 = *(const float4*)&Bt[n*132 + s0];
    float4 b1 = *(const float4*)&Bt[n*132 + s0 + 4];
    float a[8]  = {a0.x, a0.y, a0.z, a0.w, a1.x, a1.y, a1.z, a1.w};
    float bb[8] = {b0.x, b0.y, b0.z, b0.w, b1.x, b1.y, b1.z, b1.w};
    #pragma unroll
    for (int i = 0; i < 8; ++i)
      #pragma unroll
      for (int j = 0; j < 8; ++j) accG[i][j] += a[i] * bb[j];
  }
  const size_t gb = ((size_t)(b * cNC + c)) * (cCK * cCK);
  #pragma unroll
  for (int i = 0; i < 8; ++i) {
    #pragma unroll
    for (int j = 0; j < 4; ++j) {
      *(float2*)&g_gm[gb + (size_t)(l0 + i) * cCK + s0 + 2*j] =
          make_float2(accG[i][2*j], accG[i][2*j+1]);
    }
  }
}

// ============= K6: SSD Y kernel (mma.sync, 2 passes) ======================
constexpr int Y_AS = 136;                 // A row stride (elems) -> 272B
constexpr int Y_BS = 72;                  // B row stride (elems) -> 144B
constexpr int Y_AH = 0;
constexpr int Y_AL = Y_AH + 128 * Y_AS * 2;   // 34816
constexpr int Y_BH = Y_AL + 128 * Y_AS * 2;   // 69632
constexpr int Y_BL = Y_BH + 128 * Y_BS * 2;   // 88064
constexpr int Y_ACS = Y_BL + 128 * Y_BS * 2;  // 106496
constexpr int Y_DTS = Y_ACS + 512;            // 107008
constexpr int Y_SMEM = Y_DTS + 512;           // 107520

__global__ void __launch_bounds__(256, 2) k_ssd_y(const float* __restrict__ Dv)
{
  char* sm = dyn_smem;
  __nv_bfloat16* Ah = (__nv_bfloat16*)(sm + Y_AH);
  __nv_bfloat16* Al = (__nv_bfloat16*)(sm + Y_AL);
  __nv_bfloat16* Bh = (__nv_bfloat16*)(sm + Y_BH);
  __nv_bfloat16* Bl = (__nv_bfloat16*)(sm + Y_BL);
  float* acs = (float*)(sm + Y_ACS);
  float* dts = (float*)(sm + Y_DTS);
  const uint32_t sb = smem_to_u32(sm);
  const int h = blockIdx.x, c = blockIdx.y, b = blockIdx.z;
  const int tid = threadIdx.x, lane = tid & 31, wid = tid >> 5;
  const size_t rowbase = ((size_t)(b * cL + c * cCK)) * cCD;
  const size_t acb = ((size_t)b * cNH + h) * cL + c * cCK;
  if (tid < 128) { acs[tid] = g_ac[acb + tid]; dts[tid] = g_dt[acb + tid]; }
  __syncthreads();

  // ---- stage Gm (masked, decayed, split) into A region ----
  const size_t gb = ((size_t)(b * cNC + c)) * (cCK * cCK);
  #pragma unroll 1
  for (int q = 0; q < 16; ++q) {
    int i = (tid + q * 256) * 4;
    int l = i >> 7, s = i & 127;
    float4 g = *(const float4*)&g_gm[gb + i];
    float al = acs[l];
    float gv[4] = {g.x, g.y, g.z, g.w};
    #pragma unroll
    for (int j = 0; j < 4; ++j) {
      int ss = s + j;
      float m = (ss <= l) ? fexp(al - acs[ss]) : 0.0f;
      __nv_bfloat16 hh, ll;
      bsplit(gv[j] * m, hh, ll);
      Ah[l * Y_AS + ss] = hh; Al[l * Y_AS + ss] = ll;
    }
  }
  // ---- stage X' = x * dt into B region (natural [s][p]) ----
  #pragma unroll 1
  for (int q = 0; q < 8; ++q) {
    int i = (tid + q * 256) * 4;
    int s = i >> 6, p = i & 63;
    float4 x = *(const float4*)&g_xbc[rowbase + (size_t)s * cCD + h * cHD + p];
    float dv = dts[s];
    float xv[4] = {x.x * dv, x.y * dv, x.z * dv, x.w * dv};
    #pragma unroll
    for (int j = 0; j < 4; ++j) {
      __nv_bfloat16 hh, ll;
      bsplit(xv[j], hh, ll);
      Bh[s * Y_BS + p + j] = hh; Bl[s * Y_BS + p + j] = ll;
    }
  }
  __syncthreads();

  const int wm = (wid >> 1) * 32, wn = (wid & 1) * 32;
  float acc[2][4][4];
  #pragma unroll
  for (int mi = 0; mi < 2; ++mi)
    #pragma unroll
    for (int nj = 0; nj < 4; ++nj)
      #pragma unroll
      for (int q = 0; q < 4; ++q) acc[mi][nj][q] = 0.0f;

  auto mma_pass = [&]() {
    #pragma unroll
    for (int kk = 0; kk < 8; ++kk) {
      uint32_t ah4[2][4], al4[2][4];
      #pragma unroll
      for (int mi = 0; mi < 2; ++mi) {
        uint32_t ad = sb + Y_AH
          + (uint32_t)(wm + mi*16 + (lane & 15)) * (Y_AS * 2)
          + kk*32 + (lane >> 4) * 16;
        ldsm4(ah4[mi], ad);
        ldsm4(al4[mi], ad + (Y_AL - Y_AH));
      }
      #pragma unroll
      for (int nj2 = 0; nj2 < 2; ++nj2) {
        uint32_t bd = sb + Y_BH
          + (uint32_t)(kk*16 + (lane & 15)) * (Y_BS * 2)
          + (uint32_t)(wn + nj2*16 + ((lane >> 4) << 3)) * 2;
        uint32_t bh4[4], bl4[4];
        ldsm4t(bh4, bd);
        ldsm4t(bl4, bd + (Y_BL - Y_BH));
        #pragma unroll
        for (int mi = 0; mi < 2; ++mi) {
          #pragma unroll
          for (int s2 = 0; s2 < 2; ++s2) {
            int nj = nj2 * 2 + s2;
            mma16816(acc[mi][nj], ah4[mi], bh4[2*s2], bh4[2*s2+1]);
            mma16816(acc[mi][nj], ah4[mi], bl4[2*s2], bl4[2*s2+1]);
            mma16816(acc[mi][nj], al4[mi], bh4[2*s2], bh4[2*s2+1]);
          }
        }
      }
    }
  };
  mma_pass();          // Y += Gm @ X'
  __syncthreads();

  // ---- stage Ce = C * exp(ac_l) into A region ----
  #pragma unroll 1
  for (int q = 0; q < 16; ++q) {
    int i = (tid + q * 256) * 4;
    int l = i >> 7, n = i & 127;
    float4 cv = *(const float4*)&g_xbc[rowbase + (size_t)l * cCD + cDS + cST + n];
    float e = fexp(acs[l]);
    float cvv[4] = {cv.x * e, cv.y * e, cv.z * e, cv.w * e};
    #pragma unroll
    for (int j = 0; j < 4; ++j) {
      __nv_bfloat16 hh, ll;
      bsplit(cvv[j], hh, ll);
      Ah[l * Y_AS + n + j] = hh; Al[l * Y_AS + n + j] = ll;
    }
  }
  // ---- stage P (prev states, natural [n][p]) into B region ----
  {
    const size_t pb = (((size_t)b * cNC + c) * cNH + h) * (cST * cHD);
    #pragma unroll 1
    for (int q = 0; q < 8; ++q) {
      int i = (tid + q * 256) * 4;
      int n = i >> 6, p = i & 63;
      float4 pv = *(const float4*)&g_pv[pb + i];
      float pvv[4] = {pv.x, pv.y, pv.z, pv.w};
      #pragma unroll
      for (int j = 0; j < 4; ++j) {
        __nv_bfloat16 hh, ll;
        bsplit(pvv[j], hh, ll);
        Bh[n * Y_BS + p + j] = hh; Bl[n * Y_BS + p + j] = ll;
      }
    }
  }
  __syncthreads();
  mma_pass();          // Y += Ce @ P

  // ---- epilogue: Y + D*x -> g_y ----
  const float Dh = Dv[h];
  #pragma unroll
  for (int mi = 0; mi < 2; ++mi) {
    int row = wm + mi*16 + (lane >> 2);
    #pragma unroll
    for (int nj = 0; nj < 4; ++nj) {
      int col = wn + nj*8 + (lane & 3)*2;
      float2 x0 = *(const float2*)&g_xbc[rowbase + (size_t)row * cCD + h * cHD + col];
      float2 x1 = *(const float2*)&g_xbc[rowbase + (size_t)(row+8) * cCD + h * cHD + col];
      size_t y0 = ((size_t)(b * cL + c * cCK + row)) * cDS + h * cHD + col;
      size_t y1 = ((size_t)(b * cL + c * cCK + row + 8)) * cDS + h * cHD + col;
      *(float2*)&g_y[y0] = make_float2(acc[mi][nj][0] + Dh * x0.x,
                                       acc[mi][nj][1] + Dh * x0.y);
      *(float2*)&g_y[y1] = make_float2(acc[mi][nj][2] + Dh * x1.x,
                                       acc[mi][nj][3] + Dh * x1.y);
    }
  }
}

// ============= K7: gate (silu(z)) + RMSNorm + bf16 split (fused) ==========
__global__ void __launch_bounds__(256) k_gate_norm(const float* __restrict__ norm_w)
{
  const int row = blockIdx.x;
  const int tid = threadIdx.x;
  const size_t zb = (size_t)row * cDP;
  const size_t yb = (size_t)row * cDS;
  float v[16];
  float ss = 0.0f;
  #pragma unroll
  for (int q = 0; q < 16; ++q) {
    int i = tid + q * 256;
    float z = g_zx[zb + i];
    float y = g_y[yb + i];
    float t = y * z * fsig(z);
    v[q] = t;
    ss += t * t;
  }
  #pragma unroll
  for (int o = 16; o > 0; o >>= 1) ss += __shfl_xor_sync(0xffffffffu, ss, o);
  __shared__ float red[8];
  if ((tid & 31) == 0) red[tid >> 5] = ss;
  __syncthreads();
  float tot = 0.0f;
  #pragma unroll
  for (int j = 0; j < 8; ++j) tot += red[j];
  const float scale = rsqrtf(tot / (float)cDS + cEPS);
  #pragma unroll
  for (int q = 0; q < 16; ++q) {
    int i = tid + q * 256;
    float t = v[q] * scale * norm_w[i];
    __nv_bfloat16 hh, ll;
    bsplit(t, hh, ll);
    g_ah[yb + i] = *(unsigned short*)&hh;
    g_al[yb + i] = *(unsigned short*)&ll;
  }
}

// ============= K9: out + reverse(out) =====================================
__global__ void __launch_bounds__(256) k_revadd(float* __restrict__ out)
{
  const int idx4 = blockIdx.x * 256 + threadIdx.x;
  const int tot4 = cB * cL * cDM / 4;
  if (idx4 >= tot4) return;
  const int i = idx4 * 4;
  const int b = i / (cL * cDM);
  const int r = i - b * (cL * cDM);
  const int l = r / cDM;
  const int d = r - l * cDM;
  const size_t rev = ((size_t)b * cL + (cL - 1 - l)) * cDM + d;
  float4 a = *(const float4*)(&g_o[i]);
  float4 c = *(const float4*)(&g_o[rev]);
  a.x += c.x; a.y += c.y; a.z += c.z; a.w += c.w;
  *(float4*)(out + i) = a;
}

// ==========================================================================
extern "C" void kernel_launch(void* const* d_in, const int* in_sizes, int n_in,
                              void* d_out, int out_size) {
  const float* u       = (const float*)d_in[0];
  const float* W_in    = (const float*)d_in[1];
  const float* conv_w  = (const float*)d_in[2];
  const float* conv_b  = (const float*)d_in[3];
  const float* dt_bias = (const float*)d_in[4];
  const float* A_log   = (const float*)d_in[5];
  const float* Dv      = (const float*)d_in[6];
  const float* norm_w  = (const float*)d_in[7];
  const float* W_out   = (const float*)d_in[8];
  float* out = (float*)d_out;

  float* zx; cudaGetSymbolAddress((void**)&zx, g_zx);
  float* ob; cudaGetSymbolAddress((void**)&ob, g_o);
  unsigned short *ah, *al, *bh, *bl, *b2h, *b2l;
  cudaGetSymbolAddress((void**)&ah,  g_ah);
  cudaGetSymbolAddress((void**)&al,  g_al);
  cudaGetSymbolAddress((void**)&bh,  g_bh);
  cudaGetSymbolAddress((void**)&bl,  g_bl);
  cudaGetSymbolAddress((void**)&b2h, g_b2h);
  cudaGetSymbolAddress((void**)&b2l, g_b2l);

  cudaFuncSetAttribute(gemm_mma, cudaFuncAttributeMaxDynamicSharedMemorySize,
                       SMEM_GEMM);
  cudaFuncSetAttribute(k_gmat, cudaFuncAttributeMaxDynamicSharedMemorySize,
                       2 * 128 * 132 * 4);
  cudaFuncSetAttribute(k_states, cudaFuncAttributeMaxDynamicSharedMemorySize,
                       S_SMEM);
  cudaFuncSetAttribute(k_ssd_y, cudaFuncAttributeMaxDynamicSharedMemorySize,
                       Y_SMEM);

  const int M = cB * cL;   // 4096

  // --- prep: split u, W_in, W_out (W_out hoisted so launch #4 = GEMM1) ---
  {
    long totA = (long)M * cDM;
    k_cvt<<<(unsigned)((totA/4 + 255)/256), 256>>>(u, ah, al, M, cDM, totA);
    long totB = (long)cNPAD1 * cDM;
    k_cvt<<<(unsigned)((totB/4 + 255)/256), 256>>>(W_in, bh, bl, cDP, cDM, totB);
    long totB2 = (long)cDM * cDS;
    k_cvt<<<(unsigned)((totB2/4 + 255)/256), 256>>>(W_out, b2h, b2l, cDM, cDS, totB2);
  }
  // --- GEMM1: zx[4096, 8512] ---
  {
    dim3 grid(cNPAD1 / 128, M / 128);
    gemm_mma<<<grid, 256, SMEM_GEMM>>>(
        (const __nv_bfloat16*)ah, (const __nv_bfloat16*)al,
        (const __nv_bfloat16*)bh, (const __nv_bfloat16*)bl, zx, M, cDP, cDM);
  }
  // --- conv + silu + dt ---
  k_conv<<<cB * cL, 256>>>(conv_w, conv_b, dt_bias);
  // --- per-chunk cumsum ---
  { dim3 grid(cNH, cNC, cB); k_scan<<<grid, 128>>>(A_log); }
  // --- chunk states (mma) ---
  { dim3 grid(cNH, cNC, cB); k_states<<<grid, 256, S_SMEM>>>(); }
  // --- carry scan ---
  k_carry<<<cB * cNH, 256>>>();
  // --- unmasked G ---
  { dim3 grid(cNC, cB); k_gmat<<<grid, 256, 2 * 128 * 132 * 4>>>(); }
  // --- Y (mma) ---
  { dim3 grid(cNH, cNC, cB); k_ssd_y<<<grid, 256, Y_SMEM>>>(Dv); }
  // --- gate + rmsnorm + split (fused) ---
  k_gate_norm<<<cB * cL, 256>>>(norm_w);
  // --- GEMM2: o[4096, 2048] ---
  {
    dim3 grid(cDM / 128, M / 128);
    gemm_mma<<<grid, 256, SMEM_GEMM>>>(
        (const __nv_bfloat16*)ah, (const __nv_bfloat16*)al,
        (const __nv_bfloat16*)b2h, (const __nv_bfloat16*)b2l, ob, M, cDM, cDS);
  }
  // --- out + reverse(out) ---
  k_revadd<<<(cB * cL * cDM / 4 + 255) / 256, 256>>>(out);
}

// round 10
// speedup vs baseline: 3.2796x; 1.2854x over previous
#include <cuda_runtime.h>
#include <cuda_bf16.h>
#include <cuda_fp16.h>
#include <cstdint>

#define DEVFN static __device__ __forceinline__

constexpr int cB  = 2;
constexpr int cL  = 2048;
constexpr int cDM = 2048;            // D_MODEL
constexpr int cDS = 4096;            // D_SSM
constexpr int cST = 128;             // D_STATE
constexpr int cNH = 64;              // NHEADS
constexpr int cHD = 64;              // HEADDIM
constexpr int cCK = 128;             // CHUNK
constexpr int cNC = cL / cCK;        // 16
constexpr int cDP = 2*cDS + 2*cST + cNH;   // 8512
constexpr int cCD = cDS + 2*cST;           // 4352
constexpr float cEPS = 1e-5f;

constexpr int cNPAD1 = 8704;         // padded N for GEMM1 (68 * 128)

// ---------------- scratch (static device globals; no allocation) ----------
__device__ float g_zx [(size_t)cB*cL*cDP];           // in-proj output
__device__ float g_xbc[(size_t)cB*cL*cCD];           // conv+silu output
__device__ float g_dt [(size_t)cB*cNH*cL];           // softplus dt, [b][h][l]
__device__ float g_ac [(size_t)cB*cNH*cL];           // per-chunk cumsum, [b][h][l]
__device__ float g_T  [(size_t)cB*cNH*cNC];          // chunk totals
__device__ float g_cs [(size_t)cB*cNC*cNH*cST*cHD];  // per-chunk states
__device__ float g_pv [(size_t)cB*cNC*cNH*cST*cHD];  // carried states
__device__ float g_gm [(size_t)cB*cNC*cCK*cCK];      // unmasked G per (b,c)
__device__ float g_y  [(size_t)cB*cL*cDS];           // y buffer
__device__ float g_o  [(size_t)cB*cL*cDM];           // out-proj output
// fp16 operand buffers
__device__ unsigned short g_ah [(size_t)4096*4096];  // A fp16 (u, then y)
__device__ unsigned short g_bh [(size_t)cNPAD1*2048];// W_in hi
__device__ unsigned short g_bl [(size_t)cNPAD1*2048];// W_in lo
__device__ unsigned short g_b2h[(size_t)cDM*cDS];    // W_out hi
__device__ unsigned short g_b2l[(size_t)cDM*cDS];    // W_out lo

// ---------------- math helpers --------------------------------------------
DEVFN float fexp(float x) {          // exp(x), FFMA-only
  float t = x * 1.44269504088896340736f;
  t = fminf(fmaxf(t, -126.0f), 126.0f);
  float fi = rintf(t);
  float f  = t - fi;
  float p = 1.5403530393381610e-4f;
  p = fmaf(p, f, 1.3333558146428443e-3f);
  p = fmaf(p, f, 9.6181291076284772e-3f);
  p = fmaf(p, f, 5.5504108664821580e-2f);
  p = fmaf(p, f, 2.4022650695910071e-1f);
  p = fmaf(p, f, 6.9314718055994531e-1f);
  p = fmaf(p, f, 1.0f);
  int i = (int)fi;
  return __int_as_float((i + 127) << 23) * p;
}
DEVFN float fsig(float x) { return 1.0f / (1.0f + fexp(-x)); }

DEVFN uint32_t smem_to_u32(const void* p) {
  uint32_t a;
  asm("{ .reg .u64 t; cvta.to.shared.u64 t, %1; cvt.u32.u64 %0, t; }"
      : "=r"(a) : "l"(p));
  return a;
}
DEVFN void cp16(uint32_t saddr, const void* gptr) {
  asm volatile("cp.async.cg.shared.global [%0], [%1], 16;"
               :: "r"(saddr), "l"(gptr) : "memory");
}
DEVFN void ldsm4(uint32_t (&r)[4], uint32_t a) {
  asm volatile("ldmatrix.sync.aligned.m8n8.x4.shared.b16 {%0,%1,%2,%3}, [%4];"
    : "=r"(r[0]), "=r"(r[1]), "=r"(r[2]), "=r"(r[3]) : "r"(a));
}
DEVFN void ldsm4t(uint32_t (&r)[4], uint32_t a) {
  asm volatile("ldmatrix.sync.aligned.m8n8.x4.trans.shared.b16 {%0,%1,%2,%3}, [%4];"
    : "=r"(r[0]), "=r"(r[1]), "=r"(r[2]), "=r"(r[3]) : "r"(a));
}
DEVFN void mma16816(float (&d)[4], const uint32_t (&a)[4], uint32_t b0, uint32_t b1) {
  asm volatile("mma.sync.aligned.m16n8k16.row.col.f32.bf16.bf16.f32 "
    "{%0,%1,%2,%3},{%4,%5,%6,%7},{%8,%9},{%0,%1,%2,%3};"
    : "+f"(d[0]), "+f"(d[1]), "+f"(d[2]), "+f"(d[3])
    : "r"(a[0]), "r"(a[1]), "r"(a[2]), "r"(a[3]), "r"(b0), "r"(b1));
}
DEVFN void mma16816h(float (&d)[4], const uint32_t (&a)[4], uint32_t b0, uint32_t b1) {
  asm volatile("mma.sync.aligned.m16n8k16.row.col.f32.f16.f16.f32 "
    "{%0,%1,%2,%3},{%4,%5,%6,%7},{%8,%9},{%0,%1,%2,%3};"
    : "+f"(d[0]), "+f"(d[1]), "+f"(d[2]), "+f"(d[3])
    : "r"(a[0]), "r"(a[1]), "r"(a[2]), "r"(a[3]), "r"(b0), "r"(b1));
}
DEVFN void bsplit(float v, __nv_bfloat16& h, __nv_bfloat16& l) {
  h = __float2bfloat16_rn(v);
  l = __float2bfloat16_rn(v - __bfloat162float(h));
}
DEVFN void hsplit(float v, __half& h, __half& l) {
  h = __float2half_rn(v);
  l = __float2half_rn(v - __half2float(h));
}

// single shared dynamic-smem declaration for all kernels
extern __shared__ char dyn_smem[];

// ============= K0a: fp32 -> fp16, no padding (A matrices) ================
__global__ void __launch_bounds__(256) k_cvt_h(
    const float* __restrict__ src, unsigned short* __restrict__ dst, long tot)
{
  long i = ((long)blockIdx.x * 256 + threadIdx.x) * 4;
  if (i >= tot) return;
  float4 v = *(const float4*)(src + i);
  __half h0 = __float2half_rn(v.x), h1 = __float2half_rn(v.y);
  __half h2 = __float2half_rn(v.z), h3 = __float2half_rn(v.w);
  ushort4 hv;
  hv.x = *(unsigned short*)&h0; hv.y = *(unsigned short*)&h1;
  hv.z = *(unsigned short*)&h2; hv.w = *(unsigned short*)&h3;
  *(ushort4*)(dst + i) = hv;
}

// ============= K0b: fp32 -> (hi, lo) fp16, with row zero-padding ==========
__global__ void __launch_bounds__(256) k_cvt_hl(
    const float* __restrict__ src, unsigned short* __restrict__ hi,
    unsigned short* __restrict__ lo, int srcRows, int K, long tot)
{
  long i = ((long)blockIdx.x * 256 + threadIdx.x) * 4;
  if (i >= tot) return;
  long row = i / K;
  float4 v = make_float4(0.f, 0.f, 0.f, 0.f);
  if (row < srcRows) v = *(const float4*)(src + i);
  __half h0, h1, h2, h3, l0, l1, l2, l3;
  hsplit(v.x, h0, l0); hsplit(v.y, h1, l1);
  hsplit(v.z, h2, l2); hsplit(v.w, h3, l3);
  ushort4 hv, lv;
  hv.x = *(unsigned short*)&h0; hv.y = *(unsigned short*)&h1;
  hv.z = *(unsigned short*)&h2; hv.w = *(unsigned short*)&h3;
  lv.x = *(unsigned short*)&l0; lv.y = *(unsigned short*)&l1;
  lv.z = *(unsigned short*)&l2; lv.w = *(unsigned short*)&l3;
  *(ushort4*)(hi + i) = hv;
  *(ushort4*)(lo + i) = lv;
}

// ============= fp16 2-MMA GEMM: C[M,N] = A[M,K] * B[N,K]^T ================
// A plain fp16; B split hi/lo fp16. C = Ah*(Bh+Bl) (error ~2^-12).
// 128x128x32 CTA tile, 8 warps, 3-stage cp.async pipeline, 2 CTAs/SM.
constexpr int ROWB  = 80;
constexpr int TILEB = 128 * ROWB;         // 10240
constexpr int STGB  = 3 * TILEB;          // A | Bh | Bl per stage
constexpr int SMEM_GEMM = 3 * STGB;       // 92160

__global__ void __launch_bounds__(256, 2) gemm_mma(
    const __half* __restrict__ A,
    const __half* __restrict__ Bh, const __half* __restrict__ Bl,
    float* __restrict__ C, int M, int N, int K)
{
  char* smem = dyn_smem;
  const uint32_t sb0 = smem_to_u32(smem);
  const int tid = threadIdx.x;
  const int lane = tid & 31, wid = tid >> 5;
  const int bm = blockIdx.y * 128, bn = blockIdx.x * 128;
  const int wm = (wid >> 1) * 32, wn = (wid & 1) * 64;

  float acc[2][8][4];
  #pragma unroll
  for (int i = 0; i < 2; ++i)
    #pragma unroll
    for (int j = 0; j < 8; ++j)
      #pragma unroll
      for (int q = 0; q < 4; ++q) acc[i][j][q] = 0.0f;

  auto load_tile = [&](int kt, int stg) {
    const uint32_t sb = sb0 + stg * STGB;
    const long kb = (long)kt * 32;
    #pragma unroll
    for (int i = 0; i < 2; ++i) {
      int o = tid + 256 * i;
      int row = o >> 2, seg = o & 3;
      uint32_t soff = row * ROWB + seg * 16;
      long ga = (long)(bm + row) * K + kb + seg * 8;
      long gb = (long)(bn + row) * K + kb + seg * 8;
      cp16(sb + soff,             A  + ga);
      cp16(sb + TILEB + soff,     Bh + gb);
      cp16(sb + 2*TILEB + soff,   Bl + gb);
    }
    asm volatile("cp.async.commit_group;" ::: "memory");
  };

  const int KT = K >> 5;       // K/32, always >= 2 here
  load_tile(0, 0);
  load_tile(1, 1);
  for (int kt = 0; kt < KT; ++kt) {
    const int stg = kt % 3;
    if (kt + 2 < KT) {
      load_tile(kt + 2, (kt + 2) % 3);
    } else {
      asm volatile("cp.async.commit_group;" ::: "memory");
    }
    asm volatile("cp.async.wait_group 2;" ::: "memory");
    __syncthreads();
    const uint32_t sb = sb0 + stg * STGB;
    #pragma unroll
    for (int h = 0; h < 2; ++h) {
      uint32_t ah[2][4];
      #pragma unroll
      for (int mi = 0; mi < 2; ++mi) {
        uint32_t ad = sb + (uint32_t)(wm + mi*16 + (lane & 15)) * ROWB
                         + h*32 + (lane >> 4) * 16;
        ldsm4(ah[mi], ad);
      }
      #pragma unroll
      for (int nj2 = 0; nj2 < 4; ++nj2) {
        uint32_t bd = sb + TILEB
          + (uint32_t)(wn + nj2*16 + (lane & 7) + ((lane >> 4) << 3)) * ROWB
          + h*32 + ((lane >> 3) & 1) * 16;
        uint32_t bh4[4], bl4[4];
        ldsm4(bh4, bd);
        ldsm4(bl4, bd + TILEB);
        #pragma unroll
        for (int mi = 0; mi < 2; ++mi) {
          #pragma unroll
          for (int s = 0; s < 2; ++s) {
            int nj = nj2 * 2 + s;
            mma16816h(acc[mi][nj], ah[mi], bh4[2*s], bh4[2*s+1]);
            mma16816h(acc[mi][nj], ah[mi], bl4[2*s], bl4[2*s+1]);
          }
        }
      }
    }
    __syncthreads();
  }

  #pragma unroll
  for (int mi = 0; mi < 2; ++mi) {
    int row = bm + wm + mi*16 + (lane >> 2);
    #pragma unroll
    for (int nj = 0; nj < 8; ++nj) {
      int col = bn + wn + nj*8 + (lane & 3)*2;
      if (col < N) {
        *(float2*)(C + (long)row * N + col) =
            make_float2(acc[mi][nj][0], acc[mi][nj][1]);
        *(float2*)(C + (long)(row + 8) * N + col) =
            make_float2(acc[mi][nj][2], acc[mi][nj][3]);
      }
    }
  }
}

// ============= K2: conv1d + SiLU + softplus(dt), float4 ===================
__global__ void __launch_bounds__(256) k_conv(
    const float* __restrict__ conv_w, const float* __restrict__ conv_b,
    const float* __restrict__ dt_bias)
{
  const int row = blockIdx.x;
  const int b = row / cL, l = row % cL;
  const int tid = threadIdx.x;
  const float* z0 = &g_zx[(size_t)row * cDP + cDS];
  float* obp = &g_xbc[(size_t)row * cCD];
  const bool p1 = (l >= 1), p2 = (l >= 2);
  #pragma unroll 1
  for (int q = 0; q < 5; ++q) {
    int c4 = tid + q * 256;
    if (c4 >= cCD / 4) break;
    int c = c4 * 4;
    float4 wa = *(const float4*)(conv_w + c*3);
    float4 wb = *(const float4*)(conv_w + c*3 + 4);
    float4 wc = *(const float4*)(conv_w + c*3 + 8);
    float4 bs = *(const float4*)(conv_b + c);
    float4 x2 = p2 ? *(const float4*)(z0 - 2*(size_t)cDP + c) : make_float4(0,0,0,0);
    float4 x1 = p1 ? *(const float4*)(z0 -   (size_t)cDP + c) : make_float4(0,0,0,0);
    float4 x0 = *(const float4*)(z0 + c);
    float4 s;
    s.x = bs.x + x2.x*wa.x + x1.x*wa.y + x0.x*wa.z;
    s.y = bs.y + x2.y*wa.w + x1.y*wb.x + x0.y*wb.y;
    s.z = bs.z + x2.z*wb.z + x1.z*wb.w + x0.z*wc.x;
    s.w = bs.w + x2.w*wc.y + x1.w*wc.z + x0.w*wc.w;
    s.x *= fsig(s.x); s.y *= fsig(s.y); s.z *= fsig(s.z); s.w *= fsig(s.w);
    *(float4*)(obp + c) = s;
  }
  if (tid < cNH) {
    float v = g_zx[(size_t)row * cDP + (cDP - cNH) + tid] + dt_bias[tid];
    float sp = (v > 15.0f) ? v : log1pf(expf(v));
    g_dt[((size_t)b * cNH + tid) * cL + l] = sp;
  }
}

// ============= K3: per-chunk inclusive cumsum of dt*A =====================
__global__ void __launch_bounds__(128) k_scan(const float* __restrict__ A_log)
{
  const int h = blockIdx.x, c = blockIdx.y, b = blockIdx.z;
  const int l = threadIdx.x;
  const float ah = -expf(A_log[h]);
  const size_t base = ((size_t)b * cNH + h) * cL + c * cCK;
  __shared__ float s[128];
  s[l] = g_dt[base + l] * ah;
  __syncthreads();
  #pragma unroll
  for (int off = 1; off < 128; off <<= 1) {
    float t = (l >= off) ? s[l - off] : 0.0f;
    __syncthreads();
    s[l] += t;
    __syncthreads();
  }
  g_ac[base + l] = s[l];
  if (l == 127) g_T[((size_t)b * cNH + h) * cNC + c] = s[127];
}

// ============= K4: chunk states (mma.sync, split-bf16) ====================
constexpr int S_AS  = 136;
constexpr int S_BS  = 72;
constexpr int S_AHo = 0;
constexpr int S_ALo = 128 * S_AS * 2;          // 34816
constexpr int S_BHo = 2 * 128 * S_AS * 2;      // 69632
constexpr int S_BLo = S_BHo + 128 * S_BS * 2;  // 88064
constexpr int S_SCo = S_BLo + 128 * S_BS * 2;  // 106496
constexpr int S_SMEM = S_SCo + 512;            // 107008

__global__ void __launch_bounds__(256, 2) k_states()
{
  char* sm = dyn_smem;
  __nv_bfloat16* Ah = (__nv_bfloat16*)(sm + S_AHo);
  __nv_bfloat16* Al = (__nv_bfloat16*)(sm + S_ALo);
  __nv_bfloat16* Bh = (__nv_bfloat16*)(sm + S_BHo);
  __nv_bfloat16* Bl = (__nv_bfloat16*)(sm + S_BLo);
  float* sc = (float*)(sm + S_SCo);
  const uint32_t sb = smem_to_u32(sm);
  const int h = blockIdx.x, c = blockIdx.y, b = blockIdx.z;
  const int tid = threadIdx.x, lane = tid & 31, wid = tid >> 5;
  const size_t rowbase = ((size_t)(b * cL + c * cCK)) * cCD;
  const size_t acb = ((size_t)b * cNH + h) * cL + c * cCK;
  if (tid < 128) {
    float T = g_T[((size_t)b * cNH + h) * cNC + c];
    sc[tid] = g_dt[acb + tid] * fexp(T - g_ac[acb + tid]);
  }
  __syncthreads();
  #pragma unroll 1
  for (int q = 0; q < 16; ++q) {
    int i = (tid + q * 256) * 4;
    int l = i >> 7, n = i & 127;
    float4 v = *(const float4*)&g_xbc[rowbase + (size_t)l * cCD + cDS + n];
    float vv[4] = {v.x, v.y, v.z, v.w};
    #pragma unroll
    for (int j = 0; j < 4; ++j) {
      __nv_bfloat16 hh, ll;
      bsplit(vv[j], hh, ll);
      Ah[l * S_AS + n + j] = hh; Al[l * S_AS + n + j] = ll;
    }
  }
  #pragma unroll 1
  for (int q = 0; q < 8; ++q) {
    int i = (tid + q * 256) * 4;
    int l = i >> 6, p = i & 63;
    float4 x = *(const float4*)&g_xbc[rowbase + (size_t)l * cCD + h * cHD + p];
    float s = sc[l];
    float xv[4] = {x.x * s, x.y * s, x.z * s, x.w * s};
    #pragma unroll
    for (int j = 0; j < 4; ++j) {
      __nv_bfloat16 hh, ll;
      bsplit(xv[j], hh, ll);
      Bh[l * S_BS + p + j] = hh; Bl[l * S_BS + p + j] = ll;
    }
  }
  __syncthreads();

  const int wm = (wid >> 1) * 32, wn = (wid & 1) * 32;
  float acc[2][4][4];
  #pragma unroll
  for (int mi = 0; mi < 2; ++mi)
    #pragma unroll
    for (int nj = 0; nj < 4; ++nj)
      #pragma unroll
      for (int q = 0; q < 4; ++q) acc[mi][nj][q] = 0.0f;

  #pragma unroll
  for (int kk = 0; kk < 8; ++kk) {
    uint32_t ah4[2][4], al4[2][4];
    #pragma unroll
    for (int mi = 0; mi < 2; ++mi) {
      uint32_t ad = sb + S_AHo
        + (uint32_t)(kk*16 + (lane & 7) + ((lane >> 4) << 3)) * (S_AS * 2)
        + (uint32_t)(wm + mi*16 + (lane & 8)) * 2;
      ldsm4t(ah4[mi], ad);
      ldsm4t(al4[mi], ad + (S_ALo - S_AHo));
    }
    #pragma unroll
    for (int nj2 = 0; nj2 < 2; ++nj2) {
      uint32_t bd = sb + S_BHo
        + (uint32_t)(kk*16 + (lane & 15)) * (S_BS * 2)
        + (uint32_t)(wn + nj2*16 + ((lane >> 4) << 3)) * 2;
      uint32_t bh4[4], bl4[4];
      ldsm4t(bh4, bd);
      ldsm4t(bl4, bd + (S_BLo - S_BHo));
      #pragma unroll
      for (int mi = 0; mi < 2; ++mi) {
        #pragma unroll
        for (int s2 = 0; s2 < 2; ++s2) {
          int nj = nj2 * 2 + s2;
          mma16816(acc[mi][nj], ah4[mi], bh4[2*s2], bh4[2*s2+1]);
          mma16816(acc[mi][nj], ah4[mi], bl4[2*s2], bl4[2*s2+1]);
          mma16816(acc[mi][nj], al4[mi], bh4[2*s2], bh4[2*s2+1]);
        }
      }
    }
  }

  const size_t ob = (((size_t)b * cNC + c) * cNH + h) * (cST * cHD);
  #pragma unroll
  for (int mi = 0; mi < 2; ++mi) {
    int row = wm + mi*16 + (lane >> 2);
    #pragma unroll
    for (int nj = 0; nj < 4; ++nj) {
      int col = wn + nj*8 + (lane & 3)*2;
      *(float2*)&g_cs[ob + (size_t)row * cHD + col] =
          make_float2(acc[mi][nj][0], acc[mi][nj][1]);
      *(float2*)&g_cs[ob + (size_t)(row + 8) * cHD + col] =
          make_float2(acc[mi][nj][2], acc[mi][nj][3]);
    }
  }
}

// ============= K5: inter-chunk carry scan =================================
__global__ void __launch_bounds__(256) k_carry()
{
  const int bh = blockIdx.x;
  const int b = bh >> 6, h = bh & 63;
  const int tid = threadIdx.x;
  float carry[32];
  #pragma unroll
  for (int j = 0; j < 32; ++j) carry[j] = 0.0f;
  for (int c = 0; c < cNC; ++c) {
    if (c > 0) {
      float eT = fexp(g_T[(size_t)bh * cNC + (c - 1)]);
      const size_t inb = (((size_t)b * cNC + (c - 1)) * cNH + h) * (cST * cHD);
      #pragma unroll
      for (int j = 0; j < 32; ++j)
        carry[j] = carry[j] * eT + g_cs[inb + tid + j * 256];
    }
    const size_t ob = (((size_t)b * cNC + c) * cNH + h) * (cST * cHD);
    #pragma unroll
    for (int j = 0; j < 32; ++j)
      g_pv[ob + tid + j * 256] = carry[j];
  }
}

// ============= K5.5: unmasked G = C * B^T per (b,c) =======================
__global__ void __launch_bounds__(256) k_gmat()
{
  float* smf = (float*)dyn_smem;
  float* Ct = smf;                 // [n][l] stride 132
  float* Bt = smf + 128 * 132;
  const int c = blockIdx.x, b = blockIdx.y;
  const int tid = threadIdx.x;
  const size_t rowbase = ((size_t)(b * cL + c * cCK)) * cCD;
  #pragma unroll 1
  for (int q = 0; q < 16; ++q) {
    int i = tid + q * 256;
    int l = i >> 5, nq = i & 31;
    const float* src = &g_xbc[rowbase + (size_t)l * cCD];
    float4 cv = *(const float4*)(src + cDS + cST + nq * 4);
    float4 bv = *(const float4*)(src + cDS + nq * 4);
    int n = nq * 4;
    Ct[(n+0)*132 + l] = cv.x; Ct[(n+1)*132 + l] = cv.y;
    Ct[(n+2)*132 + l] = cv.z; Ct[(n+3)*132 + l] = cv.w;
    Bt[(n+0)*132 + l] = bv.x; Bt[(n+1)*132 + l] = bv.y;
    Bt[(n+2)*132 + l] = bv.z; Bt[(n+3)*132 + l] = bv.w;
  }
  __syncthreads();
  const int ty = tid >> 4, tx = tid & 15;
  const int l0 = ty * 8, s0 = tx * 8;
  float accG[8][8] = {};
  for (int n = 0; n < cST; ++n) {
    float4 a0 = *(const float4*)&Ct[n*132 + l0];
    float4 a1 = *(const float4*)&Ct[n*132 + l0 + 4];
    float4 b0 = *(const float4*)&Bt[n*132 + s0];
    float4 b1 = *(const float4*)&Bt[n*132 + s0 + 4];
    float a[8]  = {a0.x, a0.y, a0.z, a0.w, a1.x, a1.y, a1.z, a1.w};
    float bb[8] = {b0.x, b0.y, b0.z, b0.w, b1.x, b1.y, b1.z, b1.w};
    #pragma unroll
    for (int i = 0; i < 8; ++i)
      #pragma unroll
      for (int j = 0; j < 8; ++j) accG[i][j] += a[i] * bb[j];
  }
  const size_t gb = ((size_t)(b * cNC + c)) * (cCK * cCK);
  #pragma unroll
  for (int i = 0; i < 8; ++i) {
    #pragma unroll
    for (int j = 0; j < 4; ++j) {
      *(float2*)&g_gm[gb + (size_t)(l0 + i) * cCK + s0 + 2*j] =
          make_float2(accG[i][2*j], accG[i][2*j+1]);
    }
  }
}

// ============= K6: SSD Y kernel (mma.sync, 2 passes) ======================
constexpr int Y_AS = 136;
constexpr int Y_BS = 72;
constexpr int Y_AH = 0;
constexpr int Y_AL = Y_AH + 128 * Y_AS * 2;   // 34816
constexpr int Y_BH = Y_AL + 128 * Y_AS * 2;   // 69632
constexpr int Y_BL = Y_BH + 128 * Y_BS * 2;   // 88064
constexpr int Y_ACS = Y_BL + 128 * Y_BS * 2;  // 106496
constexpr int Y_DTS = Y_ACS + 512;            // 107008
constexpr int Y_SMEM = Y_DTS + 512;           // 107520

__global__ void __launch_bounds__(256, 2) k_ssd_y(const float* __restrict__ Dv)
{
  char* sm = dyn_smem;
  __nv_bfloat16* Ah = (__nv_bfloat16*)(sm + Y_AH);
  __nv_bfloat16* Al = (__nv_bfloat16*)(sm + Y_AL);
  __nv_bfloat16* Bh = (__nv_bfloat16*)(sm + Y_BH);
  __nv_bfloat16* Bl = (__nv_bfloat16*)(sm + Y_BL);
  float* acs = (float*)(sm + Y_ACS);
  float* dts = (float*)(sm + Y_DTS);
  const uint32_t sb = smem_to_u32(sm);
  const int h = blockIdx.x, c = blockIdx.y, b = blockIdx.z;
  const int tid = threadIdx.x, lane = tid & 31, wid = tid >> 5;
  const size_t rowbase = ((size_t)(b * cL + c * cCK)) * cCD;
  const size_t acb = ((size_t)b * cNH + h) * cL + c * cCK;
  if (tid < 128) { acs[tid] = g_ac[acb + tid]; dts[tid] = g_dt[acb + tid]; }
  __syncthreads();

  const size_t gb = ((size_t)(b * cNC + c)) * (cCK * cCK);
  #pragma unroll 1
  for (int q = 0; q < 16; ++q) {
    int i = (tid + q * 256) * 4;
    int l = i >> 7, s = i & 127;
    float4 g = *(const float4*)&g_gm[gb + i];
    float al = acs[l];
    float gv[4] = {g.x, g.y, g.z, g.w};
    #pragma unroll
    for (int j = 0; j < 4; ++j) {
      int ss = s + j;
      float m = (ss <= l) ? fexp(al - acs[ss]) : 0.0f;
      __nv_bfloat16 hh, ll;
      bsplit(gv[j] * m, hh, ll);
      Ah[l * Y_AS + ss] = hh; Al[l * Y_AS + ss] = ll;
    }
  }
  #pragma unroll 1
  for (int q = 0; q < 8; ++q) {
    int i = (tid + q * 256) * 4;
    int s = i >> 6, p = i & 63;
    float4 x = *(const float4*)&g_xbc[rowbase + (size_t)s * cCD + h * cHD + p];
    float dv = dts[s];
    float xv[4] = {x.x * dv, x.y * dv, x.z * dv, x.w * dv};
    #pragma unroll
    for (int j = 0; j < 4; ++j) {
      __nv_bfloat16 hh, ll;
      bsplit(xv[j], hh, ll);
      Bh[s * Y_BS + p + j] = hh; Bl[s * Y_BS + p + j] = ll;
    }
  }
  __syncthreads();

  const int wm = (wid >> 1) * 32, wn = (wid & 1) * 32;
  float acc[2][4][4];
  #pragma unroll
  for (int mi = 0; mi < 2; ++mi)
    #pragma unroll
    for (int nj = 0; nj < 4; ++nj)
      #pragma unroll
      for (int q = 0; q < 4; ++q) acc[mi][nj][q] = 0.0f;

  auto mma_pass = [&]() {
    #pragma unroll
    for (int kk = 0; kk < 8; ++kk) {
      uint32_t ah4[2][4], al4[2][4];
      #pragma unroll
      for (int mi = 0; mi < 2; ++mi) {
        uint32_t ad = sb + Y_AH
          + (uint32_t)(wm + mi*16 + (lane & 15)) * (Y_AS * 2)
          + kk*32 + (lane >> 4) * 16;
        ldsm4(ah4[mi], ad);
        ldsm4(al4[mi], ad + (Y_AL - Y_AH));
      }
      #pragma unroll
      for (int nj2 = 0; nj2 < 2; ++nj2) {
        uint32_t bd = sb + Y_BH
          + (uint32_t)(kk*16 + (lane & 15)) * (Y_BS * 2)
          + (uint32_t)(wn + nj2*16 + ((lane >> 4) << 3)) * 2;
        uint32_t bh4[4], bl4[4];
        ldsm4t(bh4, bd);
        ldsm4t(bl4, bd + (Y_BL - Y_BH));
        #pragma unroll
        for (int mi = 0; mi < 2; ++mi) {
          #pragma unroll
          for (int s2 = 0; s2 < 2; ++s2) {
            int nj = nj2 * 2 + s2;
            mma16816(acc[mi][nj], ah4[mi], bh4[2*s2], bh4[2*s2+1]);
            mma16816(acc[mi][nj], ah4[mi], bl4[2*s2], bl4[2*s2+1]);
            mma16816(acc[mi][nj], al4[mi], bh4[2*s2], bh4[2*s2+1]);
          }
        }
      }
    }
  };
  mma_pass();          // Y += Gm @ X'
  __syncthreads();

  #pragma unroll 1
  for (int q = 0; q < 16; ++q) {
    int i = (tid + q * 256) * 4;
    int l = i >> 7, n = i & 127;
    float4 cv = *(const float4*)&g_xbc[rowbase + (size_t)l * cCD + cDS + cST + n];
    float e = fexp(acs[l]);
    float cvv[4] = {cv.x * e, cv.y * e, cv.z * e, cv.w * e};
    #pragma unroll
    for (int j = 0; j < 4; ++j) {
      __nv_bfloat16 hh, ll;
      bsplit(cvv[j], hh, ll);
      Ah[l * Y_AS + n + j] = hh; Al[l * Y_AS + n + j] = ll;
    }
  }
  {
    const size_t pb = (((size_t)b * cNC + c) * cNH + h) * (cST * cHD);
    #pragma unroll 1
    for (int q = 0; q < 8; ++q) {
      int i = (tid + q * 256) * 4;
      int n = i >> 6, p = i & 63;
      float4 pv = *(const float4*)&g_pv[pb + i];
      float pvv[4] = {pv.x, pv.y, pv.z, pv.w};
      #pragma unroll
      for (int j = 0; j < 4; ++j) {
        __nv_bfloat16 hh, ll;
        bsplit(pvv[j], hh, ll);
        Bh[n * Y_BS + p + j] = hh; Bl[n * Y_BS + p + j] = ll;
      }
    }
  }
  __syncthreads();
  mma_pass();          // Y += Ce @ P

  const float Dh = Dv[h];
  #pragma unroll
  for (int mi = 0; mi < 2; ++mi) {
    int row = wm + mi*16 + (lane >> 2);
    #pragma unroll
    for (int nj = 0; nj < 4; ++nj) {
      int col = wn + nj*8 + (lane & 3)*2;
      float2 x0 = *(const float2*)&g_xbc[rowbase + (size_t)row * cCD + h * cHD + col];
      float2 x1 = *(const float2*)&g_xbc[rowbase + (size_t)(row+8) * cCD + h * cHD + col];
      size_t y0 = ((size_t)(b * cL + c * cCK + row)) * cDS + h * cHD + col;
      size_t y1 = ((size_t)(b * cL + c * cCK + row + 8)) * cDS + h * cHD + col;
      *(float2*)&g_y[y0] = make_float2(acc[mi][nj][0] + Dh * x0.x,
                                       acc[mi][nj][1] + Dh * x0.y);
      *(float2*)&g_y[y1] = make_float2(acc[mi][nj][2] + Dh * x1.x,
                                       acc[mi][nj][3] + Dh * x1.y);
    }
  }
}

// ============= K7: gate (silu(z)) + RMSNorm + fp16 cvt (fused) ============
__global__ void __launch_bounds__(256) k_gate_norm(const float* __restrict__ norm_w)
{
  const int row = blockIdx.x;
  const int tid = threadIdx.x;
  const size_t zb = (size_t)row * cDP;
  const size_t yb = (size_t)row * cDS;
  float v[16];
  float ss = 0.0f;
  #pragma unroll
  for (int q = 0; q < 16; ++q) {
    int i = tid + q * 256;
    float z = g_zx[zb + i];
    float y = g_y[yb + i];
    float t = y * z * fsig(z);
    v[q] = t;
    ss += t * t;
  }
  #pragma unroll
  for (int o = 16; o > 0; o >>= 1) ss += __shfl_xor_sync(0xffffffffu, ss, o);
  __shared__ float red[8];
  if ((tid & 31) == 0) red[tid >> 5] = ss;
  __syncthreads();
  float tot = 0.0f;
  #pragma unroll
  for (int j = 0; j < 8; ++j) tot += red[j];
  const float scale = rsqrtf(tot / (float)cDS + cEPS);
  #pragma unroll
  for (int q = 0; q < 16; ++q) {
    int i = tid + q * 256;
    float t = v[q] * scale * norm_w[i];
    __half hh = __float2half_rn(t);
    g_ah[yb + i] = *(unsigned short*)&hh;
  }
}

// ============= K9: out + reverse(out) =====================================
__global__ void __launch_bounds__(256) k_revadd(float* __restrict__ out)
{
  const int idx4 = blockIdx.x * 256 + threadIdx.x;
  const int tot4 = cB * cL * cDM / 4;
  if (idx4 >= tot4) return;
  const int i = idx4 * 4;
  const int b = i / (cL * cDM);
  const int r = i - b * (cL * cDM);
  const int l = r / cDM;
  const int d = r - l * cDM;
  const size_t rev = ((size_t)b * cL + (cL - 1 - l)) * cDM + d;
  float4 a = *(const float4*)(&g_o[i]);
  float4 c = *(const float4*)(&g_o[rev]);
  a.x += c.x; a.y += c.y; a.z += c.z; a.w += c.w;
  *(float4*)(out + i) = a;
}

// ==========================================================================
extern "C" void kernel_launch(void* const* d_in, const int* in_sizes, int n_in,
                              void* d_out, int out_size) {
  const float* u       = (const float*)d_in[0];
  const float* W_in    = (const float*)d_in[1];
  const float* conv_w  = (const float*)d_in[2];
  const float* conv_b  = (const float*)d_in[3];
  const float* dt_bias = (const float*)d_in[4];
  const float* A_log   = (const float*)d_in[5];
  const float* Dv      = (const float*)d_in[6];
  const float* norm_w  = (const float*)d_in[7];
  const float* W_out   = (const float*)d_in[8];
  float* out = (float*)d_out;

  float* zx; cudaGetSymbolAddress((void**)&zx, g_zx);
  float* ob; cudaGetSymbolAddress((void**)&ob, g_o);
  unsigned short *ah, *bh, *bl, *b2h, *b2l;
  cudaGetSymbolAddress((void**)&ah,  g_ah);
  cudaGetSymbolAddress((void**)&bh,  g_bh);
  cudaGetSymbolAddress((void**)&bl,  g_bl);
  cudaGetSymbolAddress((void**)&b2h, g_b2h);
  cudaGetSymbolAddress((void**)&b2l, g_b2l);

  cudaFuncSetAttribute(gemm_mma, cudaFuncAttributeMaxDynamicSharedMemorySize,
                       SMEM_GEMM);
  cudaFuncSetAttribute(k_gmat, cudaFuncAttributeMaxDynamicSharedMemorySize,
                       2 * 128 * 132 * 4);
  cudaFuncSetAttribute(k_states, cudaFuncAttributeMaxDynamicSharedMemorySize,
                       S_SMEM);
  cudaFuncSetAttribute(k_ssd_y, cudaFuncAttributeMaxDynamicSharedMemorySize,
                       Y_SMEM);

  const int M = cB * cL;   // 4096

  // --- prep: u -> fp16; W_in, W_out -> fp16 hi/lo (launch #4 = GEMM1) ---
  {
    long totA = (long)M * cDM;
    k_cvt_h<<<(unsigned)((totA/4 + 255)/256), 256>>>(u, ah, totA);
    long totB = (long)cNPAD1 * cDM;
    k_cvt_hl<<<(unsigned)((totB/4 + 255)/256), 256>>>(W_in, bh, bl, cDP, cDM, totB);
    long totB2 = (long)cDM * cDS;
    k_cvt_hl<<<(unsigned)((totB2/4 + 255)/256), 256>>>(W_out, b2h, b2l, cDM, cDS, totB2);
  }
  // --- GEMM1: zx[4096, 8512] ---
  {
    dim3 grid(cNPAD1 / 128, M / 128);
    gemm_mma<<<grid, 256, SMEM_GEMM>>>(
        (const __half*)ah, (const __half*)bh, (const __half*)bl,
        zx, M, cDP, cDM);
  }
  // --- conv + silu + dt ---
  k_conv<<<cB * cL, 256>>>(conv_w, conv_b, dt_bias);
  // --- per-chunk cumsum ---
  { dim3 grid(cNH, cNC, cB); k_scan<<<grid, 128>>>(A_log); }
  // --- chunk states (mma) ---
  { dim3 grid(cNH, cNC, cB); k_states<<<grid, 256, S_SMEM>>>(); }
  // --- carry scan ---
  k_carry<<<cB * cNH, 256>>>();
  // --- unmasked G ---
  { dim3 grid(cNC, cB); k_gmat<<<grid, 256, 2 * 128 * 132 * 4>>>(); }
  // --- Y (mma) ---
  { dim3 grid(cNH, cNC, cB); k_ssd_y<<<grid, 256, Y_SMEM>>>(Dv); }
  // --- gate + rmsnorm + fp16 cvt (fused) ---
  k_gate_norm<<<cB * cL, 256>>>(norm_w);
  // --- GEMM2: o[4096, 2048] ---
  {
    dim3 grid(cDM / 128, M / 128);
    gemm_mma<<<grid, 256, SMEM_GEMM>>>(
        (const __half*)ah, (const __half*)b2h, (const __half*)b2l,
        ob, M, cDM, cDS);
  }
  // --- out + reverse(out) ---
  k_revadd<<<(cB * cL * cDM / 4 + 255) / 256, 256>>>(out);
}

// round 11
// speedup vs baseline: 3.4100x; 1.0398x over previous
#include <cuda_runtime.h>
#include <cuda_bf16.h>
#include <cuda_fp16.h>
#include <cstdint>

#define DEVFN static __device__ __forceinline__

constexpr int cB  = 2;
constexpr int cL  = 2048;
constexpr int cDM = 2048;            // D_MODEL
constexpr int cDS = 4096;            // D_SSM
constexpr int cST = 128;             // D_STATE
constexpr int cNH = 64;              // NHEADS
constexpr int cHD = 64;              // HEADDIM
constexpr int cCK = 128;             // CHUNK
constexpr int cNC = cL / cCK;        // 16
constexpr int cDP = 2*cDS + 2*cST + cNH;   // 8512
constexpr int cCD = cDS + 2*cST;           // 4352
constexpr float cEPS = 1e-5f;

constexpr int cNPAD1 = 8704;         // padded N for GEMM1 (68 * 128)

// ---------------- scratch (static device globals; no allocation) ----------
__device__ float g_zx [(size_t)cB*cL*cDP];           // in-proj output
__device__ float g_xbc[(size_t)cB*cL*cCD];           // conv+silu output
__device__ float g_dt [(size_t)cB*cNH*cL];           // softplus dt, [b][h][l]
__device__ float g_ac [(size_t)cB*cNH*cL];           // per-chunk cumsum, [b][h][l]
__device__ float g_T  [(size_t)cB*cNH*cNC];          // chunk totals
__device__ float g_cs [(size_t)cB*cNC*cNH*cST*cHD];  // per-chunk states
__device__ float g_pv [(size_t)cB*cNC*cNH*cST*cHD];  // carried states
__device__ float g_gm [(size_t)cB*cNC*cCK*cCK];      // unmasked G per (b,c)
__device__ float g_y  [(size_t)cB*cL*cDS];           // y buffer
__device__ float g_o  [(size_t)cB*cL*cDM];           // out-proj output
// fp16 operand buffers
__device__ unsigned short g_ah [(size_t)4096*4096];  // A fp16 (u, then y)
__device__ unsigned short g_bh [(size_t)cNPAD1*2048];// W_in hi
__device__ unsigned short g_bl [(size_t)cNPAD1*2048];// W_in lo
__device__ unsigned short g_b2h[(size_t)cDM*cDS];    // W_out hi
__device__ unsigned short g_b2l[(size_t)cDM*cDS];    // W_out lo

// ---------------- math helpers --------------------------------------------
DEVFN float fexp(float x) {          // exp(x), FFMA-only
  float t = x * 1.44269504088896340736f;
  t = fminf(fmaxf(t, -126.0f), 126.0f);
  float fi = rintf(t);
  float f  = t - fi;
  float p = 1.5403530393381610e-4f;
  p = fmaf(p, f, 1.3333558146428443e-3f);
  p = fmaf(p, f, 9.6181291076284772e-3f);
  p = fmaf(p, f, 5.5504108664821580e-2f);
  p = fmaf(p, f, 2.4022650695910071e-1f);
  p = fmaf(p, f, 6.9314718055994531e-1f);
  p = fmaf(p, f, 1.0f);
  int i = (int)fi;
  return __int_as_float((i + 127) << 23) * p;
}
DEVFN float fsig(float x) { return 1.0f / (1.0f + fexp(-x)); }

DEVFN uint32_t smem_to_u32(const void* p) {
  uint32_t a;
  asm("{ .reg .u64 t; cvta.to.shared.u64 t, %1; cvt.u32.u64 %0, t; }"
      : "=r"(a) : "l"(p));
  return a;
}
DEVFN void cp16(uint32_t saddr, const void* gptr) {
  asm volatile("cp.async.cg.shared.global [%0], [%1], 16;"
               :: "r"(saddr), "l"(gptr) : "memory");
}
DEVFN void ldsm4(uint32_t (&r)[4], uint32_t a) {
  asm volatile("ldmatrix.sync.aligned.m8n8.x4.shared.b16 {%0,%1,%2,%3}, [%4];"
    : "=r"(r[0]), "=r"(r[1]), "=r"(r[2]), "=r"(r[3]) : "r"(a));
}
DEVFN void ldsm4t(uint32_t (&r)[4], uint32_t a) {
  asm volatile("ldmatrix.sync.aligned.m8n8.x4.trans.shared.b16 {%0,%1,%2,%3}, [%4];"
    : "=r"(r[0]), "=r"(r[1]), "=r"(r[2]), "=r"(r[3]) : "r"(a));
}
DEVFN void mma16816h(float (&d)[4], const uint32_t (&a)[4], uint32_t b0, uint32_t b1) {
  asm volatile("mma.sync.aligned.m16n8k16.row.col.f32.f16.f16.f32 "
    "{%0,%1,%2,%3},{%4,%5,%6,%7},{%8,%9},{%0,%1,%2,%3};"
    : "+f"(d[0]), "+f"(d[1]), "+f"(d[2]), "+f"(d[3])
    : "r"(a[0]), "r"(a[1]), "r"(a[2]), "r"(a[3]), "r"(b0), "r"(b1));
}
DEVFN void hsplit(float v, __half& h, __half& l) {
  h = __float2half_rn(v);
  l = __float2half_rn(v - __half2float(h));
}

// single shared dynamic-smem declaration for all kernels
extern __shared__ char dyn_smem[];

// ============= K0a: fp32 -> fp16, no padding (A matrices) ================
__global__ void __launch_bounds__(256) k_cvt_h(
    const float* __restrict__ src, unsigned short* __restrict__ dst, long tot)
{
  long i = ((long)blockIdx.x * 256 + threadIdx.x) * 4;
  if (i >= tot) return;
  float4 v = *(const float4*)(src + i);
  __half h0 = __float2half_rn(v.x), h1 = __float2half_rn(v.y);
  __half h2 = __float2half_rn(v.z), h3 = __float2half_rn(v.w);
  ushort4 hv;
  hv.x = *(unsigned short*)&h0; hv.y = *(unsigned short*)&h1;
  hv.z = *(unsigned short*)&h2; hv.w = *(unsigned short*)&h3;
  *(ushort4*)(dst + i) = hv;
}

// ============= K0b: fp32 -> (hi, lo) fp16, with row zero-padding ==========
__global__ void __launch_bounds__(256) k_cvt_hl(
    const float* __restrict__ src, unsigned short* __restrict__ hi,
    unsigned short* __restrict__ lo, int srcRows, int K, long tot)
{
  long i = ((long)blockIdx.x * 256 + threadIdx.x) * 4;
  if (i >= tot) return;
  long row = i / K;
  float4 v = make_float4(0.f, 0.f, 0.f, 0.f);
  if (row < srcRows) v = *(const float4*)(src + i);
  __half h0, h1, h2, h3, l0, l1, l2, l3;
  hsplit(v.x, h0, l0); hsplit(v.y, h1, l1);
  hsplit(v.z, h2, l2); hsplit(v.w, h3, l3);
  ushort4 hv, lv;
  hv.x = *(unsigned short*)&h0; hv.y = *(unsigned short*)&h1;
  hv.z = *(unsigned short*)&h2; hv.w = *(unsigned short*)&h3;
  lv.x = *(unsigned short*)&l0; lv.y = *(unsigned short*)&l1;
  lv.z = *(unsigned short*)&l2; lv.w = *(unsigned short*)&l3;
  *(ushort4*)(hi + i) = hv;
  *(ushort4*)(lo + i) = lv;
}

// ============= fp16 2-MMA GEMM: C[M,N] = A[M,K] * B[N,K]^T ================
// A plain fp16; B split hi/lo fp16. Single-barrier 3-stage cp.async pipeline.
constexpr int ROWB  = 80;
constexpr int TILEB = 128 * ROWB;         // 10240
constexpr int STGB  = 3 * TILEB;          // A | Bh | Bl per stage
constexpr int SMEM_GEMM = 3 * STGB;       // 92160

__global__ void __launch_bounds__(256, 2) gemm_mma(
    const __half* __restrict__ A,
    const __half* __restrict__ Bh, const __half* __restrict__ Bl,
    float* __restrict__ C, int M, int N, int K)
{
  char* smem = dyn_smem;
  const uint32_t sb0 = smem_to_u32(smem);
  const int tid = threadIdx.x;
  const int lane = tid & 31, wid = tid >> 5;
  const int bm = blockIdx.y * 128, bn = blockIdx.x * 128;
  const int wm = (wid >> 1) * 32, wn = (wid & 1) * 64;

  float acc[2][8][4];
  #pragma unroll
  for (int i = 0; i < 2; ++i)
    #pragma unroll
    for (int j = 0; j < 8; ++j)
      #pragma unroll
      for (int q = 0; q < 4; ++q) acc[i][j][q] = 0.0f;

  auto load_tile = [&](int kt, int stg) {
    const uint32_t sb = sb0 + stg * STGB;
    const long kb = (long)kt * 32;
    #pragma unroll
    for (int i = 0; i < 2; ++i) {
      int o = tid + 256 * i;
      int row = o >> 2, seg = o & 3;
      uint32_t soff = row * ROWB + seg * 16;
      long ga = (long)(bm + row) * K + kb + seg * 8;
      long gb = (long)(bn + row) * K + kb + seg * 8;
      cp16(sb + soff,             A  + ga);
      cp16(sb + TILEB + soff,     Bh + gb);
      cp16(sb + 2*TILEB + soff,   Bl + gb);
    }
    asm volatile("cp.async.commit_group;" ::: "memory");
  };

  const int KT = K >> 5;       // K/32, always >= 2 here
  load_tile(0, 0);
  load_tile(1, 1);
  for (int kt = 0; kt < KT; ++kt) {
    const int stg = kt % 3;
    // wait for stage kt to land (pending groups: kt, kt+1 at steady state)
    if (kt < KT - 1) {
      asm volatile("cp.async.wait_group 1;" ::: "memory");
    } else {
      asm volatile("cp.async.wait_group 0;" ::: "memory");
    }
    __syncthreads();   // also proves stage (kt+2)%3 == (kt-1)%3 fully consumed
    if (kt + 2 < KT) load_tile(kt + 2, (kt + 2) % 3);
    const uint32_t sb = sb0 + stg * STGB;
    #pragma unroll
    for (int h = 0; h < 2; ++h) {
      uint32_t ah[2][4];
      #pragma unroll
      for (int mi = 0; mi < 2; ++mi) {
        uint32_t ad = sb + (uint32_t)(wm + mi*16 + (lane & 15)) * ROWB
                         + h*32 + (lane >> 4) * 16;
        ldsm4(ah[mi], ad);
      }
      #pragma unroll
      for (int nj2 = 0; nj2 < 4; ++nj2) {
        uint32_t bd = sb + TILEB
          + (uint32_t)(wn + nj2*16 + (lane & 7) + ((lane >> 4) << 3)) * ROWB
          + h*32 + ((lane >> 3) & 1) * 16;
        uint32_t bh4[4], bl4[4];
        ldsm4(bh4, bd);
        ldsm4(bl4, bd + TILEB);
        #pragma unroll
        for (int mi = 0; mi < 2; ++mi) {
          #pragma unroll
          for (int s = 0; s < 2; ++s) {
            int nj = nj2 * 2 + s;
            mma16816h(acc[mi][nj], ah[mi], bh4[2*s], bh4[2*s+1]);
            mma16816h(acc[mi][nj], ah[mi], bl4[2*s], bl4[2*s+1]);
          }
        }
      }
    }
  }

  #pragma unroll
  for (int mi = 0; mi < 2; ++mi) {
    int row = bm + wm + mi*16 + (lane >> 2);
    #pragma unroll
    for (int nj = 0; nj < 8; ++nj) {
      int col = bn + wn + nj*8 + (lane & 3)*2;
      if (col < N) {
        *(float2*)(C + (long)row * N + col) =
            make_float2(acc[mi][nj][0], acc[mi][nj][1]);
        *(float2*)(C + (long)(row + 8) * N + col) =
            make_float2(acc[mi][nj][2], acc[mi][nj][3]);
      }
    }
  }
}

// ============= K2: conv1d + SiLU + softplus(dt), float4 ===================
__global__ void __launch_bounds__(256) k_conv(
    const float* __restrict__ conv_w, const float* __restrict__ conv_b,
    const float* __restrict__ dt_bias)
{
  const int row = blockIdx.x;
  const int b = row / cL, l = row % cL;
  const int tid = threadIdx.x;
  const float* z0 = &g_zx[(size_t)row * cDP + cDS];
  float* obp = &g_xbc[(size_t)row * cCD];
  const bool p1 = (l >= 1), p2 = (l >= 2);
  #pragma unroll 1
  for (int q = 0; q < 5; ++q) {
    int c4 = tid + q * 256;
    if (c4 >= cCD / 4) break;
    int c = c4 * 4;
    float4 wa = *(const float4*)(conv_w + c*3);
    float4 wb = *(const float4*)(conv_w + c*3 + 4);
    float4 wc = *(const float4*)(conv_w + c*3 + 8);
    float4 bs = *(const float4*)(conv_b + c);
    float4 x2 = p2 ? *(const float4*)(z0 - 2*(size_t)cDP + c) : make_float4(0,0,0,0);
    float4 x1 = p1 ? *(const float4*)(z0 -   (size_t)cDP + c) : make_float4(0,0,0,0);
    float4 x0 = *(const float4*)(z0 + c);
    float4 s;
    s.x = bs.x + x2.x*wa.x + x1.x*wa.y + x0.x*wa.z;
    s.y = bs.y + x2.y*wa.w + x1.y*wb.x + x0.y*wb.y;
    s.z = bs.z + x2.z*wb.z + x1.z*wb.w + x0.z*wc.x;
    s.w = bs.w + x2.w*wc.y + x1.w*wc.z + x0.w*wc.w;
    s.x *= fsig(s.x); s.y *= fsig(s.y); s.z *= fsig(s.z); s.w *= fsig(s.w);
    *(float4*)(obp + c) = s;
  }
  if (tid < cNH) {
    float v = g_zx[(size_t)row * cDP + (cDP - cNH) + tid] + dt_bias[tid];
    float sp = (v > 15.0f) ? v : log1pf(expf(v));
    g_dt[((size_t)b * cNH + tid) * cL + l] = sp;
  }
}

// ============= K3: per-chunk inclusive cumsum of dt*A =====================
__global__ void __launch_bounds__(128) k_scan(const float* __restrict__ A_log)
{
  const int h = blockIdx.x, c = blockIdx.y, b = blockIdx.z;
  const int l = threadIdx.x;
  const float ah = -expf(A_log[h]);
  const size_t base = ((size_t)b * cNH + h) * cL + c * cCK;
  __shared__ float s[128];
  s[l] = g_dt[base + l] * ah;
  __syncthreads();
  #pragma unroll
  for (int off = 1; off < 128; off <<= 1) {
    float t = (l >= off) ? s[l - off] : 0.0f;
    __syncthreads();
    s[l] += t;
    __syncthreads();
  }
  g_ac[base + l] = s[l];
  if (l == 127) g_T[((size_t)b * cNH + h) * cNC + c] = s[127];
}

// ============= K4: chunk states (mma.sync fp16, A plain + B split) ========
// states[n][p] = sum_l Bmat[l][n] * (dt[l]*exp(T-ac[l])) * x[l][p]
constexpr int S_AS  = 136;
constexpr int S_BS  = 72;
constexpr int S_Ao  = 0;
constexpr int S_BHo = 128 * S_AS * 2;          // 34816
constexpr int S_BLo = S_BHo + 128 * S_BS * 2;  // 53248
constexpr int S_SCo = S_BLo + 128 * S_BS * 2;  // 71680
constexpr int S_SMEM = S_SCo + 512;            // 72192

__global__ void __launch_bounds__(256, 2) k_states()
{
  char* sm = dyn_smem;
  __half* Ap = (__half*)(sm + S_Ao);
  __half* Bhp = (__half*)(sm + S_BHo);
  __half* Blp = (__half*)(sm + S_BLo);
  float* sc = (float*)(sm + S_SCo);
  const uint32_t sb = smem_to_u32(sm);
  const int h = blockIdx.x, c = blockIdx.y, b = blockIdx.z;
  const int tid = threadIdx.x, lane = tid & 31, wid = tid >> 5;
  const size_t rowbase = ((size_t)(b * cL + c * cCK)) * cCD;
  const size_t acb = ((size_t)b * cNH + h) * cL + c * cCK;
  if (tid < 128) {
    float T = g_T[((size_t)b * cNH + h) * cNC + c];
    sc[tid] = g_dt[acb + tid] * fexp(T - g_ac[acb + tid]);
  }
  __syncthreads();
  // stage Bmat [l][n] plain fp16 (A operand, via ldsm.trans)
  #pragma unroll 1
  for (int q = 0; q < 16; ++q) {
    int i = (tid + q * 256) * 4;
    int l = i >> 7, n = i & 127;
    float4 v = *(const float4*)&g_xbc[rowbase + (size_t)l * cCD + cDS + n];
    float vv[4] = {v.x, v.y, v.z, v.w};
    #pragma unroll
    for (int j = 0; j < 4; ++j)
      Ap[l * S_AS + n + j] = __float2half_rn(vv[j]);
  }
  // stage X' [l][p] = x * sc[l], hi/lo split (B operand)
  #pragma unroll 1
  for (int q = 0; q < 8; ++q) {
    int i = (tid + q * 256) * 4;
    int l = i >> 6, p = i & 63;
    float4 x = *(const float4*)&g_xbc[rowbase + (size_t)l * cCD + h * cHD + p];
    float s = sc[l];
    float xv[4] = {x.x * s, x.y * s, x.z * s, x.w * s};
    #pragma unroll
    for (int j = 0; j < 4; ++j) {
      __half hh, ll;
      hsplit(xv[j], hh, ll);
      Bhp[l * S_BS + p + j] = hh; Blp[l * S_BS + p + j] = ll;
    }
  }
  __syncthreads();

  const int wm = (wid >> 1) * 32, wn = (wid & 1) * 32;
  float acc[2][4][4];
  #pragma unroll
  for (int mi = 0; mi < 2; ++mi)
    #pragma unroll
    for (int nj = 0; nj < 4; ++nj)
      #pragma unroll
      for (int q = 0; q < 4; ++q) acc[mi][nj][q] = 0.0f;

  #pragma unroll
  for (int kk = 0; kk < 8; ++kk) {
    uint32_t ah4[2][4];
    #pragma unroll
    for (int mi = 0; mi < 2; ++mi) {
      uint32_t ad = sb + S_Ao
        + (uint32_t)(kk*16 + (lane & 7) + ((lane >> 4) << 3)) * (S_AS * 2)
        + (uint32_t)(wm + mi*16 + (lane & 8)) * 2;
      ldsm4t(ah4[mi], ad);
    }
    #pragma unroll
    for (int nj2 = 0; nj2 < 2; ++nj2) {
      uint32_t bd = sb + S_BHo
        + (uint32_t)(kk*16 + (lane & 15)) * (S_BS * 2)
        + (uint32_t)(wn + nj2*16 + ((lane >> 4) << 3)) * 2;
      uint32_t bh4[4], bl4[4];
      ldsm4t(bh4, bd);
      ldsm4t(bl4, bd + (S_BLo - S_BHo));
      #pragma unroll
      for (int mi = 0; mi < 2; ++mi) {
        #pragma unroll
        for (int s2 = 0; s2 < 2; ++s2) {
          int nj = nj2 * 2 + s2;
          mma16816h(acc[mi][nj], ah4[mi], bh4[2*s2], bh4[2*s2+1]);
          mma16816h(acc[mi][nj], ah4[mi], bl4[2*s2], bl4[2*s2+1]);
        }
      }
    }
  }

  const size_t ob = (((size_t)b * cNC + c) * cNH + h) * (cST * cHD);
  #pragma unroll
  for (int mi = 0; mi < 2; ++mi) {
    int row = wm + mi*16 + (lane >> 2);
    #pragma unroll
    for (int nj = 0; nj < 4; ++nj) {
      int col = wn + nj*8 + (lane & 3)*2;
      *(float2*)&g_cs[ob + (size_t)row * cHD + col] =
          make_float2(acc[mi][nj][0], acc[mi][nj][1]);
      *(float2*)&g_cs[ob + (size_t)(row + 8) * cHD + col] =
          make_float2(acc[mi][nj][2], acc[mi][nj][3]);
    }
  }
}

// ============= K5: inter-chunk carry scan =================================
__global__ void __launch_bounds__(256) k_carry()
{
  const int bh = blockIdx.x;
  const int b = bh >> 6, h = bh & 63;
  const int tid = threadIdx.x;
  float carry[32];
  #pragma unroll
  for (int j = 0; j < 32; ++j) carry[j] = 0.0f;
  for (int c = 0; c < cNC; ++c) {
    if (c > 0) {
      float eT = fexp(g_T[(size_t)bh * cNC + (c - 1)]);
      const size_t inb = (((size_t)b * cNC + (c - 1)) * cNH + h) * (cST * cHD);
      #pragma unroll
      for (int j = 0; j < 32; ++j)
        carry[j] = carry[j] * eT + g_cs[inb + tid + j * 256];
    }
    const size_t ob = (((size_t)b * cNC + c) * cNH + h) * (cST * cHD);
    #pragma unroll
    for (int j = 0; j < 32; ++j)
      g_pv[ob + tid + j * 256] = carry[j];
  }
}

// ============= K5.5: unmasked G = C * B^T per (b,c) =======================
__global__ void __launch_bounds__(256) k_gmat()
{
  float* smf = (float*)dyn_smem;
  float* Ct = smf;                 // [n][l] stride 132
  float* Bt = smf + 128 * 132;
  const int c = blockIdx.x, b = blockIdx.y;
  const int tid = threadIdx.x;
  const size_t rowbase = ((size_t)(b * cL + c * cCK)) * cCD;
  #pragma unroll 1
  for (int q = 0; q < 16; ++q) {
    int i = tid + q * 256;
    int l = i >> 5, nq = i & 31;
    const float* src = &g_xbc[rowbase + (size_t)l * cCD];
    float4 cv = *(const float4*)(src + cDS + cST + nq * 4);
    float4 bv = *(const float4*)(src + cDS + nq * 4);
    int n = nq * 4;
    Ct[(n+0)*132 + l] = cv.x; Ct[(n+1)*132 + l] = cv.y;
    Ct[(n+2)*132 + l] = cv.z; Ct[(n+3)*132 + l] = cv.w;
    Bt[(n+0)*132 + l] = bv.x; Bt[(n+1)*132 + l] = bv.y;
    Bt[(n+2)*132 + l] = bv.z; Bt[(n+3)*132 + l] = bv.w;
  }
  __syncthreads();
  const int ty = tid >> 4, tx = tid & 15;
  const int l0 = ty * 8, s0 = tx * 8;
  float accG[8][8] = {};
  for (int n = 0; n < cST; ++n) {
    float4 a0 = *(const float4*)&Ct[n*132 + l0];
    float4 a1 = *(const float4*)&Ct[n*132 + l0 + 4];
    float4 b0 = *(const float4*)&Bt[n*132 + s0];
    float4 b1 = *(const float4*)&Bt[n*132 + s0 + 4];
    float a[8]  = {a0.x, a0.y, a0.z, a0.w, a1.x, a1.y, a1.z, a1.w};
    float bb[8] = {b0.x, b0.y, b0.z, b0.w, b1.x, b1.y, b1.z, b1.w};
    #pragma unroll
    for (int i = 0; i < 8; ++i)
      #pragma unroll
      for (int j = 0; j < 8; ++j) accG[i][j] += a[i] * bb[j];
  }
  const size_t gb = ((size_t)(b * cNC + c)) * (cCK * cCK);
  #pragma unroll
  for (int i = 0; i < 8; ++i) {
    #pragma unroll
    for (int j = 0; j < 4; ++j) {
      *(float2*)&g_gm[gb + (size_t)(l0 + i) * cCK + s0 + 2*j] =
          make_float2(accG[i][2*j], accG[i][2*j+1]);
    }
  }
}

// ============= K6: SSD Y kernel (fp16 mma, 2 passes) ======================
constexpr int Y_AS = 136;
constexpr int Y_BS = 72;
constexpr int Y_Ao  = 0;
constexpr int Y_BHo = 128 * Y_AS * 2;          // 34816
constexpr int Y_BLo = Y_BHo + 128 * Y_BS * 2;  // 53248
constexpr int Y_ACS = Y_BLo + 128 * Y_BS * 2;  // 71680
constexpr int Y_DTS = Y_ACS + 512;             // 72192
constexpr int Y_SMEM = Y_DTS + 512;            // 72704

__global__ void __launch_bounds__(256, 2) k_ssd_y(const float* __restrict__ Dv)
{
  char* sm = dyn_smem;
  __half* Ap  = (__half*)(sm + Y_Ao);
  __half* Bhp = (__half*)(sm + Y_BHo);
  __half* Blp = (__half*)(sm + Y_BLo);
  float* acs = (float*)(sm + Y_ACS);
  float* dts = (float*)(sm + Y_DTS);
  const uint32_t sb = smem_to_u32(sm);
  const int h = blockIdx.x, c = blockIdx.y, b = blockIdx.z;
  const int tid = threadIdx.x, lane = tid & 31, wid = tid >> 5;
  const size_t rowbase = ((size_t)(b * cL + c * cCK)) * cCD;
  const size_t acb = ((size_t)b * cNH + h) * cL + c * cCK;
  if (tid < 128) { acs[tid] = g_ac[acb + tid]; dts[tid] = g_dt[acb + tid]; }
  __syncthreads();

  // ---- stage Gm (masked, decayed) plain fp16 into A region ----
  const size_t gb = ((size_t)(b * cNC + c)) * (cCK * cCK);
  #pragma unroll 1
  for (int q = 0; q < 16; ++q) {
    int i = (tid + q * 256) * 4;
    int l = i >> 7, s = i & 127;
    float4 g = *(const float4*)&g_gm[gb + i];
    float al = acs[l];
    float gv[4] = {g.x, g.y, g.z, g.w};
    #pragma unroll
    for (int j = 0; j < 4; ++j) {
      int ss = s + j;
      float m = (ss <= l) ? fexp(al - acs[ss]) : 0.0f;
      Ap[l * Y_AS + ss] = __float2half_rn(gv[j] * m);
    }
  }
  // ---- stage X' = x * dt hi/lo into B region (natural [s][p]) ----
  #pragma unroll 1
  for (int q = 0; q < 8; ++q) {
    int i = (tid + q * 256) * 4;
    int s = i >> 6, p = i & 63;
    float4 x = *(const float4*)&g_xbc[rowbase + (size_t)s * cCD + h * cHD + p];
    float dv = dts[s];
    float xv[4] = {x.x * dv, x.y * dv, x.z * dv, x.w * dv};
    #pragma unroll
    for (int j = 0; j < 4; ++j) {
      __half hh, ll;
      hsplit(xv[j], hh, ll);
      Bhp[s * Y_BS + p + j] = hh; Blp[s * Y_BS + p + j] = ll;
    }
  }
  __syncthreads();

  const int wm = (wid >> 1) * 32, wn = (wid & 1) * 32;
  float acc[2][4][4];
  #pragma unroll
  for (int mi = 0; mi < 2; ++mi)
    #pragma unroll
    for (int nj = 0; nj < 4; ++nj)
      #pragma unroll
      for (int q = 0; q < 4; ++q) acc[mi][nj][q] = 0.0f;

  auto mma_pass = [&]() {
    #pragma unroll
    for (int kk = 0; kk < 8; ++kk) {
      uint32_t ah4[2][4];
      #pragma unroll
      for (int mi = 0; mi < 2; ++mi) {
        uint32_t ad = sb + Y_Ao
          + (uint32_t)(wm + mi*16 + (lane & 15)) * (Y_AS * 2)
          + kk*32 + (lane >> 4) * 16;
        ldsm4(ah4[mi], ad);
      }
      #pragma unroll
      for (int nj2 = 0; nj2 < 2; ++nj2) {
        uint32_t bd = sb + Y_BHo
          + (uint32_t)(kk*16 + (lane & 15)) * (Y_BS * 2)
          + (uint32_t)(wn + nj2*16 + ((lane >> 4) << 3)) * 2;
        uint32_t bh4[4], bl4[4];
        ldsm4t(bh4, bd);
        ldsm4t(bl4, bd + (Y_BLo - Y_BHo));
        #pragma unroll
        for (int mi = 0; mi < 2; ++mi) {
          #pragma unroll
          for (int s2 = 0; s2 < 2; ++s2) {
            int nj = nj2 * 2 + s2;
            mma16816h(acc[mi][nj], ah4[mi], bh4[2*s2], bh4[2*s2+1]);
            mma16816h(acc[mi][nj], ah4[mi], bl4[2*s2], bl4[2*s2+1]);
          }
        }
      }
    }
  };
  mma_pass();          // Y += Gm @ X'
  __syncthreads();

  // ---- stage Ce = C * exp(ac_l) plain fp16 into A region ----
  #pragma unroll 1
  for (int q = 0; q < 16; ++q) {
    int i = (tid + q * 256) * 4;
    int l = i >> 7, n = i & 127;
    float4 cv = *(const float4*)&g_xbc[rowbase + (size_t)l * cCD + cDS + cST + n];
    float e = fexp(acs[l]);
    float cvv[4] = {cv.x * e, cv.y * e, cv.z * e, cv.w * e};
    #pragma unroll
    for (int j = 0; j < 4; ++j)
      Ap[l * Y_AS + n + j] = __float2half_rn(cvv[j]);
  }
  // ---- stage P (prev states, natural [n][p]) hi/lo into B region ----
  {
    const size_t pb = (((size_t)b * cNC + c) * cNH + h) * (cST * cHD);
    #pragma unroll 1
    for (int q = 0; q < 8; ++q) {
      int i = (tid + q * 256) * 4;
      int n = i >> 6, p = i & 63;
      float4 pv = *(const float4*)&g_pv[pb + i];
      float pvv[4] = {pv.x, pv.y, pv.z, pv.w};
      #pragma unroll
      for (int j = 0; j < 4; ++j) {
        __half hh, ll;
        hsplit(pvv[j], hh, ll);
        Bhp[n * Y_BS + p + j] = hh; Blp[n * Y_BS + p + j] = ll;
      }
    }
  }
  __syncthreads();
  mma_pass();          // Y += Ce @ P

  // ---- epilogue: Y + D*x -> g_y ----
  const float Dh = Dv[h];
  #pragma unroll
  for (int mi = 0; mi < 2; ++mi) {
    int row = wm + mi*16 + (lane >> 2);
    #pragma unroll
    for (int nj = 0; nj < 4; ++nj) {
      int col = wn + nj*8 + (lane & 3)*2;
      float2 x0 = *(const float2*)&g_xbc[rowbase + (size_t)row * cCD + h * cHD + col];
      float2 x1 = *(const float2*)&g_xbc[rowbase + (size_t)(row+8) * cCD + h * cHD + col];
      size_t y0 = ((size_t)(b * cL + c * cCK + row)) * cDS + h * cHD + col;
      size_t y1 = ((size_t)(b * cL + c * cCK + row + 8)) * cDS + h * cHD + col;
      *(float2*)&g_y[y0] = make_float2(acc[mi][nj][0] + Dh * x0.x,
                                       acc[mi][nj][1] + Dh * x0.y);
      *(float2*)&g_y[y1] = make_float2(acc[mi][nj][2] + Dh * x1.x,
                                       acc[mi][nj][3] + Dh * x1.y);
    }
  }
}

// ============= K7: gate (silu(z)) + RMSNorm + fp16 cvt (fused) ============
__global__ void __launch_bounds__(256) k_gate_norm(const float* __restrict__ norm_w)
{
  const int row = blockIdx.x;
  const int tid = threadIdx.x;
  const size_t zb = (size_t)row * cDP;
  const size_t yb = (size_t)row * cDS;
  float v[16];
  float ss = 0.0f;
  #pragma unroll
  for (int q = 0; q < 16; ++q) {
    int i = tid + q * 256;
    float z = g_zx[zb + i];
    float y = g_y[yb + i];
    float t = y * z * fsig(z);
    v[q] = t;
    ss += t * t;
  }
  #pragma unroll
  for (int o = 16; o > 0; o >>= 1) ss += __shfl_xor_sync(0xffffffffu, ss, o);
  __shared__ float red[8];
  if ((tid & 31) == 0) red[tid >> 5] = ss;
  __syncthreads();
  float tot = 0.0f;
  #pragma unroll
  for (int j = 0; j < 8; ++j) tot += red[j];
  const float scale = rsqrtf(tot / (float)cDS + cEPS);
  #pragma unroll
  for (int q = 0; q < 16; ++q) {
    int i = tid + q * 256;
    float t = v[q] * scale * norm_w[i];
    __half hh = __float2half_rn(t);
    g_ah[yb + i] = *(unsigned short*)&hh;
  }
}

// ============= K9: out + reverse(out) =====================================
__global__ void __launch_bounds__(256) k_revadd(float* __restrict__ out)
{
  const int idx4 = blockIdx.x * 256 + threadIdx.x;
  const int tot4 = cB * cL * cDM / 4;
  if (idx4 >= tot4) return;
  const int i = idx4 * 4;
  const int b = i / (cL * cDM);
  const int r = i - b * (cL * cDM);
  const int l = r / cDM;
  const int d = r - l * cDM;
  const size_t rev = ((size_t)b * cL + (cL - 1 - l)) * cDM + d;
  float4 a = *(const float4*)(&g_o[i]);
  float4 c = *(const float4*)(&g_o[rev]);
  a.x += c.x; a.y += c.y; a.z += c.z; a.w += c.w;
  *(float4*)(out + i) = a;
}

// ==========================================================================
extern "C" void kernel_launch(void* const* d_in, const int* in_sizes, int n_in,
                              void* d_out, int out_size) {
  const float* u       = (const float*)d_in[0];
  const float* W_in    = (const float*)d_in[1];
  const float* conv_w  = (const float*)d_in[2];
  const float* conv_b  = (const float*)d_in[3];
  const float* dt_bias = (const float*)d_in[4];
  const float* A_log   = (const float*)d_in[5];
  const float* Dv      = (const float*)d_in[6];
  const float* norm_w  = (const float*)d_in[7];
  const float* W_out   = (const float*)d_in[8];
  float* out = (float*)d_out;

  float* zx; cudaGetSymbolAddress((void**)&zx, g_zx);
  float* ob; cudaGetSymbolAddress((void**)&ob, g_o);
  unsigned short *ah, *bh, *bl, *b2h, *b2l;
  cudaGetSymbolAddress((void**)&ah,  g_ah);
  cudaGetSymbolAddress((void**)&bh,  g_bh);
  cudaGetSymbolAddress((void**)&bl,  g_bl);
  cudaGetSymbolAddress((void**)&b2h, g_b2h);
  cudaGetSymbolAddress((void**)&b2l, g_b2l);

  cudaFuncSetAttribute(gemm_mma, cudaFuncAttributeMaxDynamicSharedMemorySize,
                       SMEM_GEMM);
  cudaFuncSetAttribute(k_gmat, cudaFuncAttributeMaxDynamicSharedMemorySize,
                       2 * 128 * 132 * 4);
  cudaFuncSetAttribute(k_states, cudaFuncAttributeMaxDynamicSharedMemorySize,
                       S_SMEM);
  cudaFuncSetAttribute(k_ssd_y, cudaFuncAttributeMaxDynamicSharedMemorySize,
                       Y_SMEM);

  const int M = cB * cL;   // 4096

  // --- prep: u -> fp16; W_in, W_out -> fp16 hi/lo (launch #4 = GEMM1) ---
  {
    long totA = (long)M * cDM;
    k_cvt_h<<<(unsigned)((totA/4 + 255)/256), 256>>>(u, ah, totA);
    long totB = (long)cNPAD1 * cDM;
    k_cvt_hl<<<(unsigned)((totB/4 + 255)/256), 256>>>(W_in, bh, bl, cDP, cDM, totB);
    long totB2 = (long)cDM * cDS;
    k_cvt_hl<<<(unsigned)((totB2/4 + 255)/256), 256>>>(W_out, b2h, b2l, cDM, cDS, totB2);
  }
  // --- GEMM1: zx[4096, 8512] ---
  {
    dim3 grid(cNPAD1 / 128, M / 128);
    gemm_mma<<<grid, 256, SMEM_GEMM>>>(
        (const __half*)ah, (const __half*)bh, (const __half*)bl,
        zx, M, cDP, cDM);
  }
  // --- conv + silu + dt ---
  k_conv<<<cB * cL, 256>>>(conv_w, conv_b, dt_bias);
  // --- per-chunk cumsum ---
  { dim3 grid(cNH, cNC, cB); k_scan<<<grid, 128>>>(A_log); }
  // --- chunk states (fp16 mma) ---
  { dim3 grid(cNH, cNC, cB); k_states<<<grid, 256, S_SMEM>>>(); }
  // --- carry scan ---
  k_carry<<<cB * cNH, 256>>>();
  // --- unmasked G ---
  { dim3 grid(cNC, cB); k_gmat<<<grid, 256, 2 * 128 * 132 * 4>>>(); }
  // --- Y (fp16 mma) ---
  { dim3 grid(cNH, cNC, cB); k_ssd_y<<<grid, 256, Y_SMEM>>>(Dv); }
  // --- gate + rmsnorm + fp16 cvt (fused) ---
  k_gate_norm<<<cB * cL, 256>>>(norm_w);
  // --- GEMM2: o[4096, 2048] ---
  {
    dim3 grid(cDM / 128, M / 128);
    gemm_mma<<<grid, 256, SMEM_GEMM>>>(
        (const __half*)ah, (const __half*)b2h, (const __half*)b2l,
        ob, M, cDM, cDS);
  }
  // --- out + reverse(out) ---
  k_revadd<<<(cB * cL * cDM / 4 + 255) / 256, 256>>>(out);
}